// round 9
// baseline (speedup 1.0000x reference)
#include <cuda_runtime.h>
#include <cuda_bf16.h>
#include <cstdint>
#include <math.h>

// Problem constants
#define BB 4
#define TT 2048
#define CC 1024
#define HH 16
#define HD 64
#define BT (BB*TT)          // 8192

// Pre-split bf16 scratch (device globals: allocation-free per harness rules)
__device__ __align__(256) __nv_bfloat16 g_xhi[(size_t)BT * CC];
__device__ __align__(256) __nv_bfloat16 g_xlo[(size_t)BT * CC];
__device__ __align__(256) __nv_bfloat16 g_wqhi[(size_t)CC * 3 * CC];
__device__ __align__(256) __nv_bfloat16 g_wqlo[(size_t)CC * 3 * CC];
__device__ __align__(256) __nv_bfloat16 g_wphi[(size_t)CC * CC];
__device__ __align__(256) __nv_bfloat16 g_wplo[(size_t)CC * CC];
__device__ __align__(256) __nv_bfloat16 g_qkvhi[(size_t)BT * 3 * CC];
__device__ __align__(256) __nv_bfloat16 g_qkvlo[(size_t)BT * 3 * CC];
__device__ __align__(256) __nv_bfloat16 g_atthi[(size_t)BT * CC];
__device__ __align__(256) __nv_bfloat16 g_attlo[(size_t)BT * CC];

// ===========================================================================
// Helpers
// ===========================================================================
__device__ __forceinline__ uint32_t smem_u32(const void* p) {
    uint32_t a;
    asm("{ .reg .u64 t; cvta.to.shared.u64 t, %1; cvt.u32.u64 %0, t; }"
        : "=r"(a) : "l"(p));
    return a;
}

#define LDSM_X4(r, addr) \
    asm volatile("ldmatrix.sync.aligned.m8n8.x4.shared.b16 {%0,%1,%2,%3}, [%4];" \
        : "=r"((r)[0]), "=r"((r)[1]), "=r"((r)[2]), "=r"((r)[3]) : "r"(addr))

#define LDSM_X4T(r, addr) \
    asm volatile("ldmatrix.sync.aligned.m8n8.x4.trans.shared.b16 {%0,%1,%2,%3}, [%4];" \
        : "=r"((r)[0]), "=r"((r)[1]), "=r"((r)[2]), "=r"((r)[3]) : "r"(addr))

#define MMA_BF16(c, a, b) \
    asm volatile("mma.sync.aligned.m16n8k16.row.col.f32.bf16.bf16.f32 " \
        "{%0,%1,%2,%3}, {%4,%5,%6,%7}, {%8,%9}, {%0,%1,%2,%3};" \
        : "+f"((c)[0]), "+f"((c)[1]), "+f"((c)[2]), "+f"((c)[3]) \
        : "r"((a)[0]), "r"((a)[1]), "r"((a)[2]), "r"((a)[3]), \
          "r"((b)[0]), "r"((b)[1]))

#define MMA_BF16_2(c, a, b0, b1) \
    asm volatile("mma.sync.aligned.m16n8k16.row.col.f32.bf16.bf16.f32 " \
        "{%0,%1,%2,%3}, {%4,%5,%6,%7}, {%8,%9}, {%0,%1,%2,%3};" \
        : "+f"((c)[0]), "+f"((c)[1]), "+f"((c)[2]), "+f"((c)[3]) \
        : "r"((a)[0]), "r"((a)[1]), "r"((a)[2]), "r"((a)[3]), \
          "r"(b0), "r"(b1))

#define CP_ASYNC_CG(dst, src) \
    asm volatile("cp.async.cg.shared.global [%0], [%1], 16;" :: "r"(dst), "l"(src))
#define CP_COMMIT() asm volatile("cp.async.commit_group;" ::: "memory")
#define CP_WAIT1()  asm volatile("cp.async.wait_group 1;" ::: "memory")

__device__ __forceinline__ uint32_t pack_bf16(float a, float b) {
    __nv_bfloat162 t = __floats2bfloat162_rn(a, b);
    return *(uint32_t*)&t;
}

// split x into hi (bf16-representable float) and lo = x - hi
__device__ __forceinline__ void split2(float a, float b, uint32_t& hi, uint32_t& lo) {
    float ha = __bfloat162float(__float2bfloat16(a));
    float hb = __bfloat162float(__float2bfloat16(b));
    hi = pack_bf16(ha, hb);
    lo = pack_bf16(a - ha, b - hb);
}

// ===========================================================================
// split_f32: fp32 array -> hi/lo bf16 arrays (4 elems/thread)
// ===========================================================================
__global__ __launch_bounds__(256) void split_f32(
    const float* __restrict__ in, __nv_bfloat16* __restrict__ hi,
    __nv_bfloat16* __restrict__ lo, int n4)
{
    int i = blockIdx.x * 256 + threadIdx.x;
    if (i >= n4) return;
    float4 v = ((const float4*)in)[i];
    uint32_t h0, l0, h1, l1;
    split2(v.x, v.y, h0, l0);
    split2(v.z, v.w, h1, l1);
    ((uint2*)hi)[i] = make_uint2(h0, h1);
    ((uint2*)lo)[i] = make_uint2(l0, l1);
}

// ===========================================================================
// HMMA split-bf16 GEMM, pre-split bf16 inputs, 3-stage cp.async pipeline.
// 1 CTA/SM, full register budget, BK=64, ONE __syncthreads per chunk.
// C = A@B + bias; output fp32 OR hi/lo bf16 pair (outSplit).
// 128x128 tile, 8 warps (2x4), warp tile 64x32.
// ===========================================================================
#define GA_STRIDE 72          // bf16 elems/row (64+8): 144B row, conflict-free ldsm
#define GB_STRIDE 136         // bf16 elems/row (128+8): 272B row
#define GA_BYTES (128 * GA_STRIDE * 2)   // 18432
#define GB_BYTES (64 * GB_STRIDE * 2)    // 17408
#define GBUF (2 * GA_BYTES + 2 * GB_BYTES)   // 71680
#define GEMM_SMEM (3 * GBUF)                  // 215040

__global__ __launch_bounds__(256, 1) void gemm_bf16(
    const __nv_bfloat16* __restrict__ Ahi, const __nv_bfloat16* __restrict__ Alo,
    const __nv_bfloat16* __restrict__ Bhi, const __nv_bfloat16* __restrict__ Blo,
    const float* __restrict__ bias,
    float* __restrict__ Cf,
    __nv_bfloat16* __restrict__ Chi, __nv_bfloat16* __restrict__ Clo,
    int M, int N, int K, int outSplit)
{
    extern __shared__ char sm[];
    const uint32_t smb = smem_u32(sm);
    const int tid  = threadIdx.x;
    const int lane = tid & 31;
    const int wid  = tid >> 5;
    const int wm   = wid >> 2;
    const int wn   = wid & 3;
    const int rowBase = blockIdx.y * 128;
    const int colBase = blockIdx.x * 128;

    // issue one BK=64 chunk into stage bi: A 128x64 hi/lo + B 64x128 hi/lo
    auto issue = [&](int k0, int bi) {
        uint32_t aH = smb + bi * GBUF;
        uint32_t aL = aH + GA_BYTES;
        uint32_t bH = aH + 2 * GA_BYTES;
        uint32_t bL = bH + GB_BYTES;
#pragma unroll
        for (int j = 0; j < 4; j++) {
            int idx = tid + j * 256;
            int m  = idx >> 3;            // 0..127
            int ch = idx & 7;             // 8 x 16B per 64-elem row
            size_t ao = (size_t)(rowBase + m) * K + k0 + ch * 8;
            uint32_t ad = m * 144 + ch * 16;
            CP_ASYNC_CG(aH + ad, Ahi + ao);
            CP_ASYNC_CG(aL + ad, Alo + ao);
            int kk = idx >> 4;            // 0..63
            int c2 = idx & 15;            // 16 x 16B per 128-elem row
            size_t bo = (size_t)(k0 + kk) * N + colBase + c2 * 8;
            uint32_t bd = kk * 272 + c2 * 16;
            CP_ASYNC_CG(bH + bd, Bhi + bo);
            CP_ASYNC_CG(bL + bd, Blo + bo);
        }
    };

    float acc[4][4][4] = {};
    const int NS = K >> 6;    // 16 chunks of BK=64

    issue(0, 0);  CP_COMMIT();
    issue(64, 1); CP_COMMIT();

    int buf = 0;        // c % 3
    int nbuf = 2;       // (c+2) % 3
    for (int c = 0; c < NS; c++) {
        CP_WAIT1();          // group c complete
        __syncthreads();     // all warps past MMA(c-1); stage (c-1)%3 reusable

        if (c + 2 < NS) issue((c + 2) << 6, nbuf);
        CP_COMMIT();         // unconditional: uniform group numbering

        uint32_t aH = smb + buf * GBUF;
        uint32_t aL = aH + GA_BYTES;
        uint32_t bH = aH + 2 * GA_BYTES;
        uint32_t bL = bH + GB_BYTES;

#pragma unroll
        for (int ks = 0; ks < 4; ks++) {
            uint32_t fAH[4][4], fAL[4][4];
#pragma unroll
            for (int mf = 0; mf < 4; mf++) {
                uint32_t off = ((wm * 64 + mf * 16 + (lane & 15)) * GA_STRIDE
                                + ks * 16 + (lane >> 4) * 8) * 2;
                LDSM_X4(fAH[mf], aH + off);
                LDSM_X4(fAL[mf], aL + off);
            }
#pragma unroll
            for (int nq = 0; nq < 2; nq++) {
                uint32_t fBH[4], fBL[4];
                uint32_t off = ((ks * 16 + (lane & 15)) * GB_STRIDE
                                + wn * 32 + nq * 16 + (lane >> 4) * 8) * 2;
                LDSM_X4T(fBH, bH + off);
                LDSM_X4T(fBL, bL + off);
#pragma unroll
                for (int mf = 0; mf < 4; mf++) {
                    MMA_BF16(acc[mf][2*nq],   fAH[mf], fBH);
                    MMA_BF16(acc[mf][2*nq],   fAH[mf], fBL);
                    MMA_BF16(acc[mf][2*nq],   fAL[mf], fBH);
                    MMA_BF16(acc[mf][2*nq+1], fAH[mf], fBH + 2);
                    MMA_BF16(acc[mf][2*nq+1], fAH[mf], fBL + 2);
                    MMA_BF16(acc[mf][2*nq+1], fAL[mf], fBH + 2);
                }
            }
        }
        buf  = (buf  == 2) ? 0 : buf + 1;
        nbuf = (nbuf == 2) ? 0 : nbuf + 1;
    }

    // ---- Epilogue ----
#pragma unroll
    for (int nf = 0; nf < 4; nf++) {
        int c = colBase + wn * 32 + nf * 8 + 2 * (lane & 3);
        float2 bv = *(const float2*)&bias[c];
#pragma unroll
        for (int mf = 0; mf < 4; mf++) {
            int r0 = rowBase + wm * 64 + mf * 16 + (lane >> 2);
            float o0x = acc[mf][nf][0] + bv.x, o0y = acc[mf][nf][1] + bv.y;
            float o1x = acc[mf][nf][2] + bv.x, o1y = acc[mf][nf][3] + bv.y;
            if (!outSplit) {
                *(float2*)&Cf[(size_t)r0 * N + c] = make_float2(o0x, o0y);
                *(float2*)&Cf[(size_t)(r0 + 8) * N + c] = make_float2(o1x, o1y);
            } else {
                uint32_t ph, pl;
                split2(o0x, o0y, ph, pl);
                *(uint32_t*)&Chi[(size_t)r0 * N + c] = ph;
                *(uint32_t*)&Clo[(size_t)r0 * N + c] = pl;
                split2(o1x, o1y, ph, pl);
                *(uint32_t*)&Chi[(size_t)(r0 + 8) * N + c] = ph;
                *(uint32_t*)&Clo[(size_t)(r0 + 8) * N + c] = pl;
            }
        }
    }
}

// ===========================================================================
// HMMA flash attention (causal), pre-split bf16 qkv, cp.async KV pipeline.
// (unchanged from round 7/8; passing)
// ===========================================================================
#define AQ_BYTES  (128 * 72 * 2)   // 18432
#define AKV_BYTES (64 * 72 * 2)    // 9216
#define ASTAGE    (4 * AKV_BYTES)  // 36864
#define ATTN_SMEM (2 * AQ_BYTES + 2 * ASTAGE)   // 110592

__global__ __launch_bounds__(256, 2) void attn_hmma(
    const __nv_bfloat16* __restrict__ qhiG, const __nv_bfloat16* __restrict__ qloG,
    __nv_bfloat16* __restrict__ outHi, __nv_bfloat16* __restrict__ outLo)
{
    extern __shared__ char sm[];
    const uint32_t smb = smem_u32(sm);
    const uint32_t qHA = smb;
    const uint32_t qLA = smb + AQ_BYTES;
    const int tid  = threadIdx.x;
    const int lane = tid & 31;
    const int w    = tid >> 5;
    const int qt = blockIdx.x;
    const int hd = blockIdx.y;     // head
    const int b  = blockIdx.z;
    const int qb = qt * 128;

    // ---- Q tile via cp.async (group 0) ----
#pragma unroll
    for (int j = 0; j < 4; j++) {
        int idx = tid + j * 256;
        int row = idx >> 3;
        int ch  = idx & 7;
        size_t so = ((size_t)b * TT + qb + row) * 3072 + (size_t)hd * 64 + ch * 8;
        uint32_t doff = row * 144 + ch * 16;
        CP_ASYNC_CG(qHA + doff, qhiG + so);
        CP_ASYNC_CG(qLA + doff, qloG + so);
    }

    auto issue_kv = [&](int jt2, int s) {
        uint32_t kH = smb + 2 * AQ_BYTES + s * ASTAGE;
        uint32_t kL = kH + AKV_BYTES;
        uint32_t vH = kH + 2 * AKV_BYTES;
        uint32_t vL = kH + 3 * AKV_BYTES;
        size_t base = ((size_t)b * TT + jt2 * 64) * 3072 + CC + (size_t)hd * 64;
#pragma unroll
        for (int j = 0; j < 2; j++) {
            int idx = tid + j * 256;
            int row = idx >> 3;
            int ch  = idx & 7;
            size_t so = base + (size_t)row * 3072 + ch * 8;
            uint32_t doff = row * 144 + ch * 16;
            CP_ASYNC_CG(kH + doff, qhiG + so);
            CP_ASYNC_CG(kL + doff, qloG + so);
            CP_ASYNC_CG(vH + doff, qhiG + so + CC);
            CP_ASYNC_CG(vL + doff, qloG + so + CC);
        }
    };

    issue_kv(0, 0); CP_COMMIT();    // group 0 (Q + KV0)
    issue_kv(1, 1); CP_COMMIT();    // group 1

    float S[8][4];
    float O[8][4] = {};
    float m_run[2] = { -1e30f, -1e30f };
    float l_run[2] = { 0.0f, 0.0f };
    const float scale = 0.125f;

    const int wmin = qb + w * 16;
    const int r_in = lane >> 2;
    const int c2   = (lane & 3) * 2;
    const int row0 = wmin + r_in;
    const int row1 = row0 + 8;
    const int nt = 2 * qt + 2;

    for (int jt = 0; jt < nt; jt++) {
        CP_WAIT1();
        __syncthreads();
        const int s = jt & 1;
        const int kvb = jt * 64;

        if (kvb <= wmin + 15) {       // warp-uniform: tile not fully masked
            uint32_t kHA = smb + 2 * AQ_BYTES + s * ASTAGE;
            uint32_t kLA = kHA + AKV_BYTES;
            uint32_t vHA = kHA + 2 * AKV_BYTES;
            uint32_t vLA = kHA + 3 * AKV_BYTES;

            // ---- S = Q K^T (3-pass split) ----
#pragma unroll
            for (int nf = 0; nf < 8; nf++)
#pragma unroll
                for (int e = 0; e < 4; e++) S[nf][e] = 0.0f;

#pragma unroll
            for (int ks = 0; ks < 4; ks++) {
                uint32_t qh[4], ql[4];
                uint32_t qoff = ((w * 16 + (lane & 15)) * 72 + ks * 16 + (lane >> 4) * 8) * 2;
                LDSM_X4(qh, qHA + qoff);
                LDSM_X4(ql, qLA + qoff);
#pragma unroll
                for (int np = 0; np < 4; np++) {
                    uint32_t kh[4], kl[4];
                    uint32_t koff = ((np * 16 + (lane & 15)) * 72 + ks * 16 + (lane >> 4) * 8) * 2;
                    LDSM_X4(kh, kHA + koff);
                    LDSM_X4(kl, kLA + koff);
                    MMA_BF16_2(S[2*np],   qh, kh[0], kh[2]);
                    MMA_BF16_2(S[2*np],   qh, kl[0], kl[2]);
                    MMA_BF16_2(S[2*np],   ql, kh[0], kh[2]);
                    MMA_BF16_2(S[2*np+1], qh, kh[1], kh[3]);
                    MMA_BF16_2(S[2*np+1], qh, kl[1], kl[3]);
                    MMA_BF16_2(S[2*np+1], ql, kh[1], kh[3]);
                }
            }

            // ---- scale + causal mask + row max ----
            const bool full = (kvb + 63 <= wmin);
            float mx0 = -1e30f, mx1 = -1e30f;
#pragma unroll
            for (int nf = 0; nf < 8; nf++) {
                int col = kvb + nf * 8 + c2;
                float s0 = S[nf][0] * scale;
                float s1 = S[nf][1] * scale;
                float s2 = S[nf][2] * scale;
                float s3 = S[nf][3] * scale;
                if (!full) {
                    if (col     > row0) s0 = -1e30f;
                    if (col + 1 > row0) s1 = -1e30f;
                    if (col     > row1) s2 = -1e30f;
                    if (col + 1 > row1) s3 = -1e30f;
                }
                S[nf][0] = s0; S[nf][1] = s1; S[nf][2] = s2; S[nf][3] = s3;
                mx0 = fmaxf(mx0, fmaxf(s0, s1));
                mx1 = fmaxf(mx1, fmaxf(s2, s3));
            }
            mx0 = fmaxf(mx0, __shfl_xor_sync(0xffffffffu, mx0, 1));
            mx0 = fmaxf(mx0, __shfl_xor_sync(0xffffffffu, mx0, 2));
            mx1 = fmaxf(mx1, __shfl_xor_sync(0xffffffffu, mx1, 1));
            mx1 = fmaxf(mx1, __shfl_xor_sync(0xffffffffu, mx1, 2));

            float mn0 = fmaxf(m_run[0], mx0);
            float mn1 = fmaxf(m_run[1], mx1);
            float corr0 = __expf(m_run[0] - mn0);
            float corr1 = __expf(m_run[1] - mn1);
            l_run[0] *= corr0;
            l_run[1] *= corr1;
#pragma unroll
            for (int nf = 0; nf < 8; nf++) {
                O[nf][0] *= corr0; O[nf][1] *= corr0;
                O[nf][2] *= corr1; O[nf][3] *= corr1;
            }

            float sum0 = 0.0f, sum1 = 0.0f;
#pragma unroll
            for (int nf = 0; nf < 8; nf++) {
                float p0 = __expf(S[nf][0] - mn0);
                float p1 = __expf(S[nf][1] - mn0);
                float p2 = __expf(S[nf][2] - mn1);
                float p3 = __expf(S[nf][3] - mn1);
                S[nf][0] = p0; S[nf][1] = p1; S[nf][2] = p2; S[nf][3] = p3;
                sum0 += p0 + p1;
                sum1 += p2 + p3;
            }
            sum0 += __shfl_xor_sync(0xffffffffu, sum0, 1);
            sum0 += __shfl_xor_sync(0xffffffffu, sum0, 2);
            sum1 += __shfl_xor_sync(0xffffffffu, sum1, 1);
            sum1 += __shfl_xor_sync(0xffffffffu, sum1, 2);
            l_run[0] += sum0;
            l_run[1] += sum1;
            m_run[0] = mn0;
            m_run[1] = mn1;

            // ---- O += P V (3-pass split); S frags as A frags ----
#pragma unroll
            for (int j = 0; j < 4; j++) {
                uint32_t pH[4], pL[4];
                split2(S[2*j][0],   S[2*j][1],   pH[0], pL[0]);
                split2(S[2*j][2],   S[2*j][3],   pH[1], pL[1]);
                split2(S[2*j+1][0], S[2*j+1][1], pH[2], pL[2]);
                split2(S[2*j+1][2], S[2*j+1][3], pH[3], pL[3]);
#pragma unroll
                for (int np = 0; np < 4; np++) {
                    uint32_t vh[4], vl[4];
                    uint32_t voff = ((j * 16 + (lane & 15)) * 72 + np * 16 + (lane >> 4) * 8) * 2;
                    LDSM_X4T(vh, vHA + voff);
                    LDSM_X4T(vl, vLA + voff);
                    MMA_BF16(O[2*np],   pH, vh);
                    MMA_BF16(O[2*np],   pH, vl);
                    MMA_BF16(O[2*np],   pL, vh);
                    MMA_BF16(O[2*np+1], pH, vh + 2);
                    MMA_BF16(O[2*np+1], pH, vl + 2);
                    MMA_BF16(O[2*np+1], pL, vh + 2);
                }
            }
        }

        __syncthreads();
        if (jt + 2 < nt) issue_kv(jt + 2, s);
        CP_COMMIT();
    }

    // ---- epilogue: normalize, split hi/lo, write bf16 [B,T,C] ----
    float inv0 = 1.0f / l_run[0];
    float inv1 = 1.0f / l_run[1];
    size_t o0off = ((size_t)b * TT + row0) * CC + (size_t)hd * HD;
    size_t o1off = ((size_t)b * TT + row1) * CC + (size_t)hd * HD;
#pragma unroll
    for (int nf = 0; nf < 8; nf++) {
        int c = nf * 8 + c2;
        uint32_t ph, pl;
        split2(O[nf][0] * inv0, O[nf][1] * inv0, ph, pl);
        *(uint32_t*)&outHi[o0off + c] = ph;
        *(uint32_t*)&outLo[o0off + c] = pl;
        split2(O[nf][2] * inv1, O[nf][3] * inv1, ph, pl);
        *(uint32_t*)&outHi[o1off + c] = ph;
        *(uint32_t*)&outLo[o1off + c] = pl;
    }
}

// ---------------------------------------------------------------------------
extern "C" void kernel_launch(void* const* d_in, const int* in_sizes, int n_in,
                              void* d_out, int out_size)
{
    const float* x     = (const float*)d_in[0];
    const float* Wqkv  = (const float*)d_in[1];
    const float* bqkv  = (const float*)d_in[2];
    const float* Wproj = (const float*)d_in[3];
    const float* bproj = (const float*)d_in[4];
    float* out = (float*)d_out;

    __nv_bfloat16 *xhi, *xlo, *wqhi, *wqlo, *wphi, *wplo, *qkvhi, *qkvlo, *atthi, *attlo;
    cudaGetSymbolAddress((void**)&xhi,   g_xhi);
    cudaGetSymbolAddress((void**)&xlo,   g_xlo);
    cudaGetSymbolAddress((void**)&wqhi,  g_wqhi);
    cudaGetSymbolAddress((void**)&wqlo,  g_wqlo);
    cudaGetSymbolAddress((void**)&wphi,  g_wphi);
    cudaGetSymbolAddress((void**)&wplo,  g_wplo);
    cudaGetSymbolAddress((void**)&qkvhi, g_qkvhi);
    cudaGetSymbolAddress((void**)&qkvlo, g_qkvlo);
    cudaGetSymbolAddress((void**)&atthi, g_atthi);
    cudaGetSymbolAddress((void**)&attlo, g_attlo);

    cudaFuncSetAttribute(gemm_bf16,
                         cudaFuncAttributeMaxDynamicSharedMemorySize, GEMM_SMEM);
    cudaFuncSetAttribute(attn_hmma,
                         cudaFuncAttributeMaxDynamicSharedMemorySize, ATTN_SMEM);

    // 0) pre-split inputs to hi/lo bf16
    int n4x = BT * CC / 4;
    split_f32<<<n4x / 256, 256>>>(x, xhi, xlo, n4x);
    int n4q = CC * 3 * CC / 4;
    split_f32<<<n4q / 256, 256>>>(Wqkv, wqhi, wqlo, n4q);
    int n4p = CC * CC / 4;
    split_f32<<<n4p / 256, 256>>>(Wproj, wphi, wplo, n4p);

    dim3 blk(256);
    // 1) qkv = x @ W_qkv + b_qkv  -> hi/lo bf16
    gemm_bf16<<<dim3(3 * CC / 128, BT / 128), blk, GEMM_SMEM>>>(
        xhi, xlo, wqhi, wqlo, bqkv, nullptr, qkvhi, qkvlo, BT, 3 * CC, CC, 1);
    // 2) attention -> att hi/lo bf16
    attn_hmma<<<dim3(TT / 128, HH, BB), blk, ATTN_SMEM>>>(qkvhi, qkvlo, atthi, attlo);
    // 3) out = att @ W_proj + b_proj  -> fp32
    gemm_bf16<<<dim3(CC / 128, BT / 128), blk, GEMM_SMEM>>>(
        atthi, attlo, wphi, wplo, bproj, out, nullptr, nullptr, BT, CC, CC, 0);
}

// round 10
// speedup vs baseline: 1.0471x; 1.0471x over previous
#include <cuda_runtime.h>
#include <cuda_bf16.h>
#include <cstdint>
#include <math.h>

// Problem constants
#define BB 4
#define TT 2048
#define CC 1024
#define HH 16
#define HD 64
#define BT (BB*TT)          // 8192

// Pre-split bf16 scratch (device globals: allocation-free per harness rules)
__device__ __align__(256) __nv_bfloat16 g_xhi[(size_t)BT * CC];
__device__ __align__(256) __nv_bfloat16 g_xlo[(size_t)BT * CC];
__device__ __align__(256) __nv_bfloat16 g_wqhi[(size_t)CC * 3 * CC];
__device__ __align__(256) __nv_bfloat16 g_wqlo[(size_t)CC * 3 * CC];
__device__ __align__(256) __nv_bfloat16 g_wphi[(size_t)CC * CC];
__device__ __align__(256) __nv_bfloat16 g_wplo[(size_t)CC * CC];
__device__ __align__(256) __nv_bfloat16 g_qkvhi[(size_t)BT * 3 * CC];
__device__ __align__(256) __nv_bfloat16 g_qkvlo[(size_t)BT * 3 * CC];
__device__ __align__(256) __nv_bfloat16 g_atthi[(size_t)BT * CC];
__device__ __align__(256) __nv_bfloat16 g_attlo[(size_t)BT * CC];

// ===========================================================================
// Helpers
// ===========================================================================
__device__ __forceinline__ uint32_t smem_u32(const void* p) {
    uint32_t a;
    asm("{ .reg .u64 t; cvta.to.shared.u64 t, %1; cvt.u32.u64 %0, t; }"
        : "=r"(a) : "l"(p));
    return a;
}

#define LDSM_X4(r, addr) \
    asm volatile("ldmatrix.sync.aligned.m8n8.x4.shared.b16 {%0,%1,%2,%3}, [%4];" \
        : "=r"((r)[0]), "=r"((r)[1]), "=r"((r)[2]), "=r"((r)[3]) : "r"(addr))

#define LDSM_X4T(r, addr) \
    asm volatile("ldmatrix.sync.aligned.m8n8.x4.trans.shared.b16 {%0,%1,%2,%3}, [%4];" \
        : "=r"((r)[0]), "=r"((r)[1]), "=r"((r)[2]), "=r"((r)[3]) : "r"(addr))

#define MMA_BF16(c, a, b) \
    asm volatile("mma.sync.aligned.m16n8k16.row.col.f32.bf16.bf16.f32 " \
        "{%0,%1,%2,%3}, {%4,%5,%6,%7}, {%8,%9}, {%0,%1,%2,%3};" \
        : "+f"((c)[0]), "+f"((c)[1]), "+f"((c)[2]), "+f"((c)[3]) \
        : "r"((a)[0]), "r"((a)[1]), "r"((a)[2]), "r"((a)[3]), \
          "r"((b)[0]), "r"((b)[1]))

#define MMA_BF16_2(c, a, b0, b1) \
    asm volatile("mma.sync.aligned.m16n8k16.row.col.f32.bf16.bf16.f32 " \
        "{%0,%1,%2,%3}, {%4,%5,%6,%7}, {%8,%9}, {%0,%1,%2,%3};" \
        : "+f"((c)[0]), "+f"((c)[1]), "+f"((c)[2]), "+f"((c)[3]) \
        : "r"((a)[0]), "r"((a)[1]), "r"((a)[2]), "r"((a)[3]), \
          "r"(b0), "r"(b1))

#define CP_ASYNC_CG(dst, src) \
    asm volatile("cp.async.cg.shared.global [%0], [%1], 16;" :: "r"(dst), "l"(src))
#define CP_COMMIT() asm volatile("cp.async.commit_group;" ::: "memory")
#define CP_WAIT1()  asm volatile("cp.async.wait_group 1;" ::: "memory")

__device__ __forceinline__ uint32_t pack_bf16(float a, float b) {
    __nv_bfloat162 t = __floats2bfloat162_rn(a, b);
    return *(uint32_t*)&t;
}

// split x into hi (bf16-representable float) and lo = x - hi
__device__ __forceinline__ void split2(float a, float b, uint32_t& hi, uint32_t& lo) {
    float ha = __bfloat162float(__float2bfloat16(a));
    float hb = __bfloat162float(__float2bfloat16(b));
    hi = pack_bf16(ha, hb);
    lo = pack_bf16(a - ha, b - hb);
}

// ===========================================================================
// split_f32: fp32 array -> hi/lo bf16 arrays (4 elems/thread)
// ===========================================================================
__global__ __launch_bounds__(256) void split_f32(
    const float* __restrict__ in, __nv_bfloat16* __restrict__ hi,
    __nv_bfloat16* __restrict__ lo, int n4)
{
    int i = blockIdx.x * 256 + threadIdx.x;
    if (i >= n4) return;
    float4 v = ((const float4*)in)[i];
    uint32_t h0, l0, h1, l1;
    split2(v.x, v.y, h0, l0);
    split2(v.z, v.w, h1, l1);
    ((uint2*)hi)[i] = make_uint2(h0, h1);
    ((uint2*)lo)[i] = make_uint2(l0, l1);
}

// ===========================================================================
// HMMA split-bf16 GEMM, pre-split bf16 inputs, 3-stage cp.async pipeline,
// ONE __syncthreads per 32-K chunk.  2 CTAs/SM (R8 config).
// Pass-major MMA order: HH over all accs, then HL, then LH -> no acc RAW chains.
// 128x128 tile, BK=32, 8 warps (2x4), warp tile 64x32.
// ===========================================================================
#define GA_STRIDE 40          // bf16 elems/row (32+8) -> conflict-free ldsm
#define GB_STRIDE 136         // bf16 elems/row (128+8)
#define GA_BYTES (128 * GA_STRIDE * 2)   // 10240
#define GB_BYTES (32 * GB_STRIDE * 2)    // 8704
#define GBUF (2 * GA_BYTES + 2 * GB_BYTES)   // 37888
#define GEMM_SMEM (3 * GBUF)                  // 113664

__global__ __launch_bounds__(256, 2) void gemm_bf16(
    const __nv_bfloat16* __restrict__ Ahi, const __nv_bfloat16* __restrict__ Alo,
    const __nv_bfloat16* __restrict__ Bhi, const __nv_bfloat16* __restrict__ Blo,
    const float* __restrict__ bias,
    float* __restrict__ Cf,
    __nv_bfloat16* __restrict__ Chi, __nv_bfloat16* __restrict__ Clo,
    int M, int N, int K, int outSplit)
{
    extern __shared__ char sm[];
    const uint32_t smb = smem_u32(sm);
    const int tid  = threadIdx.x;
    const int lane = tid & 31;
    const int wid  = tid >> 5;
    const int wm   = wid >> 2;
    const int wn   = wid & 3;
    const int rowBase = blockIdx.y * 128;
    const int colBase = blockIdx.x * 128;

    auto issue = [&](int k0, int bi) {
        uint32_t aH = smb + bi * GBUF;
        uint32_t aL = aH + GA_BYTES;
        uint32_t bH = aH + 2 * GA_BYTES;
        uint32_t bL = bH + GB_BYTES;
#pragma unroll
        for (int j = 0; j < 2; j++) {
            int idx = tid + j * 256;
            int m  = idx >> 2;
            int ch = idx & 3;
            size_t ao = (size_t)(rowBase + m) * K + k0 + ch * 8;
            uint32_t ad = m * 80 + ch * 16;
            CP_ASYNC_CG(aH + ad, Ahi + ao);
            CP_ASYNC_CG(aL + ad, Alo + ao);
            int kk = idx >> 4;
            int c2 = idx & 15;
            size_t bo = (size_t)(k0 + kk) * N + colBase + c2 * 8;
            uint32_t bd = kk * 272 + c2 * 16;
            CP_ASYNC_CG(bH + bd, Bhi + bo);
            CP_ASYNC_CG(bL + bd, Blo + bo);
        }
    };

    float acc[4][4][4] = {};
    const int NS = K >> 5;

    // prologue: stages 0 and 1 in flight
    issue(0, 0);  CP_COMMIT();
    issue(32, 1); CP_COMMIT();

    int buf = 0;        // c % 3
    int nbuf = 2;       // (c+2) % 3
    for (int c = 0; c < NS; c++) {
        CP_WAIT1();
        __syncthreads();

        if (c + 2 < NS) issue((c + 2) << 5, nbuf);
        CP_COMMIT();

        uint32_t aH = smb + buf * GBUF;
        uint32_t aL = aH + GA_BYTES;
        uint32_t bH = aH + 2 * GA_BYTES;
        uint32_t bL = bH + GB_BYTES;

#pragma unroll
        for (int ks = 0; ks < 2; ks++) {
            uint32_t fAH[4][4], fAL[4][4];
#pragma unroll
            for (int mf = 0; mf < 4; mf++) {
                uint32_t off = ((wm * 64 + mf * 16 + (lane & 15)) * GA_STRIDE
                                + ks * 16 + (lane >> 4) * 8) * 2;
                LDSM_X4(fAH[mf], aH + off);
                LDSM_X4(fAL[mf], aL + off);
            }
            uint32_t fBH[2][4], fBL[2][4];
#pragma unroll
            for (int nq = 0; nq < 2; nq++) {
                uint32_t off = ((ks * 16 + (lane & 15)) * GB_STRIDE
                                + wn * 32 + nq * 16 + (lane >> 4) * 8) * 2;
                LDSM_X4T(fBH[nq], bH + off);
                LDSM_X4T(fBL[nq], bL + off);
            }
            // pass HH: all 16 accumulators, no RAW between consecutive MMAs
#pragma unroll
            for (int nq = 0; nq < 2; nq++)
#pragma unroll
                for (int mf = 0; mf < 4; mf++) {
                    MMA_BF16(acc[mf][2*nq],   fAH[mf], fBH[nq]);
                    MMA_BF16(acc[mf][2*nq+1], fAH[mf], fBH[nq] + 2);
                }
            // pass HL
#pragma unroll
            for (int nq = 0; nq < 2; nq++)
#pragma unroll
                for (int mf = 0; mf < 4; mf++) {
                    MMA_BF16(acc[mf][2*nq],   fAH[mf], fBL[nq]);
                    MMA_BF16(acc[mf][2*nq+1], fAH[mf], fBL[nq] + 2);
                }
            // pass LH
#pragma unroll
            for (int nq = 0; nq < 2; nq++)
#pragma unroll
                for (int mf = 0; mf < 4; mf++) {
                    MMA_BF16(acc[mf][2*nq],   fAL[mf], fBH[nq]);
                    MMA_BF16(acc[mf][2*nq+1], fAL[mf], fBH[nq] + 2);
                }
        }
        buf  = (buf  == 2) ? 0 : buf + 1;
        nbuf = (nbuf == 2) ? 0 : nbuf + 1;
    }

    // ---- Epilogue ----
#pragma unroll
    for (int nf = 0; nf < 4; nf++) {
        int c = colBase + wn * 32 + nf * 8 + 2 * (lane & 3);
        float2 bv = *(const float2*)&bias[c];
#pragma unroll
        for (int mf = 0; mf < 4; mf++) {
            int r0 = rowBase + wm * 64 + mf * 16 + (lane >> 2);
            float o0x = acc[mf][nf][0] + bv.x, o0y = acc[mf][nf][1] + bv.y;
            float o1x = acc[mf][nf][2] + bv.x, o1y = acc[mf][nf][3] + bv.y;
            if (!outSplit) {
                *(float2*)&Cf[(size_t)r0 * N + c] = make_float2(o0x, o0y);
                *(float2*)&Cf[(size_t)(r0 + 8) * N + c] = make_float2(o1x, o1y);
            } else {
                uint32_t ph, pl;
                split2(o0x, o0y, ph, pl);
                *(uint32_t*)&Chi[(size_t)r0 * N + c] = ph;
                *(uint32_t*)&Clo[(size_t)r0 * N + c] = pl;
                split2(o1x, o1y, ph, pl);
                *(uint32_t*)&Chi[(size_t)(r0 + 8) * N + c] = ph;
                *(uint32_t*)&Clo[(size_t)(r0 + 8) * N + c] = pl;
            }
        }
    }
}

// ===========================================================================
// HMMA flash attention (causal), pre-split bf16 qkv, cp.async KV pipeline.
// (unchanged from round 7/8; passing)
// ===========================================================================
#define AQ_BYTES  (128 * 72 * 2)   // 18432
#define AKV_BYTES (64 * 72 * 2)    // 9216
#define ASTAGE    (4 * AKV_BYTES)  // 36864
#define ATTN_SMEM (2 * AQ_BYTES + 2 * ASTAGE)   // 110592

__global__ __launch_bounds__(256, 2) void attn_hmma(
    const __nv_bfloat16* __restrict__ qhiG, const __nv_bfloat16* __restrict__ qloG,
    __nv_bfloat16* __restrict__ outHi, __nv_bfloat16* __restrict__ outLo)
{
    extern __shared__ char sm[];
    const uint32_t smb = smem_u32(sm);
    const uint32_t qHA = smb;
    const uint32_t qLA = smb + AQ_BYTES;
    const int tid  = threadIdx.x;
    const int lane = tid & 31;
    const int w    = tid >> 5;
    const int qt = blockIdx.x;
    const int hd = blockIdx.y;     // head
    const int b  = blockIdx.z;
    const int qb = qt * 128;

    // ---- Q tile via cp.async (group 0) ----
#pragma unroll
    for (int j = 0; j < 4; j++) {
        int idx = tid + j * 256;
        int row = idx >> 3;
        int ch  = idx & 7;
        size_t so = ((size_t)b * TT + qb + row) * 3072 + (size_t)hd * 64 + ch * 8;
        uint32_t doff = row * 144 + ch * 16;
        CP_ASYNC_CG(qHA + doff, qhiG + so);
        CP_ASYNC_CG(qLA + doff, qloG + so);
    }

    auto issue_kv = [&](int jt2, int s) {
        uint32_t kH = smb + 2 * AQ_BYTES + s * ASTAGE;
        uint32_t kL = kH + AKV_BYTES;
        uint32_t vH = kH + 2 * AKV_BYTES;
        uint32_t vL = kH + 3 * AKV_BYTES;
        size_t base = ((size_t)b * TT + jt2 * 64) * 3072 + CC + (size_t)hd * 64;
#pragma unroll
        for (int j = 0; j < 2; j++) {
            int idx = tid + j * 256;
            int row = idx >> 3;
            int ch  = idx & 7;
            size_t so = base + (size_t)row * 3072 + ch * 8;
            uint32_t doff = row * 144 + ch * 16;
            CP_ASYNC_CG(kH + doff, qhiG + so);
            CP_ASYNC_CG(kL + doff, qloG + so);
            CP_ASYNC_CG(vH + doff, qhiG + so + CC);
            CP_ASYNC_CG(vL + doff, qloG + so + CC);
        }
    };

    issue_kv(0, 0); CP_COMMIT();    // group 0 (Q + KV0)
    issue_kv(1, 1); CP_COMMIT();    // group 1

    float S[8][4];
    float O[8][4] = {};
    float m_run[2] = { -1e30f, -1e30f };
    float l_run[2] = { 0.0f, 0.0f };
    const float scale = 0.125f;

    const int wmin = qb + w * 16;
    const int r_in = lane >> 2;
    const int c2   = (lane & 3) * 2;
    const int row0 = wmin + r_in;
    const int row1 = row0 + 8;
    const int nt = 2 * qt + 2;

    for (int jt = 0; jt < nt; jt++) {
        CP_WAIT1();
        __syncthreads();
        const int s = jt & 1;
        const int kvb = jt * 64;

        if (kvb <= wmin + 15) {       // warp-uniform: tile not fully masked
            uint32_t kHA = smb + 2 * AQ_BYTES + s * ASTAGE;
            uint32_t kLA = kHA + AKV_BYTES;
            uint32_t vHA = kHA + 2 * AKV_BYTES;
            uint32_t vLA = kHA + 3 * AKV_BYTES;

            // ---- S = Q K^T (3-pass split) ----
#pragma unroll
            for (int nf = 0; nf < 8; nf++)
#pragma unroll
                for (int e = 0; e < 4; e++) S[nf][e] = 0.0f;

#pragma unroll
            for (int ks = 0; ks < 4; ks++) {
                uint32_t qh[4], ql[4];
                uint32_t qoff = ((w * 16 + (lane & 15)) * 72 + ks * 16 + (lane >> 4) * 8) * 2;
                LDSM_X4(qh, qHA + qoff);
                LDSM_X4(ql, qLA + qoff);
#pragma unroll
                for (int np = 0; np < 4; np++) {
                    uint32_t kh[4], kl[4];
                    uint32_t koff = ((np * 16 + (lane & 15)) * 72 + ks * 16 + (lane >> 4) * 8) * 2;
                    LDSM_X4(kh, kHA + koff);
                    LDSM_X4(kl, kLA + koff);
                    MMA_BF16_2(S[2*np],   qh, kh[0], kh[2]);
                    MMA_BF16_2(S[2*np+1], qh, kh[1], kh[3]);
                    MMA_BF16_2(S[2*np],   qh, kl[0], kl[2]);
                    MMA_BF16_2(S[2*np+1], qh, kl[1], kl[3]);
                    MMA_BF16_2(S[2*np],   ql, kh[0], kh[2]);
                    MMA_BF16_2(S[2*np+1], ql, kh[1], kh[3]);
                }
            }

            // ---- scale + causal mask + row max ----
            const bool full = (kvb + 63 <= wmin);
            float mx0 = -1e30f, mx1 = -1e30f;
#pragma unroll
            for (int nf = 0; nf < 8; nf++) {
                int col = kvb + nf * 8 + c2;
                float s0 = S[nf][0] * scale;
                float s1 = S[nf][1] * scale;
                float s2 = S[nf][2] * scale;
                float s3 = S[nf][3] * scale;
                if (!full) {
                    if (col     > row0) s0 = -1e30f;
                    if (col + 1 > row0) s1 = -1e30f;
                    if (col     > row1) s2 = -1e30f;
                    if (col + 1 > row1) s3 = -1e30f;
                }
                S[nf][0] = s0; S[nf][1] = s1; S[nf][2] = s2; S[nf][3] = s3;
                mx0 = fmaxf(mx0, fmaxf(s0, s1));
                mx1 = fmaxf(mx1, fmaxf(s2, s3));
            }
            mx0 = fmaxf(mx0, __shfl_xor_sync(0xffffffffu, mx0, 1));
            mx0 = fmaxf(mx0, __shfl_xor_sync(0xffffffffu, mx0, 2));
            mx1 = fmaxf(mx1, __shfl_xor_sync(0xffffffffu, mx1, 1));
            mx1 = fmaxf(mx1, __shfl_xor_sync(0xffffffffu, mx1, 2));

            float mn0 = fmaxf(m_run[0], mx0);
            float mn1 = fmaxf(m_run[1], mx1);
            float corr0 = __expf(m_run[0] - mn0);
            float corr1 = __expf(m_run[1] - mn1);
            l_run[0] *= corr0;
            l_run[1] *= corr1;
#pragma unroll
            for (int nf = 0; nf < 8; nf++) {
                O[nf][0] *= corr0; O[nf][1] *= corr0;
                O[nf][2] *= corr1; O[nf][3] *= corr1;
            }

            float sum0 = 0.0f, sum1 = 0.0f;
#pragma unroll
            for (int nf = 0; nf < 8; nf++) {
                float p0 = __expf(S[nf][0] - mn0);
                float p1 = __expf(S[nf][1] - mn0);
                float p2 = __expf(S[nf][2] - mn1);
                float p3 = __expf(S[nf][3] - mn1);
                S[nf][0] = p0; S[nf][1] = p1; S[nf][2] = p2; S[nf][3] = p3;
                sum0 += p0 + p1;
                sum1 += p2 + p3;
            }
            sum0 += __shfl_xor_sync(0xffffffffu, sum0, 1);
            sum0 += __shfl_xor_sync(0xffffffffu, sum0, 2);
            sum1 += __shfl_xor_sync(0xffffffffu, sum1, 1);
            sum1 += __shfl_xor_sync(0xffffffffu, sum1, 2);
            l_run[0] += sum0;
            l_run[1] += sum1;
            m_run[0] = mn0;
            m_run[1] = mn1;

            // ---- O += P V (3-pass split); S frags as A frags ----
#pragma unroll
            for (int j = 0; j < 4; j++) {
                uint32_t pH[4], pL[4];
                split2(S[2*j][0],   S[2*j][1],   pH[0], pL[0]);
                split2(S[2*j][2],   S[2*j][3],   pH[1], pL[1]);
                split2(S[2*j+1][0], S[2*j+1][1], pH[2], pL[2]);
                split2(S[2*j+1][2], S[2*j+1][3], pH[3], pL[3]);
#pragma unroll
                for (int np = 0; np < 4; np++) {
                    uint32_t vh[4], vl[4];
                    uint32_t voff = ((j * 16 + (lane & 15)) * 72 + np * 16 + (lane >> 4) * 8) * 2;
                    LDSM_X4T(vh, vHA + voff);
                    LDSM_X4T(vl, vLA + voff);
                    MMA_BF16(O[2*np],   pH, vh);
                    MMA_BF16(O[2*np+1], pH, vh + 2);
                    MMA_BF16(O[2*np],   pH, vl);
                    MMA_BF16(O[2*np+1], pH, vl + 2);
                    MMA_BF16(O[2*np],   pL, vh);
                    MMA_BF16(O[2*np+1], pL, vh + 2);
                }
            }
        }

        __syncthreads();
        if (jt + 2 < nt) issue_kv(jt + 2, s);
        CP_COMMIT();
    }

    // ---- epilogue: normalize, split hi/lo, write bf16 [B,T,C] ----
    float inv0 = 1.0f / l_run[0];
    float inv1 = 1.0f / l_run[1];
    size_t o0off = ((size_t)b * TT + row0) * CC + (size_t)hd * HD;
    size_t o1off = ((size_t)b * TT + row1) * CC + (size_t)hd * HD;
#pragma unroll
    for (int nf = 0; nf < 8; nf++) {
        int c = nf * 8 + c2;
        uint32_t ph, pl;
        split2(O[nf][0] * inv0, O[nf][1] * inv0, ph, pl);
        *(uint32_t*)&outHi[o0off + c] = ph;
        *(uint32_t*)&outLo[o0off + c] = pl;
        split2(O[nf][2] * inv1, O[nf][3] * inv1, ph, pl);
        *(uint32_t*)&outHi[o1off + c] = ph;
        *(uint32_t*)&outLo[o1off + c] = pl;
    }
}

// ---------------------------------------------------------------------------
extern "C" void kernel_launch(void* const* d_in, const int* in_sizes, int n_in,
                              void* d_out, int out_size)
{
    const float* x     = (const float*)d_in[0];
    const float* Wqkv  = (const float*)d_in[1];
    const float* bqkv  = (const float*)d_in[2];
    const float* Wproj = (const float*)d_in[3];
    const float* bproj = (const float*)d_in[4];
    float* out = (float*)d_out;

    __nv_bfloat16 *xhi, *xlo, *wqhi, *wqlo, *wphi, *wplo, *qkvhi, *qkvlo, *atthi, *attlo;
    cudaGetSymbolAddress((void**)&xhi,   g_xhi);
    cudaGetSymbolAddress((void**)&xlo,   g_xlo);
    cudaGetSymbolAddress((void**)&wqhi,  g_wqhi);
    cudaGetSymbolAddress((void**)&wqlo,  g_wqlo);
    cudaGetSymbolAddress((void**)&wphi,  g_wphi);
    cudaGetSymbolAddress((void**)&wplo,  g_wplo);
    cudaGetSymbolAddress((void**)&qkvhi, g_qkvhi);
    cudaGetSymbolAddress((void**)&qkvlo, g_qkvlo);
    cudaGetSymbolAddress((void**)&atthi, g_atthi);
    cudaGetSymbolAddress((void**)&attlo, g_attlo);

    cudaFuncSetAttribute(gemm_bf16,
                         cudaFuncAttributeMaxDynamicSharedMemorySize, GEMM_SMEM);
    cudaFuncSetAttribute(attn_hmma,
                         cudaFuncAttributeMaxDynamicSharedMemorySize, ATTN_SMEM);

    // 0) pre-split inputs to hi/lo bf16
    int n4x = BT * CC / 4;
    split_f32<<<n4x / 256, 256>>>(x, xhi, xlo, n4x);
    int n4q = CC * 3 * CC / 4;
    split_f32<<<n4q / 256, 256>>>(Wqkv, wqhi, wqlo, n4q);
    int n4p = CC * CC / 4;
    split_f32<<<n4p / 256, 256>>>(Wproj, wphi, wplo, n4p);

    dim3 blk(256);
    // 1) qkv = x @ W_qkv + b_qkv  -> hi/lo bf16
    gemm_bf16<<<dim3(3 * CC / 128, BT / 128), blk, GEMM_SMEM>>>(
        xhi, xlo, wqhi, wqlo, bqkv, nullptr, qkvhi, qkvlo, BT, 3 * CC, CC, 1);
    // 2) attention -> att hi/lo bf16
    attn_hmma<<<dim3(TT / 128, HH, BB), blk, ATTN_SMEM>>>(qkvhi, qkvlo, atthi, attlo);
    // 3) out = att @ W_proj + b_proj  -> fp32
    gemm_bf16<<<dim3(CC / 128, BT / 128), blk, GEMM_SMEM>>>(
        atthi, attlo, wphi, wplo, bproj, out, nullptr, nullptr, BT, CC, CC, 0);
}

// round 11
// speedup vs baseline: 1.0561x; 1.0086x over previous
#include <cuda_runtime.h>
#include <cuda_bf16.h>
#include <cstdint>
#include <math.h>

// Problem constants
#define BB 4
#define TT 2048
#define CC 1024
#define HH 16
#define HD 64
#define BT (BB*TT)          // 8192

// Pre-split bf16 scratch (device globals: allocation-free per harness rules)
__device__ __align__(256) __nv_bfloat16 g_xhi[(size_t)BT * CC];
__device__ __align__(256) __nv_bfloat16 g_xlo[(size_t)BT * CC];
__device__ __align__(256) __nv_bfloat16 g_wqhi[(size_t)CC * 3 * CC];
__device__ __align__(256) __nv_bfloat16 g_wqlo[(size_t)CC * 3 * CC];
__device__ __align__(256) __nv_bfloat16 g_wphi[(size_t)CC * CC];
__device__ __align__(256) __nv_bfloat16 g_wplo[(size_t)CC * CC];
__device__ __align__(256) __nv_bfloat16 g_qkvhi[(size_t)BT * 3 * CC];
__device__ __align__(256) __nv_bfloat16 g_qkvlo[(size_t)BT * 3 * CC];
__device__ __align__(256) __nv_bfloat16 g_atthi[(size_t)BT * CC];
__device__ __align__(256) __nv_bfloat16 g_attlo[(size_t)BT * CC];

// ===========================================================================
// Helpers
// ===========================================================================
__device__ __forceinline__ uint32_t smem_u32(const void* p) {
    uint32_t a;
    asm("{ .reg .u64 t; cvta.to.shared.u64 t, %1; cvt.u32.u64 %0, t; }"
        : "=r"(a) : "l"(p));
    return a;
}

#define LDSM_X4(r, addr) \
    asm volatile("ldmatrix.sync.aligned.m8n8.x4.shared.b16 {%0,%1,%2,%3}, [%4];" \
        : "=r"((r)[0]), "=r"((r)[1]), "=r"((r)[2]), "=r"((r)[3]) : "r"(addr))

#define LDSM_X4T(r, addr) \
    asm volatile("ldmatrix.sync.aligned.m8n8.x4.trans.shared.b16 {%0,%1,%2,%3}, [%4];" \
        : "=r"((r)[0]), "=r"((r)[1]), "=r"((r)[2]), "=r"((r)[3]) : "r"(addr))

#define MMA_BF16(c, a, b) \
    asm volatile("mma.sync.aligned.m16n8k16.row.col.f32.bf16.bf16.f32 " \
        "{%0,%1,%2,%3}, {%4,%5,%6,%7}, {%8,%9}, {%0,%1,%2,%3};" \
        : "+f"((c)[0]), "+f"((c)[1]), "+f"((c)[2]), "+f"((c)[3]) \
        : "r"((a)[0]), "r"((a)[1]), "r"((a)[2]), "r"((a)[3]), \
          "r"((b)[0]), "r"((b)[1]))

#define MMA_BF16_2(c, a, b0, b1) \
    asm volatile("mma.sync.aligned.m16n8k16.row.col.f32.bf16.bf16.f32 " \
        "{%0,%1,%2,%3}, {%4,%5,%6,%7}, {%8,%9}, {%0,%1,%2,%3};" \
        : "+f"((c)[0]), "+f"((c)[1]), "+f"((c)[2]), "+f"((c)[3]) \
        : "r"((a)[0]), "r"((a)[1]), "r"((a)[2]), "r"((a)[3]), \
          "r"(b0), "r"(b1))

#define CP_ASYNC_CG(dst, src) \
    asm volatile("cp.async.cg.shared.global [%0], [%1], 16;" :: "r"(dst), "l"(src))
#define CP_COMMIT() asm volatile("cp.async.commit_group;" ::: "memory")
#define CP_WAIT1()  asm volatile("cp.async.wait_group 1;" ::: "memory")

__device__ __forceinline__ uint32_t pack_bf16(float a, float b) {
    __nv_bfloat162 t = __floats2bfloat162_rn(a, b);
    return *(uint32_t*)&t;
}

// split x into hi (bf16-representable float) and lo = x - hi
__device__ __forceinline__ void split2(float a, float b, uint32_t& hi, uint32_t& lo) {
    float ha = __bfloat162float(__float2bfloat16(a));
    float hb = __bfloat162float(__float2bfloat16(b));
    hi = pack_bf16(ha, hb);
    lo = pack_bf16(a - ha, b - hb);
}

// ===========================================================================
// split_f32: fp32 array -> hi/lo bf16 arrays (4 elems/thread)
// ===========================================================================
__global__ __launch_bounds__(256) void split_f32(
    const float* __restrict__ in, __nv_bfloat16* __restrict__ hi,
    __nv_bfloat16* __restrict__ lo, int n4)
{
    int i = blockIdx.x * 256 + threadIdx.x;
    if (i >= n4) return;
    float4 v = ((const float4*)in)[i];
    uint32_t h0, l0, h1, l1;
    split2(v.x, v.y, h0, l0);
    split2(v.z, v.w, h1, l1);
    ((uint2*)hi)[i] = make_uint2(h0, h1);
    ((uint2*)lo)[i] = make_uint2(l0, l1);
}

// ===========================================================================
// HMMA split-bf16 GEMM, pre-split bf16 inputs, 3-stage cp.async pipeline,
// ONE __syncthreads per 32-K chunk.  2 CTAs/SM.  (R8 config — best measured.)
// C = A@B + bias; output fp32 OR hi/lo bf16 pair (outSplit).
// 128x128 tile, BK=32, 8 warps (2x4), warp tile 64x32.
// ===========================================================================
#define GA_STRIDE 40          // bf16 elems/row (32+8) -> conflict-free ldsm
#define GB_STRIDE 136         // bf16 elems/row (128+8)
#define GA_BYTES (128 * GA_STRIDE * 2)   // 10240
#define GB_BYTES (32 * GB_STRIDE * 2)    // 8704
#define GBUF (2 * GA_BYTES + 2 * GB_BYTES)   // 37888
#define GEMM_SMEM (3 * GBUF)                  // 113664

__global__ __launch_bounds__(256, 2) void gemm_bf16(
    const __nv_bfloat16* __restrict__ Ahi, const __nv_bfloat16* __restrict__ Alo,
    const __nv_bfloat16* __restrict__ Bhi, const __nv_bfloat16* __restrict__ Blo,
    const float* __restrict__ bias,
    float* __restrict__ Cf,
    __nv_bfloat16* __restrict__ Chi, __nv_bfloat16* __restrict__ Clo,
    int M, int N, int K, int outSplit)
{
    extern __shared__ char sm[];
    const uint32_t smb = smem_u32(sm);
    const int tid  = threadIdx.x;
    const int lane = tid & 31;
    const int wid  = tid >> 5;
    const int wm   = wid >> 2;
    const int wn   = wid & 3;
    const int rowBase = blockIdx.y * 128;
    const int colBase = blockIdx.x * 128;

    auto issue = [&](int k0, int bi) {
        uint32_t aH = smb + bi * GBUF;
        uint32_t aL = aH + GA_BYTES;
        uint32_t bH = aH + 2 * GA_BYTES;
        uint32_t bL = bH + GB_BYTES;
#pragma unroll
        for (int j = 0; j < 2; j++) {
            int idx = tid + j * 256;
            int m  = idx >> 2;
            int ch = idx & 3;
            size_t ao = (size_t)(rowBase + m) * K + k0 + ch * 8;
            uint32_t ad = m * 80 + ch * 16;
            CP_ASYNC_CG(aH + ad, Ahi + ao);
            CP_ASYNC_CG(aL + ad, Alo + ao);
            int kk = idx >> 4;
            int c2 = idx & 15;
            size_t bo = (size_t)(k0 + kk) * N + colBase + c2 * 8;
            uint32_t bd = kk * 272 + c2 * 16;
            CP_ASYNC_CG(bH + bd, Bhi + bo);
            CP_ASYNC_CG(bL + bd, Blo + bo);
        }
    };

    float acc[4][4][4] = {};
    const int NS = K >> 5;

    // prologue: stages 0 and 1 in flight
    issue(0, 0);  CP_COMMIT();
    issue(32, 1); CP_COMMIT();

    int buf = 0;        // c % 3
    int nbuf = 2;       // (c+2) % 3
    for (int c = 0; c < NS; c++) {
        CP_WAIT1();
        __syncthreads();

        if (c + 2 < NS) issue((c + 2) << 5, nbuf);
        CP_COMMIT();

        uint32_t aH = smb + buf * GBUF;
        uint32_t aL = aH + GA_BYTES;
        uint32_t bH = aH + 2 * GA_BYTES;
        uint32_t bL = bH + GB_BYTES;

#pragma unroll
        for (int ks = 0; ks < 2; ks++) {
            uint32_t fAH[4][4], fAL[4][4];
#pragma unroll
            for (int mf = 0; mf < 4; mf++) {
                uint32_t off = ((wm * 64 + mf * 16 + (lane & 15)) * GA_STRIDE
                                + ks * 16 + (lane >> 4) * 8) * 2;
                LDSM_X4(fAH[mf], aH + off);
                LDSM_X4(fAL[mf], aL + off);
            }
#pragma unroll
            for (int nq = 0; nq < 2; nq++) {
                uint32_t fBH[4], fBL[4];
                uint32_t off = ((ks * 16 + (lane & 15)) * GB_STRIDE
                                + wn * 32 + nq * 16 + (lane >> 4) * 8) * 2;
                LDSM_X4T(fBH, bH + off);
                LDSM_X4T(fBL, bL + off);
#pragma unroll
                for (int mf = 0; mf < 4; mf++) {
                    MMA_BF16(acc[mf][2*nq],   fAH[mf], fBH);
                    MMA_BF16(acc[mf][2*nq],   fAH[mf], fBL);
                    MMA_BF16(acc[mf][2*nq],   fAL[mf], fBH);
                    MMA_BF16(acc[mf][2*nq+1], fAH[mf], fBH + 2);
                    MMA_BF16(acc[mf][2*nq+1], fAH[mf], fBL + 2);
                    MMA_BF16(acc[mf][2*nq+1], fAL[mf], fBH + 2);
                }
            }
        }
        buf  = (buf  == 2) ? 0 : buf + 1;
        nbuf = (nbuf == 2) ? 0 : nbuf + 1;
    }

    // ---- Epilogue ----
#pragma unroll
    for (int nf = 0; nf < 4; nf++) {
        int c = colBase + wn * 32 + nf * 8 + 2 * (lane & 3);
        float2 bv = *(const float2*)&bias[c];
#pragma unroll
        for (int mf = 0; mf < 4; mf++) {
            int r0 = rowBase + wm * 64 + mf * 16 + (lane >> 2);
            float o0x = acc[mf][nf][0] + bv.x, o0y = acc[mf][nf][1] + bv.y;
            float o1x = acc[mf][nf][2] + bv.x, o1y = acc[mf][nf][3] + bv.y;
            if (!outSplit) {
                *(float2*)&Cf[(size_t)r0 * N + c] = make_float2(o0x, o0y);
                *(float2*)&Cf[(size_t)(r0 + 8) * N + c] = make_float2(o1x, o1y);
            } else {
                uint32_t ph, pl;
                split2(o0x, o0y, ph, pl);
                *(uint32_t*)&Chi[(size_t)r0 * N + c] = ph;
                *(uint32_t*)&Clo[(size_t)r0 * N + c] = pl;
                split2(o1x, o1y, ph, pl);
                *(uint32_t*)&Chi[(size_t)(r0 + 8) * N + c] = ph;
                *(uint32_t*)&Clo[(size_t)(r0 + 8) * N + c] = pl;
            }
        }
    }
}

// ===========================================================================
// HMMA flash attention (causal), pre-split bf16 qkv, cp.async KV pipeline.
// Heavy-first scheduling: qt = gridDim.x-1-blockIdx.x so the longest CTAs
// (largest causal span) launch first, packing light CTAs into the tail.
// ===========================================================================
#define AQ_BYTES  (128 * 72 * 2)   // 18432
#define AKV_BYTES (64 * 72 * 2)    // 9216
#define ASTAGE    (4 * AKV_BYTES)  // 36864
#define ATTN_SMEM (2 * AQ_BYTES + 2 * ASTAGE)   // 110592

__global__ __launch_bounds__(256, 2) void attn_hmma(
    const __nv_bfloat16* __restrict__ qhiG, const __nv_bfloat16* __restrict__ qloG,
    __nv_bfloat16* __restrict__ outHi, __nv_bfloat16* __restrict__ outLo)
{
    extern __shared__ char sm[];
    const uint32_t smb = smem_u32(sm);
    const uint32_t qHA = smb;
    const uint32_t qLA = smb + AQ_BYTES;
    const int tid  = threadIdx.x;
    const int lane = tid & 31;
    const int w    = tid >> 5;
    const int qt = gridDim.x - 1 - blockIdx.x;   // heavy-first
    const int hd = blockIdx.y;     // head
    const int b  = blockIdx.z;
    const int qb = qt * 128;

    // ---- Q tile via cp.async (group 0) ----
#pragma unroll
    for (int j = 0; j < 4; j++) {
        int idx = tid + j * 256;
        int row = idx >> 3;
        int ch  = idx & 7;
        size_t so = ((size_t)b * TT + qb + row) * 3072 + (size_t)hd * 64 + ch * 8;
        uint32_t doff = row * 144 + ch * 16;
        CP_ASYNC_CG(qHA + doff, qhiG + so);
        CP_ASYNC_CG(qLA + doff, qloG + so);
    }

    auto issue_kv = [&](int jt2, int s) {
        uint32_t kH = smb + 2 * AQ_BYTES + s * ASTAGE;
        uint32_t kL = kH + AKV_BYTES;
        uint32_t vH = kH + 2 * AKV_BYTES;
        uint32_t vL = kH + 3 * AKV_BYTES;
        size_t base = ((size_t)b * TT + jt2 * 64) * 3072 + CC + (size_t)hd * 64;
#pragma unroll
        for (int j = 0; j < 2; j++) {
            int idx = tid + j * 256;
            int row = idx >> 3;
            int ch  = idx & 7;
            size_t so = base + (size_t)row * 3072 + ch * 8;
            uint32_t doff = row * 144 + ch * 16;
            CP_ASYNC_CG(kH + doff, qhiG + so);
            CP_ASYNC_CG(kL + doff, qloG + so);
            CP_ASYNC_CG(vH + doff, qhiG + so + CC);
            CP_ASYNC_CG(vL + doff, qloG + so + CC);
        }
    };

    issue_kv(0, 0); CP_COMMIT();    // group 0 (Q + KV0)
    issue_kv(1, 1); CP_COMMIT();    // group 1

    float S[8][4];
    float O[8][4] = {};
    float m_run[2] = { -1e30f, -1e30f };
    float l_run[2] = { 0.0f, 0.0f };
    const float scale = 0.125f;

    const int wmin = qb + w * 16;
    const int r_in = lane >> 2;
    const int c2   = (lane & 3) * 2;
    const int row0 = wmin + r_in;
    const int row1 = row0 + 8;
    const int nt = 2 * qt + 2;

    for (int jt = 0; jt < nt; jt++) {
        CP_WAIT1();
        __syncthreads();
        const int s = jt & 1;
        const int kvb = jt * 64;

        if (kvb <= wmin + 15) {       // warp-uniform: tile not fully masked
            uint32_t kHA = smb + 2 * AQ_BYTES + s * ASTAGE;
            uint32_t kLA = kHA + AKV_BYTES;
            uint32_t vHA = kHA + 2 * AKV_BYTES;
            uint32_t vLA = kHA + 3 * AKV_BYTES;

            // ---- S = Q K^T (3-pass split) ----
#pragma unroll
            for (int nf = 0; nf < 8; nf++)
#pragma unroll
                for (int e = 0; e < 4; e++) S[nf][e] = 0.0f;

#pragma unroll
            for (int ks = 0; ks < 4; ks++) {
                uint32_t qh[4], ql[4];
                uint32_t qoff = ((w * 16 + (lane & 15)) * 72 + ks * 16 + (lane >> 4) * 8) * 2;
                LDSM_X4(qh, qHA + qoff);
                LDSM_X4(ql, qLA + qoff);
#pragma unroll
                for (int np = 0; np < 4; np++) {
                    uint32_t kh[4], kl[4];
                    uint32_t koff = ((np * 16 + (lane & 15)) * 72 + ks * 16 + (lane >> 4) * 8) * 2;
                    LDSM_X4(kh, kHA + koff);
                    LDSM_X4(kl, kLA + koff);
                    MMA_BF16_2(S[2*np],   qh, kh[0], kh[2]);
                    MMA_BF16_2(S[2*np],   qh, kl[0], kl[2]);
                    MMA_BF16_2(S[2*np],   ql, kh[0], kh[2]);
                    MMA_BF16_2(S[2*np+1], qh, kh[1], kh[3]);
                    MMA_BF16_2(S[2*np+1], qh, kl[1], kl[3]);
                    MMA_BF16_2(S[2*np+1], ql, kh[1], kh[3]);
                }
            }

            // ---- scale + causal mask + row max ----
            const bool full = (kvb + 63 <= wmin);
            float mx0 = -1e30f, mx1 = -1e30f;
#pragma unroll
            for (int nf = 0; nf < 8; nf++) {
                int col = kvb + nf * 8 + c2;
                float s0 = S[nf][0] * scale;
                float s1 = S[nf][1] * scale;
                float s2 = S[nf][2] * scale;
                float s3 = S[nf][3] * scale;
                if (!full) {
                    if (col     > row0) s0 = -1e30f;
                    if (col + 1 > row0) s1 = -1e30f;
                    if (col     > row1) s2 = -1e30f;
                    if (col + 1 > row1) s3 = -1e30f;
                }
                S[nf][0] = s0; S[nf][1] = s1; S[nf][2] = s2; S[nf][3] = s3;
                mx0 = fmaxf(mx0, fmaxf(s0, s1));
                mx1 = fmaxf(mx1, fmaxf(s2, s3));
            }
            mx0 = fmaxf(mx0, __shfl_xor_sync(0xffffffffu, mx0, 1));
            mx0 = fmaxf(mx0, __shfl_xor_sync(0xffffffffu, mx0, 2));
            mx1 = fmaxf(mx1, __shfl_xor_sync(0xffffffffu, mx1, 1));
            mx1 = fmaxf(mx1, __shfl_xor_sync(0xffffffffu, mx1, 2));

            float mn0 = fmaxf(m_run[0], mx0);
            float mn1 = fmaxf(m_run[1], mx1);
            float corr0 = __expf(m_run[0] - mn0);
            float corr1 = __expf(m_run[1] - mn1);
            l_run[0] *= corr0;
            l_run[1] *= corr1;
#pragma unroll
            for (int nf = 0; nf < 8; nf++) {
                O[nf][0] *= corr0; O[nf][1] *= corr0;
                O[nf][2] *= corr1; O[nf][3] *= corr1;
            }

            float sum0 = 0.0f, sum1 = 0.0f;
#pragma unroll
            for (int nf = 0; nf < 8; nf++) {
                float p0 = __expf(S[nf][0] - mn0);
                float p1 = __expf(S[nf][1] - mn0);
                float p2 = __expf(S[nf][2] - mn1);
                float p3 = __expf(S[nf][3] - mn1);
                S[nf][0] = p0; S[nf][1] = p1; S[nf][2] = p2; S[nf][3] = p3;
                sum0 += p0 + p1;
                sum1 += p2 + p3;
            }
            sum0 += __shfl_xor_sync(0xffffffffu, sum0, 1);
            sum0 += __shfl_xor_sync(0xffffffffu, sum0, 2);
            sum1 += __shfl_xor_sync(0xffffffffu, sum1, 1);
            sum1 += __shfl_xor_sync(0xffffffffu, sum1, 2);
            l_run[0] += sum0;
            l_run[1] += sum1;
            m_run[0] = mn0;
            m_run[1] = mn1;

            // ---- O += P V (3-pass split); S frags as A frags ----
#pragma unroll
            for (int j = 0; j < 4; j++) {
                uint32_t pH[4], pL[4];
                split2(S[2*j][0],   S[2*j][1],   pH[0], pL[0]);
                split2(S[2*j][2],   S[2*j][3],   pH[1], pL[1]);
                split2(S[2*j+1][0], S[2*j+1][1], pH[2], pL[2]);
                split2(S[2*j+1][2], S[2*j+1][3], pH[3], pL[3]);
#pragma unroll
                for (int np = 0; np < 4; np++) {
                    uint32_t vh[4], vl[4];
                    uint32_t voff = ((j * 16 + (lane & 15)) * 72 + np * 16 + (lane >> 4) * 8) * 2;
                    LDSM_X4T(vh, vHA + voff);
                    LDSM_X4T(vl, vLA + voff);
                    MMA_BF16(O[2*np],   pH, vh);
                    MMA_BF16(O[2*np],   pH, vl);
                    MMA_BF16(O[2*np],   pL, vh);
                    MMA_BF16(O[2*np+1], pH, vh + 2);
                    MMA_BF16(O[2*np+1], pH, vl + 2);
                    MMA_BF16(O[2*np+1], pL, vh + 2);
                }
            }
        }

        __syncthreads();
        if (jt + 2 < nt) issue_kv(jt + 2, s);
        CP_COMMIT();
    }

    // ---- epilogue: normalize, split hi/lo, write bf16 [B,T,C] ----
    float inv0 = 1.0f / l_run[0];
    float inv1 = 1.0f / l_run[1];
    size_t o0off = ((size_t)b * TT + row0) * CC + (size_t)hd * HD;
    size_t o1off = ((size_t)b * TT + row1) * CC + (size_t)hd * HD;
#pragma unroll
    for (int nf = 0; nf < 8; nf++) {
        int c = nf * 8 + c2;
        uint32_t ph, pl;
        split2(O[nf][0] * inv0, O[nf][1] * inv0, ph, pl);
        *(uint32_t*)&outHi[o0off + c] = ph;
        *(uint32_t*)&outLo[o0off + c] = pl;
        split2(O[nf][2] * inv1, O[nf][3] * inv1, ph, pl);
        *(uint32_t*)&outHi[o1off + c] = ph;
        *(uint32_t*)&outLo[o1off + c] = pl;
    }
}

// ---------------------------------------------------------------------------
extern "C" void kernel_launch(void* const* d_in, const int* in_sizes, int n_in,
                              void* d_out, int out_size)
{
    const float* x     = (const float*)d_in[0];
    const float* Wqkv  = (const float*)d_in[1];
    const float* bqkv  = (const float*)d_in[2];
    const float* Wproj = (const float*)d_in[3];
    const float* bproj = (const float*)d_in[4];
    float* out = (float*)d_out;

    __nv_bfloat16 *xhi, *xlo, *wqhi, *wqlo, *wphi, *wplo, *qkvhi, *qkvlo, *atthi, *attlo;
    cudaGetSymbolAddress((void**)&xhi,   g_xhi);
    cudaGetSymbolAddress((void**)&xlo,   g_xlo);
    cudaGetSymbolAddress((void**)&wqhi,  g_wqhi);
    cudaGetSymbolAddress((void**)&wqlo,  g_wqlo);
    cudaGetSymbolAddress((void**)&wphi,  g_wphi);
    cudaGetSymbolAddress((void**)&wplo,  g_wplo);
    cudaGetSymbolAddress((void**)&qkvhi, g_qkvhi);
    cudaGetSymbolAddress((void**)&qkvlo, g_qkvlo);
    cudaGetSymbolAddress((void**)&atthi, g_atthi);
    cudaGetSymbolAddress((void**)&attlo, g_attlo);

    cudaFuncSetAttribute(gemm_bf16,
                         cudaFuncAttributeMaxDynamicSharedMemorySize, GEMM_SMEM);
    cudaFuncSetAttribute(attn_hmma,
                         cudaFuncAttributeMaxDynamicSharedMemorySize, ATTN_SMEM);

    // 0) pre-split inputs to hi/lo bf16
    int n4x = BT * CC / 4;
    split_f32<<<n4x / 256, 256>>>(x, xhi, xlo, n4x);
    int n4q = CC * 3 * CC / 4;
    split_f32<<<n4q / 256, 256>>>(Wqkv, wqhi, wqlo, n4q);
    int n4p = CC * CC / 4;
    split_f32<<<n4p / 256, 256>>>(Wproj, wphi, wplo, n4p);

    dim3 blk(256);
    // 1) qkv = x @ W_qkv + b_qkv  -> hi/lo bf16
    gemm_bf16<<<dim3(3 * CC / 128, BT / 128), blk, GEMM_SMEM>>>(
        xhi, xlo, wqhi, wqlo, bqkv, nullptr, qkvhi, qkvlo, BT, 3 * CC, CC, 1);
    // 2) attention -> att hi/lo bf16
    attn_hmma<<<dim3(TT / 128, HH, BB), blk, ATTN_SMEM>>>(qkvhi, qkvlo, atthi, attlo);
    // 3) out = att @ W_proj + b_proj  -> fp32
    gemm_bf16<<<dim3(CC / 128, BT / 128), blk, GEMM_SMEM>>>(
        atthi, attlo, wphi, wplo, bproj, out, nullptr, nullptr, BT, CC, CC, 0);
}

// round 12
// speedup vs baseline: 1.1291x; 1.0691x over previous
#include <cuda_runtime.h>
#include <cuda_fp16.h>
#include <cstdint>
#include <math.h>

// Problem constants
#define BB 4
#define TT 2048
#define CC 1024
#define HH 16
#define HD 64
#define BT (BB*TT)          // 8192

// Pre-split fp16 scratch (device globals: allocation-free per harness rules)
__device__ __align__(256) __half g_xhi[(size_t)BT * CC];
__device__ __align__(256) __half g_xlo[(size_t)BT * CC];
__device__ __align__(256) __half g_wqhi[(size_t)CC * 3 * CC];
__device__ __align__(256) __half g_wqlo[(size_t)CC * 3 * CC];
__device__ __align__(256) __half g_wphi[(size_t)CC * CC];
__device__ __align__(256) __half g_wplo[(size_t)CC * CC];
__device__ __align__(256) __half g_qkvhi[(size_t)BT * 3 * CC];
__device__ __align__(256) __half g_qkvlo[(size_t)BT * 3 * CC];
__device__ __align__(256) __half g_atthi[(size_t)BT * CC];

// ===========================================================================
// Helpers
// ===========================================================================
__device__ __forceinline__ uint32_t smem_u32(const void* p) {
    uint32_t a;
    asm("{ .reg .u64 t; cvta.to.shared.u64 t, %1; cvt.u32.u64 %0, t; }"
        : "=r"(a) : "l"(p));
    return a;
}

#define LDSM_X4(r, addr) \
    asm volatile("ldmatrix.sync.aligned.m8n8.x4.shared.b16 {%0,%1,%2,%3}, [%4];" \
        : "=r"((r)[0]), "=r"((r)[1]), "=r"((r)[2]), "=r"((r)[3]) : "r"(addr))

#define LDSM_X4T(r, addr) \
    asm volatile("ldmatrix.sync.aligned.m8n8.x4.trans.shared.b16 {%0,%1,%2,%3}, [%4];" \
        : "=r"((r)[0]), "=r"((r)[1]), "=r"((r)[2]), "=r"((r)[3]) : "r"(addr))

#define MMA_F16(c, a, b) \
    asm volatile("mma.sync.aligned.m16n8k16.row.col.f32.f16.f16.f32 " \
        "{%0,%1,%2,%3}, {%4,%5,%6,%7}, {%8,%9}, {%0,%1,%2,%3};" \
        : "+f"((c)[0]), "+f"((c)[1]), "+f"((c)[2]), "+f"((c)[3]) \
        : "r"((a)[0]), "r"((a)[1]), "r"((a)[2]), "r"((a)[3]), \
          "r"((b)[0]), "r"((b)[1]))

#define MMA_F16_2(c, a, b0, b1) \
    asm volatile("mma.sync.aligned.m16n8k16.row.col.f32.f16.f16.f32 " \
        "{%0,%1,%2,%3}, {%4,%5,%6,%7}, {%8,%9}, {%0,%1,%2,%3};" \
        : "+f"((c)[0]), "+f"((c)[1]), "+f"((c)[2]), "+f"((c)[3]) \
        : "r"((a)[0]), "r"((a)[1]), "r"((a)[2]), "r"((a)[3]), \
          "r"(b0), "r"(b1))

#define CP_ASYNC_CG(dst, src) \
    asm volatile("cp.async.cg.shared.global [%0], [%1], 16;" :: "r"(dst), "l"(src))
#define CP_COMMIT() asm volatile("cp.async.commit_group;" ::: "memory")
#define CP_WAIT1()  asm volatile("cp.async.wait_group 1;" ::: "memory")

__device__ __forceinline__ uint32_t pack2h(float a, float b) {
    __half2 t = __floats2half2_rn(a, b);
    return *(uint32_t*)&t;
}

// split x into hi (fp16-representable float) and lo = x - hi (fp16)
__device__ __forceinline__ void split2h(float a, float b, uint32_t& hi, uint32_t& lo) {
    __half ha = __float2half_rn(a);
    __half hb = __float2half_rn(b);
    __half2 hp = __halves2half2(ha, hb);
    hi = *(uint32_t*)&hp;
    lo = pack2h(a - __half2float(ha), b - __half2float(hb));
}

// ===========================================================================
// split_f32: fp32 array -> hi/lo fp16 arrays (4 elems/thread)
// ===========================================================================
__global__ __launch_bounds__(256) void split_f32(
    const float* __restrict__ in, __half* __restrict__ hi,
    __half* __restrict__ lo, int n4)
{
    int i = blockIdx.x * 256 + threadIdx.x;
    if (i >= n4) return;
    float4 v = ((const float4*)in)[i];
    uint32_t h0, l0, h1, l1;
    split2h(v.x, v.y, h0, l0);
    split2h(v.z, v.w, h1, l1);
    ((uint2*)hi)[i] = make_uint2(h0, h1);
    ((uint2*)lo)[i] = make_uint2(l0, l1);
}

// ===========================================================================
// HMMA split-fp16 GEMM, pre-split fp16 inputs, 3-stage cp.async pipeline,
// ONE __syncthreads per 32-K chunk.  2 CTAs/SM.  (R8 structure — best measured.)
// passMode: 0 = 3-pass everywhere; 1 = 2-pass everywhere (drop Alo*Bhi);
//           2 = mixed: 2-pass for colBase >= 2048 (the V columns of qkv).
// C = A@B + bias; output fp32 OR hi/lo fp16 pair (outSplit).
// 128x128 tile, BK=32, 8 warps (2x4), warp tile 64x32.
// ===========================================================================
#define GA_STRIDE 40          // fp16 elems/row (32+8) -> conflict-free ldsm
#define GB_STRIDE 136         // fp16 elems/row (128+8)
#define GA_BYTES (128 * GA_STRIDE * 2)   // 10240
#define GB_BYTES (32 * GB_STRIDE * 2)    // 8704
#define GBUF (2 * GA_BYTES + 2 * GB_BYTES)   // 37888
#define GEMM_SMEM (3 * GBUF)                  // 113664

__global__ __launch_bounds__(256, 2) void gemm_f16(
    const __half* __restrict__ Ahi, const __half* __restrict__ Alo,
    const __half* __restrict__ Bhi, const __half* __restrict__ Blo,
    const float* __restrict__ bias,
    float* __restrict__ Cf,
    __half* __restrict__ Chi, __half* __restrict__ Clo,
    int M, int N, int K, int outSplit, int passMode)
{
    extern __shared__ char sm[];
    const uint32_t smb = smem_u32(sm);
    const int tid  = threadIdx.x;
    const int lane = tid & 31;
    const int wid  = tid >> 5;
    const int wm   = wid >> 2;
    const int wn   = wid & 3;
    const int rowBase = blockIdx.y * 128;
    const int colBase = blockIdx.x * 128;
    const bool tp = (passMode == 1) || (passMode == 2 && colBase >= 2048);

    auto issue = [&](int k0, int bi) {
        uint32_t aH = smb + bi * GBUF;
        uint32_t aL = aH + GA_BYTES;
        uint32_t bH = aH + 2 * GA_BYTES;
        uint32_t bL = bH + GB_BYTES;
#pragma unroll
        for (int j = 0; j < 2; j++) {
            int idx = tid + j * 256;
            int m  = idx >> 2;
            int ch = idx & 3;
            size_t ao = (size_t)(rowBase + m) * K + k0 + ch * 8;
            uint32_t ad = m * 80 + ch * 16;
            CP_ASYNC_CG(aH + ad, Ahi + ao);
            if (!tp) CP_ASYNC_CG(aL + ad, Alo + ao);  // Alo unused in 2-pass
            int kk = idx >> 4;
            int c2 = idx & 15;
            size_t bo = (size_t)(k0 + kk) * N + colBase + c2 * 8;
            uint32_t bd = kk * 272 + c2 * 16;
            CP_ASYNC_CG(bH + bd, Bhi + bo);
            CP_ASYNC_CG(bL + bd, Blo + bo);
        }
    };

    float acc[4][4][4] = {};
    const int NS = K >> 5;

    // prologue: stages 0 and 1 in flight
    issue(0, 0);  CP_COMMIT();
    issue(32, 1); CP_COMMIT();

    int buf = 0;        // c % 3
    int nbuf = 2;       // (c+2) % 3
    for (int c = 0; c < NS; c++) {
        CP_WAIT1();
        __syncthreads();

        if (c + 2 < NS) issue((c + 2) << 5, nbuf);
        CP_COMMIT();

        uint32_t aH = smb + buf * GBUF;
        uint32_t aL = aH + GA_BYTES;
        uint32_t bH = aH + 2 * GA_BYTES;
        uint32_t bL = bH + GB_BYTES;

#pragma unroll
        for (int ks = 0; ks < 2; ks++) {
            uint32_t fAH[4][4], fAL[4][4];
#pragma unroll
            for (int mf = 0; mf < 4; mf++) {
                uint32_t off = ((wm * 64 + mf * 16 + (lane & 15)) * GA_STRIDE
                                + ks * 16 + (lane >> 4) * 8) * 2;
                LDSM_X4(fAH[mf], aH + off);
                if (!tp) LDSM_X4(fAL[mf], aL + off);
            }
#pragma unroll
            for (int nq = 0; nq < 2; nq++) {
                uint32_t fBH[4], fBL[4];
                uint32_t off = ((ks * 16 + (lane & 15)) * GB_STRIDE
                                + wn * 32 + nq * 16 + (lane >> 4) * 8) * 2;
                LDSM_X4T(fBH, bH + off);
                LDSM_X4T(fBL, bL + off);
#pragma unroll
                for (int mf = 0; mf < 4; mf++) {
                    MMA_F16(acc[mf][2*nq],   fAH[mf], fBH);
                    MMA_F16(acc[mf][2*nq],   fAH[mf], fBL);
                    MMA_F16(acc[mf][2*nq+1], fAH[mf], fBH + 2);
                    MMA_F16(acc[mf][2*nq+1], fAH[mf], fBL + 2);
                    if (!tp) {
                        MMA_F16(acc[mf][2*nq],   fAL[mf], fBH);
                        MMA_F16(acc[mf][2*nq+1], fAL[mf], fBH + 2);
                    }
                }
            }
        }
        buf  = (buf  == 2) ? 0 : buf + 1;
        nbuf = (nbuf == 2) ? 0 : nbuf + 1;
    }

    // ---- Epilogue ----
#pragma unroll
    for (int nf = 0; nf < 4; nf++) {
        int c = colBase + wn * 32 + nf * 8 + 2 * (lane & 3);
        float2 bv = *(const float2*)&bias[c];
#pragma unroll
        for (int mf = 0; mf < 4; mf++) {
            int r0 = rowBase + wm * 64 + mf * 16 + (lane >> 2);
            float o0x = acc[mf][nf][0] + bv.x, o0y = acc[mf][nf][1] + bv.y;
            float o1x = acc[mf][nf][2] + bv.x, o1y = acc[mf][nf][3] + bv.y;
            if (!outSplit) {
                *(float2*)&Cf[(size_t)r0 * N + c] = make_float2(o0x, o0y);
                *(float2*)&Cf[(size_t)(r0 + 8) * N + c] = make_float2(o1x, o1y);
            } else {
                uint32_t ph, pl;
                split2h(o0x, o0y, ph, pl);
                *(uint32_t*)&Chi[(size_t)r0 * N + c] = ph;
                *(uint32_t*)&Clo[(size_t)r0 * N + c] = pl;
                split2h(o1x, o1y, ph, pl);
                *(uint32_t*)&Chi[(size_t)(r0 + 8) * N + c] = ph;
                *(uint32_t*)&Clo[(size_t)(r0 + 8) * N + c] = pl;
            }
        }
    }
}

// ===========================================================================
// HMMA flash attention (causal), pre-split fp16 qkv, cp.async KV pipeline.
// QK^T: 3-pass split (softmax exponent is error-sensitive).
// P*V : 2-pass — P as single fp16 (no split), V split hi/lo.
// Output att written as fp16 hi only (consumed by 2-pass GEMM2).
// Heavy-first scheduling.
// ===========================================================================
#define AQ_BYTES  (128 * 72 * 2)   // 18432
#define AKV_BYTES (64 * 72 * 2)    // 9216
#define ASTAGE    (4 * AKV_BYTES)  // 36864
#define ATTN_SMEM (2 * AQ_BYTES + 2 * ASTAGE)   // 110592

__global__ __launch_bounds__(256, 2) void attn_hmma(
    const __half* __restrict__ qhiG, const __half* __restrict__ qloG,
    __half* __restrict__ outHi)
{
    extern __shared__ char sm[];
    const uint32_t smb = smem_u32(sm);
    const uint32_t qHA = smb;
    const uint32_t qLA = smb + AQ_BYTES;
    const int tid  = threadIdx.x;
    const int lane = tid & 31;
    const int w    = tid >> 5;
    const int qt = gridDim.x - 1 - blockIdx.x;   // heavy-first
    const int hd = blockIdx.y;     // head
    const int b  = blockIdx.z;
    const int qb = qt * 128;

    // ---- Q tile via cp.async (group 0) ----
#pragma unroll
    for (int j = 0; j < 4; j++) {
        int idx = tid + j * 256;
        int row = idx >> 3;
        int ch  = idx & 7;
        size_t so = ((size_t)b * TT + qb + row) * 3072 + (size_t)hd * 64 + ch * 8;
        uint32_t doff = row * 144 + ch * 16;
        CP_ASYNC_CG(qHA + doff, qhiG + so);
        CP_ASYNC_CG(qLA + doff, qloG + so);
    }

    auto issue_kv = [&](int jt2, int s) {
        uint32_t kH = smb + 2 * AQ_BYTES + s * ASTAGE;
        uint32_t kL = kH + AKV_BYTES;
        uint32_t vH = kH + 2 * AKV_BYTES;
        uint32_t vL = kH + 3 * AKV_BYTES;
        size_t base = ((size_t)b * TT + jt2 * 64) * 3072 + CC + (size_t)hd * 64;
#pragma unroll
        for (int j = 0; j < 2; j++) {
            int idx = tid + j * 256;
            int row = idx >> 3;
            int ch  = idx & 7;
            size_t so = base + (size_t)row * 3072 + ch * 8;
            uint32_t doff = row * 144 + ch * 16;
            CP_ASYNC_CG(kH + doff, qhiG + so);
            CP_ASYNC_CG(kL + doff, qloG + so);
            CP_ASYNC_CG(vH + doff, qhiG + so + CC);
            CP_ASYNC_CG(vL + doff, qloG + so + CC);
        }
    };

    issue_kv(0, 0); CP_COMMIT();    // group 0 (Q + KV0)
    issue_kv(1, 1); CP_COMMIT();    // group 1

    float S[8][4];
    float O[8][4] = {};
    float m_run[2] = { -1e30f, -1e30f };
    float l_run[2] = { 0.0f, 0.0f };
    const float scale = 0.125f;

    const int wmin = qb + w * 16;
    const int r_in = lane >> 2;
    const int c2   = (lane & 3) * 2;
    const int row0 = wmin + r_in;
    const int row1 = row0 + 8;
    const int nt = 2 * qt + 2;

    for (int jt = 0; jt < nt; jt++) {
        CP_WAIT1();
        __syncthreads();
        const int s = jt & 1;
        const int kvb = jt * 64;

        if (kvb <= wmin + 15) {       // warp-uniform: tile not fully masked
            uint32_t kHA = smb + 2 * AQ_BYTES + s * ASTAGE;
            uint32_t kLA = kHA + AKV_BYTES;
            uint32_t vHA = kHA + 2 * AKV_BYTES;
            uint32_t vLA = kHA + 3 * AKV_BYTES;

            // ---- S = Q K^T (3-pass split) ----
#pragma unroll
            for (int nf = 0; nf < 8; nf++)
#pragma unroll
                for (int e = 0; e < 4; e++) S[nf][e] = 0.0f;

#pragma unroll
            for (int ks = 0; ks < 4; ks++) {
                uint32_t qh[4], ql[4];
                uint32_t qoff = ((w * 16 + (lane & 15)) * 72 + ks * 16 + (lane >> 4) * 8) * 2;
                LDSM_X4(qh, qHA + qoff);
                LDSM_X4(ql, qLA + qoff);
#pragma unroll
                for (int np = 0; np < 4; np++) {
                    uint32_t kh[4], kl[4];
                    uint32_t koff = ((np * 16 + (lane & 15)) * 72 + ks * 16 + (lane >> 4) * 8) * 2;
                    LDSM_X4(kh, kHA + koff);
                    LDSM_X4(kl, kLA + koff);
                    MMA_F16_2(S[2*np],   qh, kh[0], kh[2]);
                    MMA_F16_2(S[2*np],   qh, kl[0], kl[2]);
                    MMA_F16_2(S[2*np],   ql, kh[0], kh[2]);
                    MMA_F16_2(S[2*np+1], qh, kh[1], kh[3]);
                    MMA_F16_2(S[2*np+1], qh, kl[1], kl[3]);
                    MMA_F16_2(S[2*np+1], ql, kh[1], kh[3]);
                }
            }

            // ---- scale + causal mask + row max ----
            const bool full = (kvb + 63 <= wmin);
            float mx0 = -1e30f, mx1 = -1e30f;
#pragma unroll
            for (int nf = 0; nf < 8; nf++) {
                int col = kvb + nf * 8 + c2;
                float s0 = S[nf][0] * scale;
                float s1 = S[nf][1] * scale;
                float s2 = S[nf][2] * scale;
                float s3 = S[nf][3] * scale;
                if (!full) {
                    if (col     > row0) s0 = -1e30f;
                    if (col + 1 > row0) s1 = -1e30f;
                    if (col     > row1) s2 = -1e30f;
                    if (col + 1 > row1) s3 = -1e30f;
                }
                S[nf][0] = s0; S[nf][1] = s1; S[nf][2] = s2; S[nf][3] = s3;
                mx0 = fmaxf(mx0, fmaxf(s0, s1));
                mx1 = fmaxf(mx1, fmaxf(s2, s3));
            }
            mx0 = fmaxf(mx0, __shfl_xor_sync(0xffffffffu, mx0, 1));
            mx0 = fmaxf(mx0, __shfl_xor_sync(0xffffffffu, mx0, 2));
            mx1 = fmaxf(mx1, __shfl_xor_sync(0xffffffffu, mx1, 1));
            mx1 = fmaxf(mx1, __shfl_xor_sync(0xffffffffu, mx1, 2));

            float mn0 = fmaxf(m_run[0], mx0);
            float mn1 = fmaxf(m_run[1], mx1);
            float corr0 = __expf(m_run[0] - mn0);
            float corr1 = __expf(m_run[1] - mn1);
            l_run[0] *= corr0;
            l_run[1] *= corr1;
#pragma unroll
            for (int nf = 0; nf < 8; nf++) {
                O[nf][0] *= corr0; O[nf][1] *= corr0;
                O[nf][2] *= corr1; O[nf][3] *= corr1;
            }

            float sum0 = 0.0f, sum1 = 0.0f;
#pragma unroll
            for (int nf = 0; nf < 8; nf++) {
                float p0 = __expf(S[nf][0] - mn0);
                float p1 = __expf(S[nf][1] - mn0);
                float p2 = __expf(S[nf][2] - mn1);
                float p3 = __expf(S[nf][3] - mn1);
                S[nf][0] = p0; S[nf][1] = p1; S[nf][2] = p2; S[nf][3] = p3;
                sum0 += p0 + p1;
                sum1 += p2 + p3;
            }
            sum0 += __shfl_xor_sync(0xffffffffu, sum0, 1);
            sum0 += __shfl_xor_sync(0xffffffffu, sum0, 2);
            sum1 += __shfl_xor_sync(0xffffffffu, sum1, 1);
            sum1 += __shfl_xor_sync(0xffffffffu, sum1, 2);
            l_run[0] += sum0;
            l_run[1] += sum1;
            m_run[0] = mn0;
            m_run[1] = mn1;

            // ---- O += P V (2-pass: fp16 P unsplit, V hi/lo) ----
#pragma unroll
            for (int j = 0; j < 4; j++) {
                uint32_t pH[4];
                pH[0] = pack2h(S[2*j][0],   S[2*j][1]);
                pH[1] = pack2h(S[2*j][2],   S[2*j][3]);
                pH[2] = pack2h(S[2*j+1][0], S[2*j+1][1]);
                pH[3] = pack2h(S[2*j+1][2], S[2*j+1][3]);
#pragma unroll
                for (int np = 0; np < 4; np++) {
                    uint32_t vh[4], vl[4];
                    uint32_t voff = ((j * 16 + (lane & 15)) * 72 + np * 16 + (lane >> 4) * 8) * 2;
                    LDSM_X4T(vh, vHA + voff);
                    LDSM_X4T(vl, vLA + voff);
                    MMA_F16(O[2*np],   pH, vh);
                    MMA_F16(O[2*np+1], pH, vh + 2);
                    MMA_F16(O[2*np],   pH, vl);
                    MMA_F16(O[2*np+1], pH, vl + 2);
                }
            }
        }

        __syncthreads();
        if (jt + 2 < nt) issue_kv(jt + 2, s);
        CP_COMMIT();
    }

    // ---- epilogue: normalize, write fp16 hi [B,T,C] ----
    float inv0 = 1.0f / l_run[0];
    float inv1 = 1.0f / l_run[1];
    size_t o0off = ((size_t)b * TT + row0) * CC + (size_t)hd * HD;
    size_t o1off = ((size_t)b * TT + row1) * CC + (size_t)hd * HD;
#pragma unroll
    for (int nf = 0; nf < 8; nf++) {
        int c = nf * 8 + c2;
        *(uint32_t*)&outHi[o0off + c] = pack2h(O[nf][0] * inv0, O[nf][1] * inv0);
        *(uint32_t*)&outHi[o1off + c] = pack2h(O[nf][2] * inv1, O[nf][3] * inv1);
    }
}

// ---------------------------------------------------------------------------
extern "C" void kernel_launch(void* const* d_in, const int* in_sizes, int n_in,
                              void* d_out, int out_size)
{
    const float* x     = (const float*)d_in[0];
    const float* Wqkv  = (const float*)d_in[1];
    const float* bqkv  = (const float*)d_in[2];
    const float* Wproj = (const float*)d_in[3];
    const float* bproj = (const float*)d_in[4];
    float* out = (float*)d_out;

    __half *xhi, *xlo, *wqhi, *wqlo, *wphi, *wplo, *qkvhi, *qkvlo, *atthi;
    cudaGetSymbolAddress((void**)&xhi,   g_xhi);
    cudaGetSymbolAddress((void**)&xlo,   g_xlo);
    cudaGetSymbolAddress((void**)&wqhi,  g_wqhi);
    cudaGetSymbolAddress((void**)&wqlo,  g_wqlo);
    cudaGetSymbolAddress((void**)&wphi,  g_wphi);
    cudaGetSymbolAddress((void**)&wplo,  g_wplo);
    cudaGetSymbolAddress((void**)&qkvhi, g_qkvhi);
    cudaGetSymbolAddress((void**)&qkvlo, g_qkvlo);
    cudaGetSymbolAddress((void**)&atthi, g_atthi);

    cudaFuncSetAttribute(gemm_f16,
                         cudaFuncAttributeMaxDynamicSharedMemorySize, GEMM_SMEM);
    cudaFuncSetAttribute(attn_hmma,
                         cudaFuncAttributeMaxDynamicSharedMemorySize, ATTN_SMEM);

    // 0) pre-split inputs to hi/lo fp16
    int n4x = BT * CC / 4;
    split_f32<<<n4x / 256, 256>>>(x, xhi, xlo, n4x);
    int n4q = CC * 3 * CC / 4;
    split_f32<<<n4q / 256, 256>>>(Wqkv, wqhi, wqlo, n4q);
    int n4p = CC * CC / 4;
    split_f32<<<n4p / 256, 256>>>(Wproj, wphi, wplo, n4p);

    dim3 blk(256);
    // 1) qkv = x @ W_qkv + b_qkv  -> hi/lo fp16.  Mixed pass: V cols 2-pass.
    gemm_f16<<<dim3(3 * CC / 128, BT / 128), blk, GEMM_SMEM>>>(
        xhi, xlo, wqhi, wqlo, bqkv, nullptr, qkvhi, qkvlo, BT, 3 * CC, CC, 1, 2);
    // 2) attention -> att fp16 hi
    attn_hmma<<<dim3(TT / 128, HH, BB), blk, ATTN_SMEM>>>(qkvhi, qkvlo, atthi);
    // 3) out = att @ W_proj + b_proj  -> fp32.  2-pass (att hi only).
    gemm_f16<<<dim3(CC / 128, BT / 128), blk, GEMM_SMEM>>>(
        atthi, nullptr, wphi, wplo, bproj, out, nullptr, nullptr, BT, CC, CC, 0, 1);
}

// round 13
// speedup vs baseline: 1.2585x; 1.1146x over previous
#include <cuda_runtime.h>
#include <cuda_fp16.h>
#include <cstdint>
#include <math.h>

// Problem constants
#define BB 4
#define TT 2048
#define CC 1024
#define HH 16
#define HD 64
#define BT (BB*TT)          // 8192

// Pre-split fp16 scratch (device globals: allocation-free per harness rules)
__device__ __align__(256) __half g_xhi[(size_t)BT * CC];
__device__ __align__(256) __half g_xlo[(size_t)BT * CC];
__device__ __align__(256) __half g_wqhi[(size_t)CC * 3 * CC];
__device__ __align__(256) __half g_wqlo[(size_t)CC * 3 * CC];
__device__ __align__(256) __half g_wphi[(size_t)CC * CC];
__device__ __align__(256) __half g_qkvhi[(size_t)BT * 3 * CC];
__device__ __align__(256) __half g_qkvlo[(size_t)BT * 3 * CC];
__device__ __align__(256) __half g_atthi[(size_t)BT * CC];

// ===========================================================================
// Helpers
// ===========================================================================
__device__ __forceinline__ uint32_t smem_u32(const void* p) {
    uint32_t a;
    asm("{ .reg .u64 t; cvta.to.shared.u64 t, %1; cvt.u32.u64 %0, t; }"
        : "=r"(a) : "l"(p));
    return a;
}

#define LDSM_X4(r, addr) \
    asm volatile("ldmatrix.sync.aligned.m8n8.x4.shared.b16 {%0,%1,%2,%3}, [%4];" \
        : "=r"((r)[0]), "=r"((r)[1]), "=r"((r)[2]), "=r"((r)[3]) : "r"(addr))

#define LDSM_X4T(r, addr) \
    asm volatile("ldmatrix.sync.aligned.m8n8.x4.trans.shared.b16 {%0,%1,%2,%3}, [%4];" \
        : "=r"((r)[0]), "=r"((r)[1]), "=r"((r)[2]), "=r"((r)[3]) : "r"(addr))

#define MMA_F16(c, a, b) \
    asm volatile("mma.sync.aligned.m16n8k16.row.col.f32.f16.f16.f32 " \
        "{%0,%1,%2,%3}, {%4,%5,%6,%7}, {%8,%9}, {%0,%1,%2,%3};" \
        : "+f"((c)[0]), "+f"((c)[1]), "+f"((c)[2]), "+f"((c)[3]) \
        : "r"((a)[0]), "r"((a)[1]), "r"((a)[2]), "r"((a)[3]), \
          "r"((b)[0]), "r"((b)[1]))

#define MMA_F16_2(c, a, b0, b1) \
    asm volatile("mma.sync.aligned.m16n8k16.row.col.f32.f16.f16.f32 " \
        "{%0,%1,%2,%3}, {%4,%5,%6,%7}, {%8,%9}, {%0,%1,%2,%3};" \
        : "+f"((c)[0]), "+f"((c)[1]), "+f"((c)[2]), "+f"((c)[3]) \
        : "r"((a)[0]), "r"((a)[1]), "r"((a)[2]), "r"((a)[3]), \
          "r"(b0), "r"(b1))

#define CP_ASYNC_CG(dst, src) \
    asm volatile("cp.async.cg.shared.global [%0], [%1], 16;" :: "r"(dst), "l"(src))
#define CP_COMMIT() asm volatile("cp.async.commit_group;" ::: "memory")
#define CP_WAIT1()  asm volatile("cp.async.wait_group 1;" ::: "memory")

__device__ __forceinline__ uint32_t pack2h(float a, float b) {
    __half2 t = __floats2half2_rn(a, b);
    return *(uint32_t*)&t;
}

// split x into hi (fp16-representable float) and lo = x - hi (fp16)
__device__ __forceinline__ void split2h(float a, float b, uint32_t& hi, uint32_t& lo) {
    __half ha = __float2half_rn(a);
    __half hb = __float2half_rn(b);
    __half2 hp = __halves2half2(ha, hb);
    hi = *(uint32_t*)&hp;
    lo = pack2h(a - __half2float(ha), b - __half2float(hb));
}

// ===========================================================================
// split_f32: fp32 array -> hi/lo fp16 arrays (4 elems/thread)
// ===========================================================================
__global__ __launch_bounds__(256) void split_f32(
    const float* __restrict__ in, __half* __restrict__ hi,
    __half* __restrict__ lo, int n4)
{
    int i = blockIdx.x * 256 + threadIdx.x;
    if (i >= n4) return;
    float4 v = ((const float4*)in)[i];
    uint32_t h0, l0, h1, l1;
    split2h(v.x, v.y, h0, l0);
    split2h(v.z, v.w, h1, l1);
    ((uint2*)hi)[i] = make_uint2(h0, h1);
    ((uint2*)lo)[i] = make_uint2(l0, l1);
}

// hi-only variant (for Wproj: lo never consumed)
__global__ __launch_bounds__(256) void trunc_f32(
    const float* __restrict__ in, __half* __restrict__ hi, int n4)
{
    int i = blockIdx.x * 256 + threadIdx.x;
    if (i >= n4) return;
    float4 v = ((const float4*)in)[i];
    ((uint2*)hi)[i] = make_uint2(pack2h(v.x, v.y), pack2h(v.z, v.w));
}

// ===========================================================================
// HMMA split-fp16 GEMM, pre-split fp16 inputs, 3-stage cp.async pipeline,
// ONE __syncthreads per 32-K chunk.  2 CTAs/SM.
// passMode: 0 = 3-pass; 1 = 2-pass (drop Alo·Bhi); 2 = mixed (2-pass for
//           colBase >= 2048, the V columns); 3 = 1-pass (hi·hi only).
// C = A@B + bias; output fp32 OR hi/lo fp16 pair (outSplit).
// 128x128 tile, BK=32, 8 warps (2x4), warp tile 64x32.
// ===========================================================================
#define GA_STRIDE 40          // fp16 elems/row (32+8) -> conflict-free ldsm
#define GB_STRIDE 136         // fp16 elems/row (128+8)
#define GA_BYTES (128 * GA_STRIDE * 2)   // 10240
#define GB_BYTES (32 * GB_STRIDE * 2)    // 8704
#define GBUF (2 * GA_BYTES + 2 * GB_BYTES)   // 37888
#define GEMM_SMEM (3 * GBUF)                  // 113664

__global__ __launch_bounds__(256, 2) void gemm_f16(
    const __half* __restrict__ Ahi, const __half* __restrict__ Alo,
    const __half* __restrict__ Bhi, const __half* __restrict__ Blo,
    const float* __restrict__ bias,
    float* __restrict__ Cf,
    __half* __restrict__ Chi, __half* __restrict__ Clo,
    int M, int N, int K, int outSplit, int passMode)
{
    extern __shared__ char sm[];
    const uint32_t smb = smem_u32(sm);
    const int tid  = threadIdx.x;
    const int lane = tid & 31;
    const int wid  = tid >> 5;
    const int wm   = wid >> 2;
    const int wn   = wid & 3;
    const int rowBase = blockIdx.y * 128;
    const int colBase = blockIdx.x * 128;
    const bool useAlo = (passMode == 0) || (passMode == 2 && colBase < 2048);
    const bool useBlo = (passMode != 3);

    auto issue = [&](int k0, int bi) {
        uint32_t aH = smb + bi * GBUF;
        uint32_t aL = aH + GA_BYTES;
        uint32_t bH = aH + 2 * GA_BYTES;
        uint32_t bL = bH + GB_BYTES;
#pragma unroll
        for (int j = 0; j < 2; j++) {
            int idx = tid + j * 256;
            int m  = idx >> 2;
            int ch = idx & 3;
            size_t ao = (size_t)(rowBase + m) * K + k0 + ch * 8;
            uint32_t ad = m * 80 + ch * 16;
            CP_ASYNC_CG(aH + ad, Ahi + ao);
            if (useAlo) CP_ASYNC_CG(aL + ad, Alo + ao);
            int kk = idx >> 4;
            int c2 = idx & 15;
            size_t bo = (size_t)(k0 + kk) * N + colBase + c2 * 8;
            uint32_t bd = kk * 272 + c2 * 16;
            CP_ASYNC_CG(bH + bd, Bhi + bo);
            if (useBlo) CP_ASYNC_CG(bL + bd, Blo + bo);
        }
    };

    float acc[4][4][4] = {};
    const int NS = K >> 5;

    // prologue: stages 0 and 1 in flight
    issue(0, 0);  CP_COMMIT();
    issue(32, 1); CP_COMMIT();

    int buf = 0;        // c % 3
    int nbuf = 2;       // (c+2) % 3
    for (int c = 0; c < NS; c++) {
        CP_WAIT1();
        __syncthreads();

        if (c + 2 < NS) issue((c + 2) << 5, nbuf);
        CP_COMMIT();

        uint32_t aH = smb + buf * GBUF;
        uint32_t aL = aH + GA_BYTES;
        uint32_t bH = aH + 2 * GA_BYTES;
        uint32_t bL = bH + GB_BYTES;

#pragma unroll
        for (int ks = 0; ks < 2; ks++) {
            uint32_t fAH[4][4], fAL[4][4];
#pragma unroll
            for (int mf = 0; mf < 4; mf++) {
                uint32_t off = ((wm * 64 + mf * 16 + (lane & 15)) * GA_STRIDE
                                + ks * 16 + (lane >> 4) * 8) * 2;
                LDSM_X4(fAH[mf], aH + off);
                if (useAlo) LDSM_X4(fAL[mf], aL + off);
            }
#pragma unroll
            for (int nq = 0; nq < 2; nq++) {
                uint32_t fBH[4], fBL[4];
                uint32_t off = ((ks * 16 + (lane & 15)) * GB_STRIDE
                                + wn * 32 + nq * 16 + (lane >> 4) * 8) * 2;
                LDSM_X4T(fBH, bH + off);
                if (useBlo) LDSM_X4T(fBL, bL + off);
#pragma unroll
                for (int mf = 0; mf < 4; mf++) {
                    MMA_F16(acc[mf][2*nq],   fAH[mf], fBH);
                    MMA_F16(acc[mf][2*nq+1], fAH[mf], fBH + 2);
                    if (useBlo) {
                        MMA_F16(acc[mf][2*nq],   fAH[mf], fBL);
                        MMA_F16(acc[mf][2*nq+1], fAH[mf], fBL + 2);
                    }
                    if (useAlo) {
                        MMA_F16(acc[mf][2*nq],   fAL[mf], fBH);
                        MMA_F16(acc[mf][2*nq+1], fAL[mf], fBH + 2);
                    }
                }
            }
        }
        buf  = (buf  == 2) ? 0 : buf + 1;
        nbuf = (nbuf == 2) ? 0 : nbuf + 1;
    }

    // ---- Epilogue ----
#pragma unroll
    for (int nf = 0; nf < 4; nf++) {
        int c = colBase + wn * 32 + nf * 8 + 2 * (lane & 3);
        float2 bv = *(const float2*)&bias[c];
#pragma unroll
        for (int mf = 0; mf < 4; mf++) {
            int r0 = rowBase + wm * 64 + mf * 16 + (lane >> 2);
            float o0x = acc[mf][nf][0] + bv.x, o0y = acc[mf][nf][1] + bv.y;
            float o1x = acc[mf][nf][2] + bv.x, o1y = acc[mf][nf][3] + bv.y;
            if (!outSplit) {
                *(float2*)&Cf[(size_t)r0 * N + c] = make_float2(o0x, o0y);
                *(float2*)&Cf[(size_t)(r0 + 8) * N + c] = make_float2(o1x, o1y);
            } else {
                uint32_t ph, pl;
                split2h(o0x, o0y, ph, pl);
                *(uint32_t*)&Chi[(size_t)r0 * N + c] = ph;
                *(uint32_t*)&Clo[(size_t)r0 * N + c] = pl;
                split2h(o1x, o1y, ph, pl);
                *(uint32_t*)&Chi[(size_t)(r0 + 8) * N + c] = ph;
                *(uint32_t*)&Clo[(size_t)(r0 + 8) * N + c] = pl;
            }
        }
    }
}

// ===========================================================================
// HMMA flash attention (causal), pre-split fp16 qkv, cp.async KV pipeline.
// QK^T: 3-pass split (softmax exponent is error-sensitive).
// P*V : 1-pass — P as single fp16, V hi only.
// Output att written as fp16 hi only (consumed by 1-pass GEMM2).
// Heavy-first scheduling.
// ===========================================================================
#define AQ_BYTES  (128 * 72 * 2)   // 18432
#define AKV_BYTES (64 * 72 * 2)    // 9216
#define ASTAGE    (3 * AKV_BYTES)  // 27648 (Khi, Klo, Vhi)
#define ATTN_SMEM (2 * AQ_BYTES + 2 * ASTAGE)   // 92160

__global__ __launch_bounds__(256, 2) void attn_hmma(
    const __half* __restrict__ qhiG, const __half* __restrict__ qloG,
    __half* __restrict__ outHi)
{
    extern __shared__ char sm[];
    const uint32_t smb = smem_u32(sm);
    const uint32_t qHA = smb;
    const uint32_t qLA = smb + AQ_BYTES;
    const int tid  = threadIdx.x;
    const int lane = tid & 31;
    const int w    = tid >> 5;
    const int qt = gridDim.x - 1 - blockIdx.x;   // heavy-first
    const int hd = blockIdx.y;     // head
    const int b  = blockIdx.z;
    const int qb = qt * 128;

    // ---- Q tile via cp.async (group 0) ----
#pragma unroll
    for (int j = 0; j < 4; j++) {
        int idx = tid + j * 256;
        int row = idx >> 3;
        int ch  = idx & 7;
        size_t so = ((size_t)b * TT + qb + row) * 3072 + (size_t)hd * 64 + ch * 8;
        uint32_t doff = row * 144 + ch * 16;
        CP_ASYNC_CG(qHA + doff, qhiG + so);
        CP_ASYNC_CG(qLA + doff, qloG + so);
    }

    auto issue_kv = [&](int jt2, int s) {
        uint32_t kH = smb + 2 * AQ_BYTES + s * ASTAGE;
        uint32_t kL = kH + AKV_BYTES;
        uint32_t vH = kH + 2 * AKV_BYTES;
        size_t base = ((size_t)b * TT + jt2 * 64) * 3072 + CC + (size_t)hd * 64;
#pragma unroll
        for (int j = 0; j < 2; j++) {
            int idx = tid + j * 256;
            int row = idx >> 3;
            int ch  = idx & 7;
            size_t so = base + (size_t)row * 3072 + ch * 8;
            uint32_t doff = row * 144 + ch * 16;
            CP_ASYNC_CG(kH + doff, qhiG + so);
            CP_ASYNC_CG(kL + doff, qloG + so);
            CP_ASYNC_CG(vH + doff, qhiG + so + CC);
        }
    };

    issue_kv(0, 0); CP_COMMIT();    // group 0 (Q + KV0)
    issue_kv(1, 1); CP_COMMIT();    // group 1

    float S[8][4];
    float O[8][4] = {};
    float m_run[2] = { -1e30f, -1e30f };
    float l_run[2] = { 0.0f, 0.0f };
    const float scale = 0.125f;

    const int wmin = qb + w * 16;
    const int r_in = lane >> 2;
    const int c2   = (lane & 3) * 2;
    const int row0 = wmin + r_in;
    const int row1 = row0 + 8;
    const int nt = 2 * qt + 2;

    for (int jt = 0; jt < nt; jt++) {
        CP_WAIT1();
        __syncthreads();
        const int s = jt & 1;
        const int kvb = jt * 64;

        if (kvb <= wmin + 15) {       // warp-uniform: tile not fully masked
            uint32_t kHA = smb + 2 * AQ_BYTES + s * ASTAGE;
            uint32_t kLA = kHA + AKV_BYTES;
            uint32_t vHA = kHA + 2 * AKV_BYTES;

            // ---- S = Q K^T (3-pass split) ----
#pragma unroll
            for (int nf = 0; nf < 8; nf++)
#pragma unroll
                for (int e = 0; e < 4; e++) S[nf][e] = 0.0f;

#pragma unroll
            for (int ks = 0; ks < 4; ks++) {
                uint32_t qh[4], ql[4];
                uint32_t qoff = ((w * 16 + (lane & 15)) * 72 + ks * 16 + (lane >> 4) * 8) * 2;
                LDSM_X4(qh, qHA + qoff);
                LDSM_X4(ql, qLA + qoff);
#pragma unroll
                for (int np = 0; np < 4; np++) {
                    uint32_t kh[4], kl[4];
                    uint32_t koff = ((np * 16 + (lane & 15)) * 72 + ks * 16 + (lane >> 4) * 8) * 2;
                    LDSM_X4(kh, kHA + koff);
                    LDSM_X4(kl, kLA + koff);
                    MMA_F16_2(S[2*np],   qh, kh[0], kh[2]);
                    MMA_F16_2(S[2*np],   qh, kl[0], kl[2]);
                    MMA_F16_2(S[2*np],   ql, kh[0], kh[2]);
                    MMA_F16_2(S[2*np+1], qh, kh[1], kh[3]);
                    MMA_F16_2(S[2*np+1], qh, kl[1], kl[3]);
                    MMA_F16_2(S[2*np+1], ql, kh[1], kh[3]);
                }
            }

            // ---- scale + causal mask + row max ----
            const bool full = (kvb + 63 <= wmin);
            float mx0 = -1e30f, mx1 = -1e30f;
#pragma unroll
            for (int nf = 0; nf < 8; nf++) {
                int col = kvb + nf * 8 + c2;
                float s0 = S[nf][0] * scale;
                float s1 = S[nf][1] * scale;
                float s2 = S[nf][2] * scale;
                float s3 = S[nf][3] * scale;
                if (!full) {
                    if (col     > row0) s0 = -1e30f;
                    if (col + 1 > row0) s1 = -1e30f;
                    if (col     > row1) s2 = -1e30f;
                    if (col + 1 > row1) s3 = -1e30f;
                }
                S[nf][0] = s0; S[nf][1] = s1; S[nf][2] = s2; S[nf][3] = s3;
                mx0 = fmaxf(mx0, fmaxf(s0, s1));
                mx1 = fmaxf(mx1, fmaxf(s2, s3));
            }
            mx0 = fmaxf(mx0, __shfl_xor_sync(0xffffffffu, mx0, 1));
            mx0 = fmaxf(mx0, __shfl_xor_sync(0xffffffffu, mx0, 2));
            mx1 = fmaxf(mx1, __shfl_xor_sync(0xffffffffu, mx1, 1));
            mx1 = fmaxf(mx1, __shfl_xor_sync(0xffffffffu, mx1, 2));

            float mn0 = fmaxf(m_run[0], mx0);
            float mn1 = fmaxf(m_run[1], mx1);
            float corr0 = __expf(m_run[0] - mn0);
            float corr1 = __expf(m_run[1] - mn1);
            l_run[0] *= corr0;
            l_run[1] *= corr1;
#pragma unroll
            for (int nf = 0; nf < 8; nf++) {
                O[nf][0] *= corr0; O[nf][1] *= corr0;
                O[nf][2] *= corr1; O[nf][3] *= corr1;
            }

            float sum0 = 0.0f, sum1 = 0.0f;
#pragma unroll
            for (int nf = 0; nf < 8; nf++) {
                float p0 = __expf(S[nf][0] - mn0);
                float p1 = __expf(S[nf][1] - mn0);
                float p2 = __expf(S[nf][2] - mn1);
                float p3 = __expf(S[nf][3] - mn1);
                S[nf][0] = p0; S[nf][1] = p1; S[nf][2] = p2; S[nf][3] = p3;
                sum0 += p0 + p1;
                sum1 += p2 + p3;
            }
            sum0 += __shfl_xor_sync(0xffffffffu, sum0, 1);
            sum0 += __shfl_xor_sync(0xffffffffu, sum0, 2);
            sum1 += __shfl_xor_sync(0xffffffffu, sum1, 1);
            sum1 += __shfl_xor_sync(0xffffffffu, sum1, 2);
            l_run[0] += sum0;
            l_run[1] += sum1;
            m_run[0] = mn0;
            m_run[1] = mn1;

            // ---- O += P V (1-pass: fp16 P, V hi only) ----
#pragma unroll
            for (int j = 0; j < 4; j++) {
                uint32_t pH[4];
                pH[0] = pack2h(S[2*j][0],   S[2*j][1]);
                pH[1] = pack2h(S[2*j][2],   S[2*j][3]);
                pH[2] = pack2h(S[2*j+1][0], S[2*j+1][1]);
                pH[3] = pack2h(S[2*j+1][2], S[2*j+1][3]);
#pragma unroll
                for (int np = 0; np < 4; np++) {
                    uint32_t vh[4];
                    uint32_t voff = ((j * 16 + (lane & 15)) * 72 + np * 16 + (lane >> 4) * 8) * 2;
                    LDSM_X4T(vh, vHA + voff);
                    MMA_F16(O[2*np],   pH, vh);
                    MMA_F16(O[2*np+1], pH, vh + 2);
                }
            }
        }

        __syncthreads();
        if (jt + 2 < nt) issue_kv(jt + 2, s);
        CP_COMMIT();
    }

    // ---- epilogue: normalize, write fp16 hi [B,T,C] ----
    float inv0 = 1.0f / l_run[0];
    float inv1 = 1.0f / l_run[1];
    size_t o0off = ((size_t)b * TT + row0) * CC + (size_t)hd * HD;
    size_t o1off = ((size_t)b * TT + row1) * CC + (size_t)hd * HD;
#pragma unroll
    for (int nf = 0; nf < 8; nf++) {
        int c = nf * 8 + c2;
        *(uint32_t*)&outHi[o0off + c] = pack2h(O[nf][0] * inv0, O[nf][1] * inv0);
        *(uint32_t*)&outHi[o1off + c] = pack2h(O[nf][2] * inv1, O[nf][3] * inv1);
    }
}

// ---------------------------------------------------------------------------
extern "C" void kernel_launch(void* const* d_in, const int* in_sizes, int n_in,
                              void* d_out, int out_size)
{
    const float* x     = (const float*)d_in[0];
    const float* Wqkv  = (const float*)d_in[1];
    const float* bqkv  = (const float*)d_in[2];
    const float* Wproj = (const float*)d_in[3];
    const float* bproj = (const float*)d_in[4];
    float* out = (float*)d_out;

    __half *xhi, *xlo, *wqhi, *wqlo, *wphi, *qkvhi, *qkvlo, *atthi;
    cudaGetSymbolAddress((void**)&xhi,   g_xhi);
    cudaGetSymbolAddress((void**)&xlo,   g_xlo);
    cudaGetSymbolAddress((void**)&wqhi,  g_wqhi);
    cudaGetSymbolAddress((void**)&wqlo,  g_wqlo);
    cudaGetSymbolAddress((void**)&wphi,  g_wphi);
    cudaGetSymbolAddress((void**)&qkvhi, g_qkvhi);
    cudaGetSymbolAddress((void**)&qkvlo, g_qkvlo);
    cudaGetSymbolAddress((void**)&atthi, g_atthi);

    cudaFuncSetAttribute(gemm_f16,
                         cudaFuncAttributeMaxDynamicSharedMemorySize, GEMM_SMEM);
    cudaFuncSetAttribute(attn_hmma,
                         cudaFuncAttributeMaxDynamicSharedMemorySize, ATTN_SMEM);

    // 0) pre-split inputs to hi/lo fp16 (Wproj: hi only, lo never consumed)
    int n4x = BT * CC / 4;
    split_f32<<<n4x / 256, 256>>>(x, xhi, xlo, n4x);
    int n4q = CC * 3 * CC / 4;
    split_f32<<<n4q / 256, 256>>>(Wqkv, wqhi, wqlo, n4q);
    int n4p = CC * CC / 4;
    trunc_f32<<<n4p / 256, 256>>>(Wproj, wphi, n4p);

    dim3 blk(256);
    // 1) qkv = x @ W_qkv + b_qkv  -> hi/lo fp16.  Mixed pass: V cols 2-pass.
    gemm_f16<<<dim3(3 * CC / 128, BT / 128), blk, GEMM_SMEM>>>(
        xhi, xlo, wqhi, wqlo, bqkv, nullptr, qkvhi, qkvlo, BT, 3 * CC, CC, 1, 2);
    // 2) attention -> att fp16 hi
    attn_hmma<<<dim3(TT / 128, HH, BB), blk, ATTN_SMEM>>>(qkvhi, qkvlo, atthi);
    // 3) out = att @ W_proj + b_proj  -> fp32.  1-pass (hi·hi).
    gemm_f16<<<dim3(CC / 128, BT / 128), blk, GEMM_SMEM>>>(
        atthi, nullptr, wphi, nullptr, bproj, out, nullptr, nullptr, BT, CC, CC, 0, 3);
}

// round 14
// speedup vs baseline: 1.3796x; 1.0962x over previous
#include <cuda_runtime.h>
#include <cuda_fp16.h>
#include <cstdint>
#include <math.h>

// Problem constants
#define BB 4
#define TT 2048
#define CC 1024
#define HH 16
#define HD 64
#define BT (BB*TT)          // 8192

// Pre-split fp16 scratch (device globals: allocation-free per harness rules)
__device__ __align__(256) __half g_xhi[(size_t)BT * CC];
__device__ __align__(256) __half g_wqhi[(size_t)CC * 3 * CC];
__device__ __align__(256) __half g_wqlo[(size_t)CC * 3 * CC];
__device__ __align__(256) __half g_wphi[(size_t)CC * CC];
__device__ __align__(256) __half g_qkvhi[(size_t)BT * 3 * CC];
__device__ __align__(256) __half g_qkvlo[(size_t)BT * 3 * CC];
__device__ __align__(256) __half g_atthi[(size_t)BT * CC];

// ===========================================================================
// Helpers
// ===========================================================================
__device__ __forceinline__ uint32_t smem_u32(const void* p) {
    uint32_t a;
    asm("{ .reg .u64 t; cvta.to.shared.u64 t, %1; cvt.u32.u64 %0, t; }"
        : "=r"(a) : "l"(p));
    return a;
}

#define LDSM_X4(r, addr) \
    asm volatile("ldmatrix.sync.aligned.m8n8.x4.shared.b16 {%0,%1,%2,%3}, [%4];" \
        : "=r"((r)[0]), "=r"((r)[1]), "=r"((r)[2]), "=r"((r)[3]) : "r"(addr))

#define LDSM_X4T(r, addr) \
    asm volatile("ldmatrix.sync.aligned.m8n8.x4.trans.shared.b16 {%0,%1,%2,%3}, [%4];" \
        : "=r"((r)[0]), "=r"((r)[1]), "=r"((r)[2]), "=r"((r)[3]) : "r"(addr))

#define MMA_F16(c, a, b) \
    asm volatile("mma.sync.aligned.m16n8k16.row.col.f32.f16.f16.f32 " \
        "{%0,%1,%2,%3}, {%4,%5,%6,%7}, {%8,%9}, {%0,%1,%2,%3};" \
        : "+f"((c)[0]), "+f"((c)[1]), "+f"((c)[2]), "+f"((c)[3]) \
        : "r"((a)[0]), "r"((a)[1]), "r"((a)[2]), "r"((a)[3]), \
          "r"((b)[0]), "r"((b)[1]))

#define MMA_F16_2(c, a, b0, b1) \
    asm volatile("mma.sync.aligned.m16n8k16.row.col.f32.f16.f16.f32 " \
        "{%0,%1,%2,%3}, {%4,%5,%6,%7}, {%8,%9}, {%0,%1,%2,%3};" \
        : "+f"((c)[0]), "+f"((c)[1]), "+f"((c)[2]), "+f"((c)[3]) \
        : "r"((a)[0]), "r"((a)[1]), "r"((a)[2]), "r"((a)[3]), \
          "r"(b0), "r"(b1))

#define CP_ASYNC_CG(dst, src) \
    asm volatile("cp.async.cg.shared.global [%0], [%1], 16;" :: "r"(dst), "l"(src))
#define CP_COMMIT() asm volatile("cp.async.commit_group;" ::: "memory")
#define CP_WAIT1()  asm volatile("cp.async.wait_group 1;" ::: "memory")

__device__ __forceinline__ uint32_t pack2h(float a, float b) {
    __half2 t = __floats2half2_rn(a, b);
    return *(uint32_t*)&t;
}

// split x into hi (fp16-representable float) and lo = x - hi (fp16)
__device__ __forceinline__ void split2h(float a, float b, uint32_t& hi, uint32_t& lo) {
    __half ha = __float2half_rn(a);
    __half hb = __float2half_rn(b);
    __half2 hp = __halves2half2(ha, hb);
    hi = *(uint32_t*)&hp;
    lo = pack2h(a - __half2float(ha), b - __half2float(hb));
}

// ===========================================================================
// split_f32: fp32 array -> hi/lo fp16 arrays (4 elems/thread)
// ===========================================================================
__global__ __launch_bounds__(256) void split_f32(
    const float* __restrict__ in, __half* __restrict__ hi,
    __half* __restrict__ lo, int n4)
{
    int i = blockIdx.x * 256 + threadIdx.x;
    if (i >= n4) return;
    float4 v = ((const float4*)in)[i];
    uint32_t h0, l0, h1, l1;
    split2h(v.x, v.y, h0, l0);
    split2h(v.z, v.w, h1, l1);
    ((uint2*)hi)[i] = make_uint2(h0, h1);
    ((uint2*)lo)[i] = make_uint2(l0, l1);
}

// hi-only variant (lo never consumed)
__global__ __launch_bounds__(256) void trunc_f32(
    const float* __restrict__ in, __half* __restrict__ hi, int n4)
{
    int i = blockIdx.x * 256 + threadIdx.x;
    if (i >= n4) return;
    float4 v = ((const float4*)in)[i];
    ((uint2*)hi)[i] = make_uint2(pack2h(v.x, v.y), pack2h(v.z, v.w));
}

// ===========================================================================
// HMMA split-fp16 GEMM, pre-split fp16 inputs, 3-stage cp.async pipeline,
// ONE __syncthreads per 32-K chunk.  2 CTAs/SM.
// passMode: 0 = 3-pass; 1 = 2-pass (Ahi·Bhi + Ahi·Blo); 3 = 1-pass (hi·hi).
// C = A@B + bias; output fp32 OR hi/lo fp16 pair (outSplit).
// 128x128 tile, BK=32, 8 warps (2x4), warp tile 64x32.
// ===========================================================================
#define GA_STRIDE 40          // fp16 elems/row (32+8) -> conflict-free ldsm
#define GB_STRIDE 136         // fp16 elems/row (128+8)
#define GA_BYTES (128 * GA_STRIDE * 2)   // 10240
#define GB_BYTES (32 * GB_STRIDE * 2)    // 8704
#define GBUF (2 * GA_BYTES + 2 * GB_BYTES)   // 37888
#define GEMM_SMEM (3 * GBUF)                  // 113664

__global__ __launch_bounds__(256, 2) void gemm_f16(
    const __half* __restrict__ Ahi, const __half* __restrict__ Alo,
    const __half* __restrict__ Bhi, const __half* __restrict__ Blo,
    const float* __restrict__ bias,
    float* __restrict__ Cf,
    __half* __restrict__ Chi, __half* __restrict__ Clo,
    int M, int N, int K, int outSplit, int passMode)
{
    extern __shared__ char sm[];
    const uint32_t smb = smem_u32(sm);
    const int tid  = threadIdx.x;
    const int lane = tid & 31;
    const int wid  = tid >> 5;
    const int wm   = wid >> 2;
    const int wn   = wid & 3;
    const int rowBase = blockIdx.y * 128;
    const int colBase = blockIdx.x * 128;
    const bool useAlo = (passMode == 0);
    const bool useBlo = (passMode != 3);

    auto issue = [&](int k0, int bi) {
        uint32_t aH = smb + bi * GBUF;
        uint32_t aL = aH + GA_BYTES;
        uint32_t bH = aH + 2 * GA_BYTES;
        uint32_t bL = bH + GB_BYTES;
#pragma unroll
        for (int j = 0; j < 2; j++) {
            int idx = tid + j * 256;
            int m  = idx >> 2;
            int ch = idx & 3;
            size_t ao = (size_t)(rowBase + m) * K + k0 + ch * 8;
            uint32_t ad = m * 80 + ch * 16;
            CP_ASYNC_CG(aH + ad, Ahi + ao);
            if (useAlo) CP_ASYNC_CG(aL + ad, Alo + ao);
            int kk = idx >> 4;
            int c2 = idx & 15;
            size_t bo = (size_t)(k0 + kk) * N + colBase + c2 * 8;
            uint32_t bd = kk * 272 + c2 * 16;
            CP_ASYNC_CG(bH + bd, Bhi + bo);
            if (useBlo) CP_ASYNC_CG(bL + bd, Blo + bo);
        }
    };

    float acc[4][4][4] = {};
    const int NS = K >> 5;

    // prologue: stages 0 and 1 in flight
    issue(0, 0);  CP_COMMIT();
    issue(32, 1); CP_COMMIT();

    int buf = 0;        // c % 3
    int nbuf = 2;       // (c+2) % 3
    for (int c = 0; c < NS; c++) {
        CP_WAIT1();
        __syncthreads();

        if (c + 2 < NS) issue((c + 2) << 5, nbuf);
        CP_COMMIT();

        uint32_t aH = smb + buf * GBUF;
        uint32_t aL = aH + GA_BYTES;
        uint32_t bH = aH + 2 * GA_BYTES;
        uint32_t bL = bH + GB_BYTES;

#pragma unroll
        for (int ks = 0; ks < 2; ks++) {
            uint32_t fAH[4][4], fAL[4][4];
#pragma unroll
            for (int mf = 0; mf < 4; mf++) {
                uint32_t off = ((wm * 64 + mf * 16 + (lane & 15)) * GA_STRIDE
                                + ks * 16 + (lane >> 4) * 8) * 2;
                LDSM_X4(fAH[mf], aH + off);
                if (useAlo) LDSM_X4(fAL[mf], aL + off);
            }
#pragma unroll
            for (int nq = 0; nq < 2; nq++) {
                uint32_t fBH[4], fBL[4];
                uint32_t off = ((ks * 16 + (lane & 15)) * GB_STRIDE
                                + wn * 32 + nq * 16 + (lane >> 4) * 8) * 2;
                LDSM_X4T(fBH, bH + off);
                if (useBlo) LDSM_X4T(fBL, bL + off);
#pragma unroll
                for (int mf = 0; mf < 4; mf++) {
                    MMA_F16(acc[mf][2*nq],   fAH[mf], fBH);
                    MMA_F16(acc[mf][2*nq+1], fAH[mf], fBH + 2);
                    if (useBlo) {
                        MMA_F16(acc[mf][2*nq],   fAH[mf], fBL);
                        MMA_F16(acc[mf][2*nq+1], fAH[mf], fBL + 2);
                    }
                    if (useAlo) {
                        MMA_F16(acc[mf][2*nq],   fAL[mf], fBH);
                        MMA_F16(acc[mf][2*nq+1], fAL[mf], fBH + 2);
                    }
                }
            }
        }
        buf  = (buf  == 2) ? 0 : buf + 1;
        nbuf = (nbuf == 2) ? 0 : nbuf + 1;
    }

    // ---- Epilogue ----
#pragma unroll
    for (int nf = 0; nf < 4; nf++) {
        int c = colBase + wn * 32 + nf * 8 + 2 * (lane & 3);
        float2 bv = *(const float2*)&bias[c];
#pragma unroll
        for (int mf = 0; mf < 4; mf++) {
            int r0 = rowBase + wm * 64 + mf * 16 + (lane >> 2);
            float o0x = acc[mf][nf][0] + bv.x, o0y = acc[mf][nf][1] + bv.y;
            float o1x = acc[mf][nf][2] + bv.x, o1y = acc[mf][nf][3] + bv.y;
            if (!outSplit) {
                *(float2*)&Cf[(size_t)r0 * N + c] = make_float2(o0x, o0y);
                *(float2*)&Cf[(size_t)(r0 + 8) * N + c] = make_float2(o1x, o1y);
            } else {
                uint32_t ph, pl;
                split2h(o0x, o0y, ph, pl);
                *(uint32_t*)&Chi[(size_t)r0 * N + c] = ph;
                *(uint32_t*)&Clo[(size_t)r0 * N + c] = pl;
                split2h(o1x, o1y, ph, pl);
                *(uint32_t*)&Chi[(size_t)(r0 + 8) * N + c] = ph;
                *(uint32_t*)&Clo[(size_t)(r0 + 8) * N + c] = pl;
            }
        }
    }
}

// ===========================================================================
// HMMA flash attention (causal), pre-split fp16 qkv, cp.async KV pipeline.
// QK^T: 2-pass — Qhi·(Khi+Klo); Q-lo never loaded.
// P*V : 1-pass — P as single fp16, V hi only.
// Output att written as fp16 hi only (consumed by 1-pass GEMM2).
// Heavy-first scheduling.
// ===========================================================================
#define AQ_BYTES  (128 * 72 * 2)   // 18432 (Q hi only)
#define AKV_BYTES (64 * 72 * 2)    // 9216
#define ASTAGE    (3 * AKV_BYTES)  // 27648 (Khi, Klo, Vhi)
#define ATTN_SMEM (AQ_BYTES + 2 * ASTAGE)   // 73728

__global__ __launch_bounds__(256, 2) void attn_hmma(
    const __half* __restrict__ qhiG, const __half* __restrict__ qloG,
    __half* __restrict__ outHi)
{
    extern __shared__ char sm[];
    const uint32_t smb = smem_u32(sm);
    const uint32_t qHA = smb;
    const int tid  = threadIdx.x;
    const int lane = tid & 31;
    const int w    = tid >> 5;
    const int qt = gridDim.x - 1 - blockIdx.x;   // heavy-first
    const int hd = blockIdx.y;     // head
    const int b  = blockIdx.z;
    const int qb = qt * 128;

    // ---- Q tile (hi only) via cp.async (group 0) ----
#pragma unroll
    for (int j = 0; j < 4; j++) {
        int idx = tid + j * 256;
        int row = idx >> 3;
        int ch  = idx & 7;
        size_t so = ((size_t)b * TT + qb + row) * 3072 + (size_t)hd * 64 + ch * 8;
        uint32_t doff = row * 144 + ch * 16;
        CP_ASYNC_CG(qHA + doff, qhiG + so);
    }

    auto issue_kv = [&](int jt2, int s) {
        uint32_t kH = smb + AQ_BYTES + s * ASTAGE;
        uint32_t kL = kH + AKV_BYTES;
        uint32_t vH = kH + 2 * AKV_BYTES;
        size_t base = ((size_t)b * TT + jt2 * 64) * 3072 + CC + (size_t)hd * 64;
#pragma unroll
        for (int j = 0; j < 2; j++) {
            int idx = tid + j * 256;
            int row = idx >> 3;
            int ch  = idx & 7;
            size_t so = base + (size_t)row * 3072 + ch * 8;
            uint32_t doff = row * 144 + ch * 16;
            CP_ASYNC_CG(kH + doff, qhiG + so);
            CP_ASYNC_CG(kL + doff, qloG + so);
            CP_ASYNC_CG(vH + doff, qhiG + so + CC);
        }
    };

    issue_kv(0, 0); CP_COMMIT();    // group 0 (Q + KV0)
    issue_kv(1, 1); CP_COMMIT();    // group 1

    float S[8][4];
    float O[8][4] = {};
    float m_run[2] = { -1e30f, -1e30f };
    float l_run[2] = { 0.0f, 0.0f };
    const float scale = 0.125f;

    const int wmin = qb + w * 16;
    const int r_in = lane >> 2;
    const int c2   = (lane & 3) * 2;
    const int row0 = wmin + r_in;
    const int row1 = row0 + 8;
    const int nt = 2 * qt + 2;

    for (int jt = 0; jt < nt; jt++) {
        CP_WAIT1();
        __syncthreads();
        const int s = jt & 1;
        const int kvb = jt * 64;

        if (kvb <= wmin + 15) {       // warp-uniform: tile not fully masked
            uint32_t kHA = smb + AQ_BYTES + s * ASTAGE;
            uint32_t kLA = kHA + AKV_BYTES;
            uint32_t vHA = kHA + 2 * AKV_BYTES;

            // ---- S = Q K^T (2-pass: Qhi·Khi + Qhi·Klo) ----
#pragma unroll
            for (int nf = 0; nf < 8; nf++)
#pragma unroll
                for (int e = 0; e < 4; e++) S[nf][e] = 0.0f;

#pragma unroll
            for (int ks = 0; ks < 4; ks++) {
                uint32_t qh[4];
                uint32_t qoff = ((w * 16 + (lane & 15)) * 72 + ks * 16 + (lane >> 4) * 8) * 2;
                LDSM_X4(qh, qHA + qoff);
#pragma unroll
                for (int np = 0; np < 4; np++) {
                    uint32_t kh[4], kl[4];
                    uint32_t koff = ((np * 16 + (lane & 15)) * 72 + ks * 16 + (lane >> 4) * 8) * 2;
                    LDSM_X4(kh, kHA + koff);
                    LDSM_X4(kl, kLA + koff);
                    MMA_F16_2(S[2*np],   qh, kh[0], kh[2]);
                    MMA_F16_2(S[2*np],   qh, kl[0], kl[2]);
                    MMA_F16_2(S[2*np+1], qh, kh[1], kh[3]);
                    MMA_F16_2(S[2*np+1], qh, kl[1], kl[3]);
                }
            }

            // ---- scale + causal mask + row max ----
            const bool full = (kvb + 63 <= wmin);
            float mx0 = -1e30f, mx1 = -1e30f;
#pragma unroll
            for (int nf = 0; nf < 8; nf++) {
                int col = kvb + nf * 8 + c2;
                float s0 = S[nf][0] * scale;
                float s1 = S[nf][1] * scale;
                float s2 = S[nf][2] * scale;
                float s3 = S[nf][3] * scale;
                if (!full) {
                    if (col     > row0) s0 = -1e30f;
                    if (col + 1 > row0) s1 = -1e30f;
                    if (col     > row1) s2 = -1e30f;
                    if (col + 1 > row1) s3 = -1e30f;
                }
                S[nf][0] = s0; S[nf][1] = s1; S[nf][2] = s2; S[nf][3] = s3;
                mx0 = fmaxf(mx0, fmaxf(s0, s1));
                mx1 = fmaxf(mx1, fmaxf(s2, s3));
            }
            mx0 = fmaxf(mx0, __shfl_xor_sync(0xffffffffu, mx0, 1));
            mx0 = fmaxf(mx0, __shfl_xor_sync(0xffffffffu, mx0, 2));
            mx1 = fmaxf(mx1, __shfl_xor_sync(0xffffffffu, mx1, 1));
            mx1 = fmaxf(mx1, __shfl_xor_sync(0xffffffffu, mx1, 2));

            float mn0 = fmaxf(m_run[0], mx0);
            float mn1 = fmaxf(m_run[1], mx1);
            float corr0 = __expf(m_run[0] - mn0);
            float corr1 = __expf(m_run[1] - mn1);
            l_run[0] *= corr0;
            l_run[1] *= corr1;
#pragma unroll
            for (int nf = 0; nf < 8; nf++) {
                O[nf][0] *= corr0; O[nf][1] *= corr0;
                O[nf][2] *= corr1; O[nf][3] *= corr1;
            }

            float sum0 = 0.0f, sum1 = 0.0f;
#pragma unroll
            for (int nf = 0; nf < 8; nf++) {
                float p0 = __expf(S[nf][0] - mn0);
                float p1 = __expf(S[nf][1] - mn0);
                float p2 = __expf(S[nf][2] - mn1);
                float p3 = __expf(S[nf][3] - mn1);
                S[nf][0] = p0; S[nf][1] = p1; S[nf][2] = p2; S[nf][3] = p3;
                sum0 += p0 + p1;
                sum1 += p2 + p3;
            }
            sum0 += __shfl_xor_sync(0xffffffffu, sum0, 1);
            sum0 += __shfl_xor_sync(0xffffffffu, sum0, 2);
            sum1 += __shfl_xor_sync(0xffffffffu, sum1, 1);
            sum1 += __shfl_xor_sync(0xffffffffu, sum1, 2);
            l_run[0] += sum0;
            l_run[1] += sum1;
            m_run[0] = mn0;
            m_run[1] = mn1;

            // ---- O += P V (1-pass: fp16 P, V hi only) ----
#pragma unroll
            for (int j = 0; j < 4; j++) {
                uint32_t pH[4];
                pH[0] = pack2h(S[2*j][0],   S[2*j][1]);
                pH[1] = pack2h(S[2*j][2],   S[2*j][3]);
                pH[2] = pack2h(S[2*j+1][0], S[2*j+1][1]);
                pH[3] = pack2h(S[2*j+1][2], S[2*j+1][3]);
#pragma unroll
                for (int np = 0; np < 4; np++) {
                    uint32_t vh[4];
                    uint32_t voff = ((j * 16 + (lane & 15)) * 72 + np * 16 + (lane >> 4) * 8) * 2;
                    LDSM_X4T(vh, vHA + voff);
                    MMA_F16(O[2*np],   pH, vh);
                    MMA_F16(O[2*np+1], pH, vh + 2);
                }
            }
        }

        __syncthreads();
        if (jt + 2 < nt) issue_kv(jt + 2, s);
        CP_COMMIT();
    }

    // ---- epilogue: normalize, write fp16 hi [B,T,C] ----
    float inv0 = 1.0f / l_run[0];
    float inv1 = 1.0f / l_run[1];
    size_t o0off = ((size_t)b * TT + row0) * CC + (size_t)hd * HD;
    size_t o1off = ((size_t)b * TT + row1) * CC + (size_t)hd * HD;
#pragma unroll
    for (int nf = 0; nf < 8; nf++) {
        int c = nf * 8 + c2;
        *(uint32_t*)&outHi[o0off + c] = pack2h(O[nf][0] * inv0, O[nf][1] * inv0);
        *(uint32_t*)&outHi[o1off + c] = pack2h(O[nf][2] * inv1, O[nf][3] * inv1);
    }
}

// ---------------------------------------------------------------------------
extern "C" void kernel_launch(void* const* d_in, const int* in_sizes, int n_in,
                              void* d_out, int out_size)
{
    const float* x     = (const float*)d_in[0];
    const float* Wqkv  = (const float*)d_in[1];
    const float* bqkv  = (const float*)d_in[2];
    const float* Wproj = (const float*)d_in[3];
    const float* bproj = (const float*)d_in[4];
    float* out = (float*)d_out;

    __half *xhi, *wqhi, *wqlo, *wphi, *qkvhi, *qkvlo, *atthi;
    cudaGetSymbolAddress((void**)&xhi,   g_xhi);
    cudaGetSymbolAddress((void**)&wqhi,  g_wqhi);
    cudaGetSymbolAddress((void**)&wqlo,  g_wqlo);
    cudaGetSymbolAddress((void**)&wphi,  g_wphi);
    cudaGetSymbolAddress((void**)&qkvhi, g_qkvhi);
    cudaGetSymbolAddress((void**)&qkvlo, g_qkvlo);
    cudaGetSymbolAddress((void**)&atthi, g_atthi);

    cudaFuncSetAttribute(gemm_f16,
                         cudaFuncAttributeMaxDynamicSharedMemorySize, GEMM_SMEM);
    cudaFuncSetAttribute(attn_hmma,
                         cudaFuncAttributeMaxDynamicSharedMemorySize, ATTN_SMEM);

    // 0) pre-split inputs to fp16 (x, Wproj: hi only; Wqkv: hi+lo)
    int n4x = BT * CC / 4;
    trunc_f32<<<n4x / 256, 256>>>(x, xhi, n4x);
    int n4q = CC * 3 * CC / 4;
    split_f32<<<n4q / 256, 256>>>(Wqkv, wqhi, wqlo, n4q);
    int n4p = CC * CC / 4;
    trunc_f32<<<n4p / 256, 256>>>(Wproj, wphi, n4p);

    dim3 blk(256);
    // 1) qkv = x @ W_qkv + b_qkv  -> hi/lo fp16.  2-pass everywhere.
    gemm_f16<<<dim3(3 * CC / 128, BT / 128), blk, GEMM_SMEM>>>(
        xhi, nullptr, wqhi, wqlo, bqkv, nullptr, qkvhi, qkvlo, BT, 3 * CC, CC, 1, 1);
    // 2) attention -> att fp16 hi
    attn_hmma<<<dim3(TT / 128, HH, BB), blk, ATTN_SMEM>>>(qkvhi, qkvlo, atthi);
    // 3) out = att @ W_proj + b_proj  -> fp32.  1-pass (hi·hi).
    gemm_f16<<<dim3(CC / 128, BT / 128), blk, GEMM_SMEM>>>(
        atthi, nullptr, wphi, nullptr, bproj, out, nullptr, nullptr, BT, CC, CC, 0, 3);
}

// round 15
// speedup vs baseline: 1.6406x; 1.1892x over previous
#include <cuda_runtime.h>
#include <cuda_fp16.h>
#include <cstdint>
#include <math.h>

// Problem constants
#define BB 4
#define TT 2048
#define CC 1024
#define HH 16
#define HD 64
#define BT (BB*TT)          // 8192

// Pre-split fp16 scratch (device globals: allocation-free per harness rules)
__device__ __align__(256) __half g_xhi[(size_t)BT * CC];
__device__ __align__(256) __half g_wqhi[(size_t)CC * 3 * CC];
__device__ __align__(256) __half g_wqlo[(size_t)CC * 3 * CC];
__device__ __align__(256) __half g_wphi[(size_t)CC * CC];
__device__ __align__(256) __half g_qkvhi[(size_t)BT * 3 * CC];
__device__ __align__(256) __half g_qkvlo[(size_t)BT * 3 * CC];
__device__ __align__(256) __half g_atthi[(size_t)BT * CC];

// ===========================================================================
// Helpers
// ===========================================================================
__device__ __forceinline__ uint32_t smem_u32(const void* p) {
    uint32_t a;
    asm("{ .reg .u64 t; cvta.to.shared.u64 t, %1; cvt.u32.u64 %0, t; }"
        : "=r"(a) : "l"(p));
    return a;
}

#define LDSM_X4(r, addr) \
    asm volatile("ldmatrix.sync.aligned.m8n8.x4.shared.b16 {%0,%1,%2,%3}, [%4];" \
        : "=r"((r)[0]), "=r"((r)[1]), "=r"((r)[2]), "=r"((r)[3]) : "r"(addr))

#define LDSM_X4T(r, addr) \
    asm volatile("ldmatrix.sync.aligned.m8n8.x4.trans.shared.b16 {%0,%1,%2,%3}, [%4];" \
        : "=r"((r)[0]), "=r"((r)[1]), "=r"((r)[2]), "=r"((r)[3]) : "r"(addr))

#define MMA_F16(c, a, b) \
    asm volatile("mma.sync.aligned.m16n8k16.row.col.f32.f16.f16.f32 " \
        "{%0,%1,%2,%3}, {%4,%5,%6,%7}, {%8,%9}, {%0,%1,%2,%3};" \
        : "+f"((c)[0]), "+f"((c)[1]), "+f"((c)[2]), "+f"((c)[3]) \
        : "r"((a)[0]), "r"((a)[1]), "r"((a)[2]), "r"((a)[3]), \
          "r"((b)[0]), "r"((b)[1]))

#define MMA_F16_2(c, a, b0, b1) \
    asm volatile("mma.sync.aligned.m16n8k16.row.col.f32.f16.f16.f32 " \
        "{%0,%1,%2,%3}, {%4,%5,%6,%7}, {%8,%9}, {%0,%1,%2,%3};" \
        : "+f"((c)[0]), "+f"((c)[1]), "+f"((c)[2]), "+f"((c)[3]) \
        : "r"((a)[0]), "r"((a)[1]), "r"((a)[2]), "r"((a)[3]), \
          "r"(b0), "r"(b1))

#define CP_ASYNC_CG(dst, src) \
    asm volatile("cp.async.cg.shared.global [%0], [%1], 16;" :: "r"(dst), "l"(src))
#define CP_COMMIT() asm volatile("cp.async.commit_group;" ::: "memory")
#define CP_WAIT0()  asm volatile("cp.async.wait_group 0;" ::: "memory")
#define CP_WAIT1()  asm volatile("cp.async.wait_group 1;" ::: "memory")

__device__ __forceinline__ uint32_t pack2h(float a, float b) {
    __half2 t = __floats2half2_rn(a, b);
    return *(uint32_t*)&t;
}

// split x into hi (fp16-representable float) and lo = x - hi (fp16)
__device__ __forceinline__ void split2h(float a, float b, uint32_t& hi, uint32_t& lo) {
    __half ha = __float2half_rn(a);
    __half hb = __float2half_rn(b);
    __half2 hp = __halves2half2(ha, hb);
    hi = *(uint32_t*)&hp;
    lo = pack2h(a - __half2float(ha), b - __half2float(hb));
}

// ===========================================================================
// split_f32: fp32 array -> hi/lo fp16 arrays (4 elems/thread)
// ===========================================================================
__global__ __launch_bounds__(256) void split_f32(
    const float* __restrict__ in, __half* __restrict__ hi,
    __half* __restrict__ lo, int n4)
{
    int i = blockIdx.x * 256 + threadIdx.x;
    if (i >= n4) return;
    float4 v = ((const float4*)in)[i];
    uint32_t h0, l0, h1, l1;
    split2h(v.x, v.y, h0, l0);
    split2h(v.z, v.w, h1, l1);
    ((uint2*)hi)[i] = make_uint2(h0, h1);
    ((uint2*)lo)[i] = make_uint2(l0, l1);
}

// hi-only variant (lo never consumed)
__global__ __launch_bounds__(256) void trunc_f32(
    const float* __restrict__ in, __half* __restrict__ hi, int n4)
{
    int i = blockIdx.x * 256 + threadIdx.x;
    if (i >= n4) return;
    float4 v = ((const float4*)in)[i];
    ((uint2*)hi)[i] = make_uint2(pack2h(v.x, v.y), pack2h(v.z, v.w));
}

// ===========================================================================
// HMMA split-fp16 GEMM, BK=64, 2-stage cp.async pipeline, ONE sync per chunk.
// 2 CTAs/SM.  passMode: 1 = 2-pass (Ahi·Bhi + Ahi·Blo); 3 = 1-pass (hi·hi).
// C = A@B + bias; output fp32 OR hi/lo fp16 pair (outSplit).
// 128x128 tile, 8 warps (2x4), warp tile 64x32.
// ===========================================================================
#define GA_STRIDE 72          // fp16 elems/row (64+8): 144B rows, conflict-free
#define GB_STRIDE 136         // fp16 elems/row (128+8): 272B rows
#define GA_BYTES (128 * GA_STRIDE * 2)   // 18432
#define GB_BYTES (64 * GB_STRIDE * 2)    // 17408
#define GBUF (GA_BYTES + 2 * GB_BYTES)   // 53248 (Ahi, Bhi, Blo)
#define GEMM_SMEM (2 * GBUF)             // 106496

__global__ __launch_bounds__(256, 2) void gemm_f16(
    const __half* __restrict__ Ahi,
    const __half* __restrict__ Bhi, const __half* __restrict__ Blo,
    const float* __restrict__ bias,
    float* __restrict__ Cf,
    __half* __restrict__ Chi, __half* __restrict__ Clo,
    int M, int N, int K, int outSplit, int passMode)
{
    extern __shared__ char sm[];
    const uint32_t smb = smem_u32(sm);
    const int tid  = threadIdx.x;
    const int lane = tid & 31;
    const int wid  = tid >> 5;
    const int wm   = wid >> 2;
    const int wn   = wid & 3;
    const int rowBase = blockIdx.y * 128;
    const int colBase = blockIdx.x * 128;
    const bool useBlo = (passMode != 3);

    auto issue = [&](int k0, int bi) {
        uint32_t aH = smb + bi * GBUF;
        uint32_t bH = aH + GA_BYTES;
        uint32_t bL = bH + GB_BYTES;
        // A: 128 rows x 64 cols x 2B = 8 chunks of 16B per row -> 1024 loads
#pragma unroll
        for (int j = 0; j < 4; j++) {
            int idx = tid + j * 256;
            int m  = idx >> 3;
            int ch = idx & 7;
            size_t ao = (size_t)(rowBase + m) * K + k0 + ch * 8;
            CP_ASYNC_CG(aH + m * 144 + ch * 16, Ahi + ao);
            // B: 64 rows x 128 cols x 2B = 16 chunks/row -> 1024 loads each
            int kk = idx >> 4;
            int c2 = idx & 15;
            size_t bo = (size_t)(k0 + kk) * N + colBase + c2 * 8;
            uint32_t bd = kk * 272 + c2 * 16;
            CP_ASYNC_CG(bH + bd, Bhi + bo);
            if (useBlo) CP_ASYNC_CG(bL + bd, Blo + bo);
        }
    };

    float acc[4][4][4] = {};
    const int NS = K >> 6;    // 16 chunks of BK=64

    issue(0, 0);
    CP_COMMIT();

    for (int c = 0; c < NS; c++) {
        CP_WAIT0();          // chunk c landed (only outstanding group)
        __syncthreads();     // all warps done computing chunk c-1 (stage (c+1)&1)

        if (c + 1 < NS) issue((c + 1) << 6, (c + 1) & 1);
        CP_COMMIT();         // chunk c+1 loads overlap compute(c)

        uint32_t aH = smb + (c & 1) * GBUF;
        uint32_t bH = aH + GA_BYTES;
        uint32_t bL = bH + GB_BYTES;

#pragma unroll
        for (int ks = 0; ks < 4; ks++) {
            uint32_t fAH[4][4];
#pragma unroll
            for (int mf = 0; mf < 4; mf++) {
                uint32_t off = ((wm * 64 + mf * 16 + (lane & 15)) * GA_STRIDE
                                + ks * 16 + (lane >> 4) * 8) * 2;
                LDSM_X4(fAH[mf], aH + off);
            }
#pragma unroll
            for (int nq = 0; nq < 2; nq++) {
                uint32_t fBH[4], fBL[4];
                uint32_t off = ((ks * 16 + (lane & 15)) * GB_STRIDE
                                + wn * 32 + nq * 16 + (lane >> 4) * 8) * 2;
                LDSM_X4T(fBH, bH + off);
                if (useBlo) LDSM_X4T(fBL, bL + off);
#pragma unroll
                for (int mf = 0; mf < 4; mf++) {
                    MMA_F16(acc[mf][2*nq],   fAH[mf], fBH);
                    MMA_F16(acc[mf][2*nq+1], fAH[mf], fBH + 2);
                    if (useBlo) {
                        MMA_F16(acc[mf][2*nq],   fAH[mf], fBL);
                        MMA_F16(acc[mf][2*nq+1], fAH[mf], fBL + 2);
                    }
                }
            }
        }
    }

    // ---- Epilogue ----
#pragma unroll
    for (int nf = 0; nf < 4; nf++) {
        int c = colBase + wn * 32 + nf * 8 + 2 * (lane & 3);
        float2 bv = *(const float2*)&bias[c];
#pragma unroll
        for (int mf = 0; mf < 4; mf++) {
            int r0 = rowBase + wm * 64 + mf * 16 + (lane >> 2);
            float o0x = acc[mf][nf][0] + bv.x, o0y = acc[mf][nf][1] + bv.y;
            float o1x = acc[mf][nf][2] + bv.x, o1y = acc[mf][nf][3] + bv.y;
            if (!outSplit) {
                *(float2*)&Cf[(size_t)r0 * N + c] = make_float2(o0x, o0y);
                *(float2*)&Cf[(size_t)(r0 + 8) * N + c] = make_float2(o1x, o1y);
            } else {
                uint32_t ph, pl;
                split2h(o0x, o0y, ph, pl);
                *(uint32_t*)&Chi[(size_t)r0 * N + c] = ph;
                *(uint32_t*)&Clo[(size_t)r0 * N + c] = pl;
                split2h(o1x, o1y, ph, pl);
                *(uint32_t*)&Chi[(size_t)(r0 + 8) * N + c] = ph;
                *(uint32_t*)&Clo[(size_t)(r0 + 8) * N + c] = pl;
            }
        }
    }
}

// ===========================================================================
// HMMA flash attention (causal), pre-split fp16 qkv, cp.async KV pipeline.
// QK^T: 2-pass — Qhi·(Khi+Klo); Q-lo never loaded.
// P*V : 1-pass — P as single fp16, V hi only.
// Output att written as fp16 hi only (consumed by 1-pass GEMM2).
// Heavy-first scheduling.  (unchanged from R14; passing)
// ===========================================================================
#define AQ_BYTES  (128 * 72 * 2)   // 18432 (Q hi only)
#define AKV_BYTES (64 * 72 * 2)    // 9216
#define ASTAGE    (3 * AKV_BYTES)  // 27648 (Khi, Klo, Vhi)
#define ATTN_SMEM (AQ_BYTES + 2 * ASTAGE)   // 73728

__global__ __launch_bounds__(256, 2) void attn_hmma(
    const __half* __restrict__ qhiG, const __half* __restrict__ qloG,
    __half* __restrict__ outHi)
{
    extern __shared__ char sm[];
    const uint32_t smb = smem_u32(sm);
    const uint32_t qHA = smb;
    const int tid  = threadIdx.x;
    const int lane = tid & 31;
    const int w    = tid >> 5;
    const int qt = gridDim.x - 1 - blockIdx.x;   // heavy-first
    const int hd = blockIdx.y;     // head
    const int b  = blockIdx.z;
    const int qb = qt * 128;

    // ---- Q tile (hi only) via cp.async (group 0) ----
#pragma unroll
    for (int j = 0; j < 4; j++) {
        int idx = tid + j * 256;
        int row = idx >> 3;
        int ch  = idx & 7;
        size_t so = ((size_t)b * TT + qb + row) * 3072 + (size_t)hd * 64 + ch * 8;
        uint32_t doff = row * 144 + ch * 16;
        CP_ASYNC_CG(qHA + doff, qhiG + so);
    }

    auto issue_kv = [&](int jt2, int s) {
        uint32_t kH = smb + AQ_BYTES + s * ASTAGE;
        uint32_t kL = kH + AKV_BYTES;
        uint32_t vH = kH + 2 * AKV_BYTES;
        size_t base = ((size_t)b * TT + jt2 * 64) * 3072 + CC + (size_t)hd * 64;
#pragma unroll
        for (int j = 0; j < 2; j++) {
            int idx = tid + j * 256;
            int row = idx >> 3;
            int ch  = idx & 7;
            size_t so = base + (size_t)row * 3072 + ch * 8;
            uint32_t doff = row * 144 + ch * 16;
            CP_ASYNC_CG(kH + doff, qhiG + so);
            CP_ASYNC_CG(kL + doff, qloG + so);
            CP_ASYNC_CG(vH + doff, qhiG + so + CC);
        }
    };

    issue_kv(0, 0); CP_COMMIT();    // group 0 (Q + KV0)
    issue_kv(1, 1); CP_COMMIT();    // group 1

    float S[8][4];
    float O[8][4] = {};
    float m_run[2] = { -1e30f, -1e30f };
    float l_run[2] = { 0.0f, 0.0f };
    const float scale = 0.125f;

    const int wmin = qb + w * 16;
    const int r_in = lane >> 2;
    const int c2   = (lane & 3) * 2;
    const int row0 = wmin + r_in;
    const int row1 = row0 + 8;
    const int nt = 2 * qt + 2;

    for (int jt = 0; jt < nt; jt++) {
        CP_WAIT1();
        __syncthreads();
        const int s = jt & 1;
        const int kvb = jt * 64;

        if (kvb <= wmin + 15) {       // warp-uniform: tile not fully masked
            uint32_t kHA = smb + AQ_BYTES + s * ASTAGE;
            uint32_t kLA = kHA + AKV_BYTES;
            uint32_t vHA = kHA + 2 * AKV_BYTES;

            // ---- S = Q K^T (2-pass: Qhi·Khi + Qhi·Klo) ----
#pragma unroll
            for (int nf = 0; nf < 8; nf++)
#pragma unroll
                for (int e = 0; e < 4; e++) S[nf][e] = 0.0f;

#pragma unroll
            for (int ks = 0; ks < 4; ks++) {
                uint32_t qh[4];
                uint32_t qoff = ((w * 16 + (lane & 15)) * 72 + ks * 16 + (lane >> 4) * 8) * 2;
                LDSM_X4(qh, qHA + qoff);
#pragma unroll
                for (int np = 0; np < 4; np++) {
                    uint32_t kh[4], kl[4];
                    uint32_t koff = ((np * 16 + (lane & 15)) * 72 + ks * 16 + (lane >> 4) * 8) * 2;
                    LDSM_X4(kh, kHA + koff);
                    LDSM_X4(kl, kLA + koff);
                    MMA_F16_2(S[2*np],   qh, kh[0], kh[2]);
                    MMA_F16_2(S[2*np],   qh, kl[0], kl[2]);
                    MMA_F16_2(S[2*np+1], qh, kh[1], kh[3]);
                    MMA_F16_2(S[2*np+1], qh, kl[1], kl[3]);
                }
            }

            // ---- scale + causal mask + row max ----
            const bool full = (kvb + 63 <= wmin);
            float mx0 = -1e30f, mx1 = -1e30f;
#pragma unroll
            for (int nf = 0; nf < 8; nf++) {
                int col = kvb + nf * 8 + c2;
                float s0 = S[nf][0] * scale;
                float s1 = S[nf][1] * scale;
                float s2 = S[nf][2] * scale;
                float s3 = S[nf][3] * scale;
                if (!full) {
                    if (col     > row0) s0 = -1e30f;
                    if (col + 1 > row0) s1 = -1e30f;
                    if (col     > row1) s2 = -1e30f;
                    if (col + 1 > row1) s3 = -1e30f;
                }
                S[nf][0] = s0; S[nf][1] = s1; S[nf][2] = s2; S[nf][3] = s3;
                mx0 = fmaxf(mx0, fmaxf(s0, s1));
                mx1 = fmaxf(mx1, fmaxf(s2, s3));
            }
            mx0 = fmaxf(mx0, __shfl_xor_sync(0xffffffffu, mx0, 1));
            mx0 = fmaxf(mx0, __shfl_xor_sync(0xffffffffu, mx0, 2));
            mx1 = fmaxf(mx1, __shfl_xor_sync(0xffffffffu, mx1, 1));
            mx1 = fmaxf(mx1, __shfl_xor_sync(0xffffffffu, mx1, 2));

            float mn0 = fmaxf(m_run[0], mx0);
            float mn1 = fmaxf(m_run[1], mx1);
            float corr0 = __expf(m_run[0] - mn0);
            float corr1 = __expf(m_run[1] - mn1);
            l_run[0] *= corr0;
            l_run[1] *= corr1;
#pragma unroll
            for (int nf = 0; nf < 8; nf++) {
                O[nf][0] *= corr0; O[nf][1] *= corr0;
                O[nf][2] *= corr1; O[nf][3] *= corr1;
            }

            float sum0 = 0.0f, sum1 = 0.0f;
#pragma unroll
            for (int nf = 0; nf < 8; nf++) {
                float p0 = __expf(S[nf][0] - mn0);
                float p1 = __expf(S[nf][1] - mn0);
                float p2 = __expf(S[nf][2] - mn1);
                float p3 = __expf(S[nf][3] - mn1);
                S[nf][0] = p0; S[nf][1] = p1; S[nf][2] = p2; S[nf][3] = p3;
                sum0 += p0 + p1;
                sum1 += p2 + p3;
            }
            sum0 += __shfl_xor_sync(0xffffffffu, sum0, 1);
            sum0 += __shfl_xor_sync(0xffffffffu, sum0, 2);
            sum1 += __shfl_xor_sync(0xffffffffu, sum1, 1);
            sum1 += __shfl_xor_sync(0xffffffffu, sum1, 2);
            l_run[0] += sum0;
            l_run[1] += sum1;
            m_run[0] = mn0;
            m_run[1] = mn1;

            // ---- O += P V (1-pass: fp16 P, V hi only) ----
#pragma unroll
            for (int j = 0; j < 4; j++) {
                uint32_t pH[4];
                pH[0] = pack2h(S[2*j][0],   S[2*j][1]);
                pH[1] = pack2h(S[2*j][2],   S[2*j][3]);
                pH[2] = pack2h(S[2*j+1][0], S[2*j+1][1]);
                pH[3] = pack2h(S[2*j+1][2], S[2*j+1][3]);
#pragma unroll
                for (int np = 0; np < 4; np++) {
                    uint32_t vh[4];
                    uint32_t voff = ((j * 16 + (lane & 15)) * 72 + np * 16 + (lane >> 4) * 8) * 2;
                    LDSM_X4T(vh, vHA + voff);
                    MMA_F16(O[2*np],   pH, vh);
                    MMA_F16(O[2*np+1], pH, vh + 2);
                }
            }
        }

        __syncthreads();
        if (jt + 2 < nt) issue_kv(jt + 2, s);
        CP_COMMIT();
    }

    // ---- epilogue: normalize, write fp16 hi [B,T,C] ----
    float inv0 = 1.0f / l_run[0];
    float inv1 = 1.0f / l_run[1];
    size_t o0off = ((size_t)b * TT + row0) * CC + (size_t)hd * HD;
    size_t o1off = ((size_t)b * TT + row1) * CC + (size_t)hd * HD;
#pragma unroll
    for (int nf = 0; nf < 8; nf++) {
        int c = nf * 8 + c2;
        *(uint32_t*)&outHi[o0off + c] = pack2h(O[nf][0] * inv0, O[nf][1] * inv0);
        *(uint32_t*)&outHi[o1off + c] = pack2h(O[nf][2] * inv1, O[nf][3] * inv1);
    }
}

// ---------------------------------------------------------------------------
extern "C" void kernel_launch(void* const* d_in, const int* in_sizes, int n_in,
                              void* d_out, int out_size)
{
    const float* x     = (const float*)d_in[0];
    const float* Wqkv  = (const float*)d_in[1];
    const float* bqkv  = (const float*)d_in[2];
    const float* Wproj = (const float*)d_in[3];
    const float* bproj = (const float*)d_in[4];
    float* out = (float*)d_out;

    __half *xhi, *wqhi, *wqlo, *wphi, *qkvhi, *qkvlo, *atthi;
    cudaGetSymbolAddress((void**)&xhi,   g_xhi);
    cudaGetSymbolAddress((void**)&wqhi,  g_wqhi);
    cudaGetSymbolAddress((void**)&wqlo,  g_wqlo);
    cudaGetSymbolAddress((void**)&wphi,  g_wphi);
    cudaGetSymbolAddress((void**)&qkvhi, g_qkvhi);
    cudaGetSymbolAddress((void**)&qkvlo, g_qkvlo);
    cudaGetSymbolAddress((void**)&atthi, g_atthi);

    cudaFuncSetAttribute(gemm_f16,
                         cudaFuncAttributeMaxDynamicSharedMemorySize, GEMM_SMEM);
    cudaFuncSetAttribute(attn_hmma,
                         cudaFuncAttributeMaxDynamicSharedMemorySize, ATTN_SMEM);

    // 0) pre-split inputs to fp16 (x, Wproj: hi only; Wqkv: hi+lo)
    int n4x = BT * CC / 4;
    trunc_f32<<<n4x / 256, 256>>>(x, xhi, n4x);
    int n4q = CC * 3 * CC / 4;
    split_f32<<<n4q / 256, 256>>>(Wqkv, wqhi, wqlo, n4q);
    int n4p = CC * CC / 4;
    trunc_f32<<<n4p / 256, 256>>>(Wproj, wphi, n4p);

    dim3 blk(256);
    // 1) qkv = x @ W_qkv + b_qkv  -> hi/lo fp16.  2-pass, BK=64.
    gemm_f16<<<dim3(3 * CC / 128, BT / 128), blk, GEMM_SMEM>>>(
        xhi, wqhi, wqlo, bqkv, nullptr, qkvhi, qkvlo, BT, 3 * CC, CC, 1, 1);
    // 2) attention -> att fp16 hi
    attn_hmma<<<dim3(TT / 128, HH, BB), blk, ATTN_SMEM>>>(qkvhi, qkvlo, atthi);
    // 3) out = att @ W_proj + b_proj  -> fp32.  1-pass, BK=64.
    gemm_f16<<<dim3(CC / 128, BT / 128), blk, GEMM_SMEM>>>(
        atthi, wphi, nullptr, bproj, out, nullptr, nullptr, BT, CC, CC, 0, 3);
}

// round 16
// speedup vs baseline: 1.6483x; 1.0047x over previous
#include <cuda_runtime.h>
#include <cuda_fp16.h>
#include <cstdint>
#include <math.h>

// Problem constants
#define BB 4
#define TT 2048
#define CC 1024
#define HH 16
#define HD 64
#define BT (BB*TT)          // 8192

// Pre-split fp16 scratch (device globals: allocation-free per harness rules)
__device__ __align__(256) __half g_xhi[(size_t)BT * CC];
__device__ __align__(256) __half g_wqhi[(size_t)CC * 3 * CC];
__device__ __align__(256) __half g_wqlo[(size_t)CC * 3 * CC];
__device__ __align__(256) __half g_wphi[(size_t)CC * CC];
__device__ __align__(256) __half g_qkvhi[(size_t)BT * 3 * CC];
__device__ __align__(256) __half g_qkvlo[(size_t)BT * 3 * CC];
__device__ __align__(256) __half g_atthi[(size_t)BT * CC];

// ===========================================================================
// Helpers
// ===========================================================================
__device__ __forceinline__ uint32_t smem_u32(const void* p) {
    uint32_t a;
    asm("{ .reg .u64 t; cvta.to.shared.u64 t, %1; cvt.u32.u64 %0, t; }"
        : "=r"(a) : "l"(p));
    return a;
}

#define LDSM_X4(r, addr) \
    asm volatile("ldmatrix.sync.aligned.m8n8.x4.shared.b16 {%0,%1,%2,%3}, [%4];" \
        : "=r"((r)[0]), "=r"((r)[1]), "=r"((r)[2]), "=r"((r)[3]) : "r"(addr))

#define LDSM_X4T(r, addr) \
    asm volatile("ldmatrix.sync.aligned.m8n8.x4.trans.shared.b16 {%0,%1,%2,%3}, [%4];" \
        : "=r"((r)[0]), "=r"((r)[1]), "=r"((r)[2]), "=r"((r)[3]) : "r"(addr))

#define MMA_F16(c, a, b) \
    asm volatile("mma.sync.aligned.m16n8k16.row.col.f32.f16.f16.f32 " \
        "{%0,%1,%2,%3}, {%4,%5,%6,%7}, {%8,%9}, {%0,%1,%2,%3};" \
        : "+f"((c)[0]), "+f"((c)[1]), "+f"((c)[2]), "+f"((c)[3]) \
        : "r"((a)[0]), "r"((a)[1]), "r"((a)[2]), "r"((a)[3]), \
          "r"((b)[0]), "r"((b)[1]))

#define MMA_F16_2(c, a, b0, b1) \
    asm volatile("mma.sync.aligned.m16n8k16.row.col.f32.f16.f16.f32 " \
        "{%0,%1,%2,%3}, {%4,%5,%6,%7}, {%8,%9}, {%0,%1,%2,%3};" \
        : "+f"((c)[0]), "+f"((c)[1]), "+f"((c)[2]), "+f"((c)[3]) \
        : "r"((a)[0]), "r"((a)[1]), "r"((a)[2]), "r"((a)[3]), \
          "r"(b0), "r"(b1))

#define CP_ASYNC_CG(dst, src) \
    asm volatile("cp.async.cg.shared.global [%0], [%1], 16;" :: "r"(dst), "l"(src))
#define CP_COMMIT() asm volatile("cp.async.commit_group;" ::: "memory")
#define CP_WAIT0()  asm volatile("cp.async.wait_group 0;" ::: "memory")
#define CP_WAIT1()  asm volatile("cp.async.wait_group 1;" ::: "memory")

__device__ __forceinline__ uint32_t pack2h(float a, float b) {
    __half2 t = __floats2half2_rn(a, b);
    return *(uint32_t*)&t;
}

// split x into hi (fp16-representable float) and lo = x - hi (fp16)
__device__ __forceinline__ void split2h(float a, float b, uint32_t& hi, uint32_t& lo) {
    __half ha = __float2half_rn(a);
    __half hb = __float2half_rn(b);
    __half2 hp = __halves2half2(ha, hb);
    hi = *(uint32_t*)&hp;
    lo = pack2h(a - __half2float(ha), b - __half2float(hb));
}

// ===========================================================================
// split_f32: fp32 array -> hi/lo fp16 arrays (4 elems/thread)
// ===========================================================================
__global__ __launch_bounds__(256) void split_f32(
    const float* __restrict__ in, __half* __restrict__ hi,
    __half* __restrict__ lo, int n4)
{
    int i = blockIdx.x * 256 + threadIdx.x;
    if (i >= n4) return;
    float4 v = ((const float4*)in)[i];
    uint32_t h0, l0, h1, l1;
    split2h(v.x, v.y, h0, l0);
    split2h(v.z, v.w, h1, l1);
    ((uint2*)hi)[i] = make_uint2(h0, h1);
    ((uint2*)lo)[i] = make_uint2(l0, l1);
}

// hi-only variant (lo never consumed)
__global__ __launch_bounds__(256) void trunc_f32(
    const float* __restrict__ in, __half* __restrict__ hi, int n4)
{
    int i = blockIdx.x * 256 + threadIdx.x;
    if (i >= n4) return;
    float4 v = ((const float4*)in)[i];
    ((uint2*)hi)[i] = make_uint2(pack2h(v.x, v.y), pack2h(v.z, v.w));
}

// ===========================================================================
// HMMA split-fp16 GEMM, BK=64, 2-stage cp.async pipeline, ONE sync per chunk.
// 2 CTAs/SM.  passMode: 1 = 2-pass (Ahi·Bhi + Ahi·Blo); 3 = 1-pass (hi·hi).
// (unchanged from R15; best measured)
// ===========================================================================
#define GA_STRIDE 72          // fp16 elems/row (64+8): 144B rows, conflict-free
#define GB_STRIDE 136         // fp16 elems/row (128+8): 272B rows
#define GA_BYTES (128 * GA_STRIDE * 2)   // 18432
#define GB_BYTES (64 * GB_STRIDE * 2)    // 17408
#define GBUF (GA_BYTES + 2 * GB_BYTES)   // 53248 (Ahi, Bhi, Blo)
#define GEMM_SMEM (2 * GBUF)             // 106496

__global__ __launch_bounds__(256, 2) void gemm_f16(
    const __half* __restrict__ Ahi,
    const __half* __restrict__ Bhi, const __half* __restrict__ Blo,
    const float* __restrict__ bias,
    float* __restrict__ Cf,
    __half* __restrict__ Chi, __half* __restrict__ Clo,
    int M, int N, int K, int outSplit, int passMode)
{
    extern __shared__ char sm[];
    const uint32_t smb = smem_u32(sm);
    const int tid  = threadIdx.x;
    const int lane = tid & 31;
    const int wid  = tid >> 5;
    const int wm   = wid >> 2;
    const int wn   = wid & 3;
    const int rowBase = blockIdx.y * 128;
    const int colBase = blockIdx.x * 128;
    const bool useBlo = (passMode != 3);

    auto issue = [&](int k0, int bi) {
        uint32_t aH = smb + bi * GBUF;
        uint32_t bH = aH + GA_BYTES;
        uint32_t bL = bH + GB_BYTES;
#pragma unroll
        for (int j = 0; j < 4; j++) {
            int idx = tid + j * 256;
            int m  = idx >> 3;
            int ch = idx & 7;
            size_t ao = (size_t)(rowBase + m) * K + k0 + ch * 8;
            CP_ASYNC_CG(aH + m * 144 + ch * 16, Ahi + ao);
            int kk = idx >> 4;
            int c2 = idx & 15;
            size_t bo = (size_t)(k0 + kk) * N + colBase + c2 * 8;
            uint32_t bd = kk * 272 + c2 * 16;
            CP_ASYNC_CG(bH + bd, Bhi + bo);
            if (useBlo) CP_ASYNC_CG(bL + bd, Blo + bo);
        }
    };

    float acc[4][4][4] = {};
    const int NS = K >> 6;    // 16 chunks of BK=64

    issue(0, 0);
    CP_COMMIT();

    for (int c = 0; c < NS; c++) {
        CP_WAIT0();
        __syncthreads();

        if (c + 1 < NS) issue((c + 1) << 6, (c + 1) & 1);
        CP_COMMIT();

        uint32_t aH = smb + (c & 1) * GBUF;
        uint32_t bH = aH + GA_BYTES;
        uint32_t bL = bH + GB_BYTES;

#pragma unroll
        for (int ks = 0; ks < 4; ks++) {
            uint32_t fAH[4][4];
#pragma unroll
            for (int mf = 0; mf < 4; mf++) {
                uint32_t off = ((wm * 64 + mf * 16 + (lane & 15)) * GA_STRIDE
                                + ks * 16 + (lane >> 4) * 8) * 2;
                LDSM_X4(fAH[mf], aH + off);
            }
#pragma unroll
            for (int nq = 0; nq < 2; nq++) {
                uint32_t fBH[4], fBL[4];
                uint32_t off = ((ks * 16 + (lane & 15)) * GB_STRIDE
                                + wn * 32 + nq * 16 + (lane >> 4) * 8) * 2;
                LDSM_X4T(fBH, bH + off);
                if (useBlo) LDSM_X4T(fBL, bL + off);
#pragma unroll
                for (int mf = 0; mf < 4; mf++) {
                    MMA_F16(acc[mf][2*nq],   fAH[mf], fBH);
                    MMA_F16(acc[mf][2*nq+1], fAH[mf], fBH + 2);
                    if (useBlo) {
                        MMA_F16(acc[mf][2*nq],   fAH[mf], fBL);
                        MMA_F16(acc[mf][2*nq+1], fAH[mf], fBL + 2);
                    }
                }
            }
        }
    }

    // ---- Epilogue ----
#pragma unroll
    for (int nf = 0; nf < 4; nf++) {
        int c = colBase + wn * 32 + nf * 8 + 2 * (lane & 3);
        float2 bv = *(const float2*)&bias[c];
#pragma unroll
        for (int mf = 0; mf < 4; mf++) {
            int r0 = rowBase + wm * 64 + mf * 16 + (lane >> 2);
            float o0x = acc[mf][nf][0] + bv.x, o0y = acc[mf][nf][1] + bv.y;
            float o1x = acc[mf][nf][2] + bv.x, o1y = acc[mf][nf][3] + bv.y;
            if (!outSplit) {
                *(float2*)&Cf[(size_t)r0 * N + c] = make_float2(o0x, o0y);
                *(float2*)&Cf[(size_t)(r0 + 8) * N + c] = make_float2(o1x, o1y);
            } else {
                uint32_t ph, pl;
                split2h(o0x, o0y, ph, pl);
                *(uint32_t*)&Chi[(size_t)r0 * N + c] = ph;
                *(uint32_t*)&Clo[(size_t)r0 * N + c] = pl;
                split2h(o1x, o1y, ph, pl);
                *(uint32_t*)&Chi[(size_t)(r0 + 8) * N + c] = ph;
                *(uint32_t*)&Clo[(size_t)(r0 + 8) * N + c] = pl;
            }
        }
    }
}

// ===========================================================================
// HMMA flash attention (causal), pre-split fp16 qkv.
// 3-stage cp.async KV ring, ONE __syncthreads per KV tile (R8 GEMM pattern).
// QK^T: 2-pass — Qhi·(Khi+Klo).  P*V: 1-pass — fp16 P, V hi only.
// Output att fp16 hi.  Heavy-first scheduling.
// ===========================================================================
#define AQ_BYTES  (128 * 72 * 2)   // 18432 (Q hi only)
#define AKV_BYTES (64 * 72 * 2)    // 9216
#define ASTAGE    (3 * AKV_BYTES)  // 27648 (Khi, Klo, Vhi)
#define ATTN_SMEM (AQ_BYTES + 3 * ASTAGE)   // 101376

__global__ __launch_bounds__(256, 2) void attn_hmma(
    const __half* __restrict__ qhiG, const __half* __restrict__ qloG,
    __half* __restrict__ outHi)
{
    extern __shared__ char sm[];
    const uint32_t smb = smem_u32(sm);
    const uint32_t qHA = smb;
    const int tid  = threadIdx.x;
    const int lane = tid & 31;
    const int w    = tid >> 5;
    const int qt = gridDim.x - 1 - blockIdx.x;   // heavy-first
    const int hd = blockIdx.y;     // head
    const int b  = blockIdx.z;
    const int qb = qt * 128;

    // ---- Q tile (hi only) via cp.async (group 0) ----
#pragma unroll
    for (int j = 0; j < 4; j++) {
        int idx = tid + j * 256;
        int row = idx >> 3;
        int ch  = idx & 7;
        size_t so = ((size_t)b * TT + qb + row) * 3072 + (size_t)hd * 64 + ch * 8;
        uint32_t doff = row * 144 + ch * 16;
        CP_ASYNC_CG(qHA + doff, qhiG + so);
    }

    auto issue_kv = [&](int jt2, int s) {
        uint32_t kH = smb + AQ_BYTES + s * ASTAGE;
        uint32_t kL = kH + AKV_BYTES;
        uint32_t vH = kH + 2 * AKV_BYTES;
        size_t base = ((size_t)b * TT + jt2 * 64) * 3072 + CC + (size_t)hd * 64;
#pragma unroll
        for (int j = 0; j < 2; j++) {
            int idx = tid + j * 256;
            int row = idx >> 3;
            int ch  = idx & 7;
            size_t so = base + (size_t)row * 3072 + ch * 8;
            uint32_t doff = row * 144 + ch * 16;
            CP_ASYNC_CG(kH + doff, qhiG + so);
            CP_ASYNC_CG(kL + doff, qloG + so);
            CP_ASYNC_CG(vH + doff, qhiG + so + CC);
        }
    };

    issue_kv(0, 0); CP_COMMIT();    // group 0 (Q + KV0)
    issue_kv(1, 1); CP_COMMIT();    // group 1 (KV1)

    float S[8][4];
    float O[8][4] = {};
    float m_run[2] = { -1e30f, -1e30f };
    float l_run[2] = { 0.0f, 0.0f };
    const float scale = 0.125f;

    const int wmin = qb + w * 16;
    const int r_in = lane >> 2;
    const int c2   = (lane & 3) * 2;
    const int row0 = wmin + r_in;
    const int row1 = row0 + 8;
    const int nt = 2 * qt + 2;

    int s = 0;       // jt % 3
    int sn = 2;      // (jt+2) % 3
    for (int jt = 0; jt < nt; jt++) {
        CP_WAIT1();          // KV tile jt landed
        __syncthreads();     // all warps finished reading stage (jt-1)%3 == sn

        if (jt + 2 < nt) issue_kv(jt + 2, sn);
        CP_COMMIT();         // unconditional: uniform group numbering

        const int kvb = jt * 64;
        if (kvb <= wmin + 15) {       // warp-uniform: tile not fully masked
            uint32_t kHA = smb + AQ_BYTES + s * ASTAGE;
            uint32_t kLA = kHA + AKV_BYTES;
            uint32_t vHA = kHA + 2 * AKV_BYTES;

            // ---- S = Q K^T (2-pass: Qhi·Khi + Qhi·Klo) ----
#pragma unroll
            for (int nf = 0; nf < 8; nf++)
#pragma unroll
                for (int e = 0; e < 4; e++) S[nf][e] = 0.0f;

#pragma unroll
            for (int ks = 0; ks < 4; ks++) {
                uint32_t qh[4];
                uint32_t qoff = ((w * 16 + (lane & 15)) * 72 + ks * 16 + (lane >> 4) * 8) * 2;
                LDSM_X4(qh, qHA + qoff);
#pragma unroll
                for (int np = 0; np < 4; np++) {
                    uint32_t kh[4], kl[4];
                    uint32_t koff = ((np * 16 + (lane & 15)) * 72 + ks * 16 + (lane >> 4) * 8) * 2;
                    LDSM_X4(kh, kHA + koff);
                    LDSM_X4(kl, kLA + koff);
                    MMA_F16_2(S[2*np],   qh, kh[0], kh[2]);
                    MMA_F16_2(S[2*np],   qh, kl[0], kl[2]);
                    MMA_F16_2(S[2*np+1], qh, kh[1], kh[3]);
                    MMA_F16_2(S[2*np+1], qh, kl[1], kl[3]);
                }
            }

            // ---- scale + causal mask + row max ----
            const bool full = (kvb + 63 <= wmin);
            float mx0 = -1e30f, mx1 = -1e30f;
#pragma unroll
            for (int nf = 0; nf < 8; nf++) {
                int col = kvb + nf * 8 + c2;
                float s0 = S[nf][0] * scale;
                float s1 = S[nf][1] * scale;
                float s2 = S[nf][2] * scale;
                float s3 = S[nf][3] * scale;
                if (!full) {
                    if (col     > row0) s0 = -1e30f;
                    if (col + 1 > row0) s1 = -1e30f;
                    if (col     > row1) s2 = -1e30f;
                    if (col + 1 > row1) s3 = -1e30f;
                }
                S[nf][0] = s0; S[nf][1] = s1; S[nf][2] = s2; S[nf][3] = s3;
                mx0 = fmaxf(mx0, fmaxf(s0, s1));
                mx1 = fmaxf(mx1, fmaxf(s2, s3));
            }
            mx0 = fmaxf(mx0, __shfl_xor_sync(0xffffffffu, mx0, 1));
            mx0 = fmaxf(mx0, __shfl_xor_sync(0xffffffffu, mx0, 2));
            mx1 = fmaxf(mx1, __shfl_xor_sync(0xffffffffu, mx1, 1));
            mx1 = fmaxf(mx1, __shfl_xor_sync(0xffffffffu, mx1, 2));

            float mn0 = fmaxf(m_run[0], mx0);
            float mn1 = fmaxf(m_run[1], mx1);
            float corr0 = __expf(m_run[0] - mn0);
            float corr1 = __expf(m_run[1] - mn1);
            l_run[0] *= corr0;
            l_run[1] *= corr1;
#pragma unroll
            for (int nf = 0; nf < 8; nf++) {
                O[nf][0] *= corr0; O[nf][1] *= corr0;
                O[nf][2] *= corr1; O[nf][3] *= corr1;
            }

            float sum0 = 0.0f, sum1 = 0.0f;
#pragma unroll
            for (int nf = 0; nf < 8; nf++) {
                float p0 = __expf(S[nf][0] - mn0);
                float p1 = __expf(S[nf][1] - mn0);
                float p2 = __expf(S[nf][2] - mn1);
                float p3 = __expf(S[nf][3] - mn1);
                S[nf][0] = p0; S[nf][1] = p1; S[nf][2] = p2; S[nf][3] = p3;
                sum0 += p0 + p1;
                sum1 += p2 + p3;
            }
            sum0 += __shfl_xor_sync(0xffffffffu, sum0, 1);
            sum0 += __shfl_xor_sync(0xffffffffu, sum0, 2);
            sum1 += __shfl_xor_sync(0xffffffffu, sum1, 1);
            sum1 += __shfl_xor_sync(0xffffffffu, sum1, 2);
            l_run[0] += sum0;
            l_run[1] += sum1;
            m_run[0] = mn0;
            m_run[1] = mn1;

            // ---- O += P V (1-pass: fp16 P, V hi only) ----
#pragma unroll
            for (int j = 0; j < 4; j++) {
                uint32_t pH[4];
                pH[0] = pack2h(S[2*j][0],   S[2*j][1]);
                pH[1] = pack2h(S[2*j][2],   S[2*j][3]);
                pH[2] = pack2h(S[2*j+1][0], S[2*j+1][1]);
                pH[3] = pack2h(S[2*j+1][2], S[2*j+1][3]);
#pragma unroll
                for (int np = 0; np < 4; np++) {
                    uint32_t vh[4];
                    uint32_t voff = ((j * 16 + (lane & 15)) * 72 + np * 16 + (lane >> 4) * 8) * 2;
                    LDSM_X4T(vh, vHA + voff);
                    MMA_F16(O[2*np],   pH, vh);
                    MMA_F16(O[2*np+1], pH, vh + 2);
                }
            }
        }

        s  = (s  == 2) ? 0 : s + 1;
        sn = (sn == 2) ? 0 : sn + 1;
    }

    // ---- epilogue: normalize, write fp16 hi [B,T,C] ----
    float inv0 = 1.0f / l_run[0];
    float inv1 = 1.0f / l_run[1];
    size_t o0off = ((size_t)b * TT + row0) * CC + (size_t)hd * HD;
    size_t o1off = ((size_t)b * TT + row1) * CC + (size_t)hd * HD;
#pragma unroll
    for (int nf = 0; nf < 8; nf++) {
        int c = nf * 8 + c2;
        *(uint32_t*)&outHi[o0off + c] = pack2h(O[nf][0] * inv0, O[nf][1] * inv0);
        *(uint32_t*)&outHi[o1off + c] = pack2h(O[nf][2] * inv1, O[nf][3] * inv1);
    }
}

// ---------------------------------------------------------------------------
extern "C" void kernel_launch(void* const* d_in, const int* in_sizes, int n_in,
                              void* d_out, int out_size)
{
    const float* x     = (const float*)d_in[0];
    const float* Wqkv  = (const float*)d_in[1];
    const float* bqkv  = (const float*)d_in[2];
    const float* Wproj = (const float*)d_in[3];
    const float* bproj = (const float*)d_in[4];
    float* out = (float*)d_out;

    __half *xhi, *wqhi, *wqlo, *wphi, *qkvhi, *qkvlo, *atthi;
    cudaGetSymbolAddress((void**)&xhi,   g_xhi);
    cudaGetSymbolAddress((void**)&wqhi,  g_wqhi);
    cudaGetSymbolAddress((void**)&wqlo,  g_wqlo);
    cudaGetSymbolAddress((void**)&wphi,  g_wphi);
    cudaGetSymbolAddress((void**)&qkvhi, g_qkvhi);
    cudaGetSymbolAddress((void**)&qkvlo, g_qkvlo);
    cudaGetSymbolAddress((void**)&atthi, g_atthi);

    cudaFuncSetAttribute(gemm_f16,
                         cudaFuncAttributeMaxDynamicSharedMemorySize, GEMM_SMEM);
    cudaFuncSetAttribute(attn_hmma,
                         cudaFuncAttributeMaxDynamicSharedMemorySize, ATTN_SMEM);

    // 0) pre-split inputs to fp16 (x, Wproj: hi only; Wqkv: hi+lo)
    int n4x = BT * CC / 4;
    trunc_f32<<<n4x / 256, 256>>>(x, xhi, n4x);
    int n4q = CC * 3 * CC / 4;
    split_f32<<<n4q / 256, 256>>>(Wqkv, wqhi, wqlo, n4q);
    int n4p = CC * CC / 4;
    trunc_f32<<<n4p / 256, 256>>>(Wproj, wphi, n4p);

    dim3 blk(256);
    // 1) qkv = x @ W_qkv + b_qkv  -> hi/lo fp16.  2-pass, BK=64.
    gemm_f16<<<dim3(3 * CC / 128, BT / 128), blk, GEMM_SMEM>>>(
        xhi, wqhi, wqlo, bqkv, nullptr, qkvhi, qkvlo, BT, 3 * CC, CC, 1, 1);
    // 2) attention -> att fp16 hi
    attn_hmma<<<dim3(TT / 128, HH, BB), blk, ATTN_SMEM>>>(qkvhi, qkvlo, atthi);
    // 3) out = att @ W_proj + b_proj  -> fp32.  1-pass, BK=64.
    gemm_f16<<<dim3(CC / 128, BT / 128), blk, GEMM_SMEM>>>(
        atthi, wphi, nullptr, bproj, out, nullptr, nullptr, BT, CC, CC, 0, 3);
}

// round 17
// speedup vs baseline: 1.7268x; 1.0476x over previous
#include <cuda_runtime.h>
#include <cuda_fp16.h>
#include <cstdint>
#include <math.h>

// Problem constants
#define BB 4
#define TT 2048
#define CC 1024
#define HH 16
#define HD 64
#define BT (BB*TT)          // 8192

// Pre-split fp16 scratch (device globals: allocation-free per harness rules)
__device__ __align__(256) __half g_xhi[(size_t)BT * CC];
__device__ __align__(256) __half g_wqhi[(size_t)CC * 3 * CC];
__device__ __align__(256) __half g_wphi[(size_t)CC * CC];
__device__ __align__(256) __half g_qkvhi[(size_t)BT * 3 * CC];
__device__ __align__(256) __half g_qkvlo[(size_t)BT * 3 * CC];
__device__ __align__(256) __half g_atthi[(size_t)BT * CC];

// ===========================================================================
// Helpers
// ===========================================================================
__device__ __forceinline__ uint32_t smem_u32(const void* p) {
    uint32_t a;
    asm("{ .reg .u64 t; cvta.to.shared.u64 t, %1; cvt.u32.u64 %0, t; }"
        : "=r"(a) : "l"(p));
    return a;
}

#define LDSM_X4(r, addr) \
    asm volatile("ldmatrix.sync.aligned.m8n8.x4.shared.b16 {%0,%1,%2,%3}, [%4];" \
        : "=r"((r)[0]), "=r"((r)[1]), "=r"((r)[2]), "=r"((r)[3]) : "r"(addr))

#define LDSM_X4T(r, addr) \
    asm volatile("ldmatrix.sync.aligned.m8n8.x4.trans.shared.b16 {%0,%1,%2,%3}, [%4];" \
        : "=r"((r)[0]), "=r"((r)[1]), "=r"((r)[2]), "=r"((r)[3]) : "r"(addr))

#define MMA_F16(c, a, b) \
    asm volatile("mma.sync.aligned.m16n8k16.row.col.f32.f16.f16.f32 " \
        "{%0,%1,%2,%3}, {%4,%5,%6,%7}, {%8,%9}, {%0,%1,%2,%3};" \
        : "+f"((c)[0]), "+f"((c)[1]), "+f"((c)[2]), "+f"((c)[3]) \
        : "r"((a)[0]), "r"((a)[1]), "r"((a)[2]), "r"((a)[3]), \
          "r"((b)[0]), "r"((b)[1]))

#define MMA_F16_2(c, a, b0, b1) \
    asm volatile("mma.sync.aligned.m16n8k16.row.col.f32.f16.f16.f32 " \
        "{%0,%1,%2,%3}, {%4,%5,%6,%7}, {%8,%9}, {%0,%1,%2,%3};" \
        : "+f"((c)[0]), "+f"((c)[1]), "+f"((c)[2]), "+f"((c)[3]) \
        : "r"((a)[0]), "r"((a)[1]), "r"((a)[2]), "r"((a)[3]), \
          "r"(b0), "r"(b1))

#define CP_ASYNC_CG(dst, src) \
    asm volatile("cp.async.cg.shared.global [%0], [%1], 16;" :: "r"(dst), "l"(src))
#define CP_COMMIT() asm volatile("cp.async.commit_group;" ::: "memory")
#define CP_WAIT0()  asm volatile("cp.async.wait_group 0;" ::: "memory")
#define CP_WAIT1()  asm volatile("cp.async.wait_group 1;" ::: "memory")

__device__ __forceinline__ uint32_t pack2h(float a, float b) {
    __half2 t = __floats2half2_rn(a, b);
    return *(uint32_t*)&t;
}

// split x into hi (fp16-representable float) and lo = x - hi (fp16)
__device__ __forceinline__ void split2h(float a, float b, uint32_t& hi, uint32_t& lo) {
    __half ha = __float2half_rn(a);
    __half hb = __float2half_rn(b);
    __half2 hp = __halves2half2(ha, hb);
    hi = *(uint32_t*)&hp;
    lo = pack2h(a - __half2float(ha), b - __half2float(hb));
}

// ===========================================================================
// trunc_f32: fp32 array -> hi fp16 array (4 elems/thread)
// ===========================================================================
__global__ __launch_bounds__(256) void trunc_f32(
    const float* __restrict__ in, __half* __restrict__ hi, int n4)
{
    int i = blockIdx.x * 256 + threadIdx.x;
    if (i >= n4) return;
    float4 v = ((const float4*)in)[i];
    ((uint2*)hi)[i] = make_uint2(pack2h(v.x, v.y), pack2h(v.z, v.w));
}

// ===========================================================================
// HMMA fp16 GEMM, BK=64, 2-stage cp.async pipeline, ONE sync per chunk.
// 2 CTAs/SM.  passMode: 1 = 2-pass (Ahi·Bhi + Ahi·Blo); 3 = 1-pass (hi·hi).
// C = A@B + bias; output fp32 OR hi/lo fp16 pair (outSplit).
// 128x128 tile, 8 warps (2x4), warp tile 64x32.
// ===========================================================================
#define GA_STRIDE 72          // fp16 elems/row (64+8): 144B rows, conflict-free
#define GB_STRIDE 136         // fp16 elems/row (128+8): 272B rows
#define GA_BYTES (128 * GA_STRIDE * 2)   // 18432
#define GB_BYTES (64 * GB_STRIDE * 2)    // 17408
#define GBUF (GA_BYTES + 2 * GB_BYTES)   // 53248 (Ahi, Bhi, Blo)
#define GEMM_SMEM (2 * GBUF)             // 106496

__global__ __launch_bounds__(256, 2) void gemm_f16(
    const __half* __restrict__ Ahi,
    const __half* __restrict__ Bhi, const __half* __restrict__ Blo,
    const float* __restrict__ bias,
    float* __restrict__ Cf,
    __half* __restrict__ Chi, __half* __restrict__ Clo,
    int M, int N, int K, int outSplit, int passMode)
{
    extern __shared__ char sm[];
    const uint32_t smb = smem_u32(sm);
    const int tid  = threadIdx.x;
    const int lane = tid & 31;
    const int wid  = tid >> 5;
    const int wm   = wid >> 2;
    const int wn   = wid & 3;
    const int rowBase = blockIdx.y * 128;
    const int colBase = blockIdx.x * 128;
    const bool useBlo = (passMode != 3);

    auto issue = [&](int k0, int bi) {
        uint32_t aH = smb + bi * GBUF;
        uint32_t bH = aH + GA_BYTES;
        uint32_t bL = bH + GB_BYTES;
#pragma unroll
        for (int j = 0; j < 4; j++) {
            int idx = tid + j * 256;
            int m  = idx >> 3;
            int ch = idx & 7;
            size_t ao = (size_t)(rowBase + m) * K + k0 + ch * 8;
            CP_ASYNC_CG(aH + m * 144 + ch * 16, Ahi + ao);
            int kk = idx >> 4;
            int c2 = idx & 15;
            size_t bo = (size_t)(k0 + kk) * N + colBase + c2 * 8;
            uint32_t bd = kk * 272 + c2 * 16;
            CP_ASYNC_CG(bH + bd, Bhi + bo);
            if (useBlo) CP_ASYNC_CG(bL + bd, Blo + bo);
        }
    };

    float acc[4][4][4] = {};
    const int NS = K >> 6;    // 16 chunks of BK=64

    issue(0, 0);
    CP_COMMIT();

    for (int c = 0; c < NS; c++) {
        CP_WAIT0();
        __syncthreads();

        if (c + 1 < NS) issue((c + 1) << 6, (c + 1) & 1);
        CP_COMMIT();

        uint32_t aH = smb + (c & 1) * GBUF;
        uint32_t bH = aH + GA_BYTES;
        uint32_t bL = bH + GB_BYTES;

#pragma unroll
        for (int ks = 0; ks < 4; ks++) {
            uint32_t fAH[4][4];
#pragma unroll
            for (int mf = 0; mf < 4; mf++) {
                uint32_t off = ((wm * 64 + mf * 16 + (lane & 15)) * GA_STRIDE
                                + ks * 16 + (lane >> 4) * 8) * 2;
                LDSM_X4(fAH[mf], aH + off);
            }
#pragma unroll
            for (int nq = 0; nq < 2; nq++) {
                uint32_t fBH[4], fBL[4];
                uint32_t off = ((ks * 16 + (lane & 15)) * GB_STRIDE
                                + wn * 32 + nq * 16 + (lane >> 4) * 8) * 2;
                LDSM_X4T(fBH, bH + off);
                if (useBlo) LDSM_X4T(fBL, bL + off);
#pragma unroll
                for (int mf = 0; mf < 4; mf++) {
                    MMA_F16(acc[mf][2*nq],   fAH[mf], fBH);
                    MMA_F16(acc[mf][2*nq+1], fAH[mf], fBH + 2);
                    if (useBlo) {
                        MMA_F16(acc[mf][2*nq],   fAH[mf], fBL);
                        MMA_F16(acc[mf][2*nq+1], fAH[mf], fBL + 2);
                    }
                }
            }
        }
    }

    // ---- Epilogue ----
#pragma unroll
    for (int nf = 0; nf < 4; nf++) {
        int c = colBase + wn * 32 + nf * 8 + 2 * (lane & 3);
        float2 bv = *(const float2*)&bias[c];
#pragma unroll
        for (int mf = 0; mf < 4; mf++) {
            int r0 = rowBase + wm * 64 + mf * 16 + (lane >> 2);
            float o0x = acc[mf][nf][0] + bv.x, o0y = acc[mf][nf][1] + bv.y;
            float o1x = acc[mf][nf][2] + bv.x, o1y = acc[mf][nf][3] + bv.y;
            if (!outSplit) {
                *(float2*)&Cf[(size_t)r0 * N + c] = make_float2(o0x, o0y);
                *(float2*)&Cf[(size_t)(r0 + 8) * N + c] = make_float2(o1x, o1y);
            } else {
                uint32_t ph, pl;
                split2h(o0x, o0y, ph, pl);
                *(uint32_t*)&Chi[(size_t)r0 * N + c] = ph;
                *(uint32_t*)&Clo[(size_t)r0 * N + c] = pl;
                split2h(o1x, o1y, ph, pl);
                *(uint32_t*)&Chi[(size_t)(r0 + 8) * N + c] = ph;
                *(uint32_t*)&Clo[(size_t)(r0 + 8) * N + c] = pl;
            }
        }
    }
}

// ===========================================================================
// HMMA flash attention (causal), pre-split fp16 qkv.
// 3-stage cp.async KV ring, ONE __syncthreads per KV tile.
// QK^T: 2-pass — Qhi·(Khi+Klo).  P*V: 1-pass — fp16 P, V hi only.
// Output att fp16 hi.  Heavy-first scheduling.  (unchanged from R16)
// ===========================================================================
#define AQ_BYTES  (128 * 72 * 2)   // 18432 (Q hi only)
#define AKV_BYTES (64 * 72 * 2)    // 9216
#define ASTAGE    (3 * AKV_BYTES)  // 27648 (Khi, Klo, Vhi)
#define ATTN_SMEM (AQ_BYTES + 3 * ASTAGE)   // 101376

__global__ __launch_bounds__(256, 2) void attn_hmma(
    const __half* __restrict__ qhiG, const __half* __restrict__ qloG,
    __half* __restrict__ outHi)
{
    extern __shared__ char sm[];
    const uint32_t smb = smem_u32(sm);
    const uint32_t qHA = smb;
    const int tid  = threadIdx.x;
    const int lane = tid & 31;
    const int w    = tid >> 5;
    const int qt = gridDim.x - 1 - blockIdx.x;   // heavy-first
    const int hd = blockIdx.y;     // head
    const int b  = blockIdx.z;
    const int qb = qt * 128;

    // ---- Q tile (hi only) via cp.async (group 0) ----
#pragma unroll
    for (int j = 0; j < 4; j++) {
        int idx = tid + j * 256;
        int row = idx >> 3;
        int ch  = idx & 7;
        size_t so = ((size_t)b * TT + qb + row) * 3072 + (size_t)hd * 64 + ch * 8;
        uint32_t doff = row * 144 + ch * 16;
        CP_ASYNC_CG(qHA + doff, qhiG + so);
    }

    auto issue_kv = [&](int jt2, int s) {
        uint32_t kH = smb + AQ_BYTES + s * ASTAGE;
        uint32_t kL = kH + AKV_BYTES;
        uint32_t vH = kH + 2 * AKV_BYTES;
        size_t base = ((size_t)b * TT + jt2 * 64) * 3072 + CC + (size_t)hd * 64;
#pragma unroll
        for (int j = 0; j < 2; j++) {
            int idx = tid + j * 256;
            int row = idx >> 3;
            int ch  = idx & 7;
            size_t so = base + (size_t)row * 3072 + ch * 8;
            uint32_t doff = row * 144 + ch * 16;
            CP_ASYNC_CG(kH + doff, qhiG + so);
            CP_ASYNC_CG(kL + doff, qloG + so);
            CP_ASYNC_CG(vH + doff, qhiG + so + CC);
        }
    };

    issue_kv(0, 0); CP_COMMIT();    // group 0 (Q + KV0)
    issue_kv(1, 1); CP_COMMIT();    // group 1 (KV1)

    float S[8][4];
    float O[8][4] = {};
    float m_run[2] = { -1e30f, -1e30f };
    float l_run[2] = { 0.0f, 0.0f };
    const float scale = 0.125f;

    const int wmin = qb + w * 16;
    const int r_in = lane >> 2;
    const int c2   = (lane & 3) * 2;
    const int row0 = wmin + r_in;
    const int row1 = row0 + 8;
    const int nt = 2 * qt + 2;

    int s = 0;       // jt % 3
    int sn = 2;      // (jt+2) % 3
    for (int jt = 0; jt < nt; jt++) {
        CP_WAIT1();
        __syncthreads();

        if (jt + 2 < nt) issue_kv(jt + 2, sn);
        CP_COMMIT();

        const int kvb = jt * 64;
        if (kvb <= wmin + 15) {       // warp-uniform: tile not fully masked
            uint32_t kHA = smb + AQ_BYTES + s * ASTAGE;
            uint32_t kLA = kHA + AKV_BYTES;
            uint32_t vHA = kHA + 2 * AKV_BYTES;

            // ---- S = Q K^T (2-pass: Qhi·Khi + Qhi·Klo) ----
#pragma unroll
            for (int nf = 0; nf < 8; nf++)
#pragma unroll
                for (int e = 0; e < 4; e++) S[nf][e] = 0.0f;

#pragma unroll
            for (int ks = 0; ks < 4; ks++) {
                uint32_t qh[4];
                uint32_t qoff = ((w * 16 + (lane & 15)) * 72 + ks * 16 + (lane >> 4) * 8) * 2;
                LDSM_X4(qh, qHA + qoff);
#pragma unroll
                for (int np = 0; np < 4; np++) {
                    uint32_t kh[4], kl[4];
                    uint32_t koff = ((np * 16 + (lane & 15)) * 72 + ks * 16 + (lane >> 4) * 8) * 2;
                    LDSM_X4(kh, kHA + koff);
                    LDSM_X4(kl, kLA + koff);
                    MMA_F16_2(S[2*np],   qh, kh[0], kh[2]);
                    MMA_F16_2(S[2*np],   qh, kl[0], kl[2]);
                    MMA_F16_2(S[2*np+1], qh, kh[1], kh[3]);
                    MMA_F16_2(S[2*np+1], qh, kl[1], kl[3]);
                }
            }

            // ---- scale + causal mask + row max ----
            const bool full = (kvb + 63 <= wmin);
            float mx0 = -1e30f, mx1 = -1e30f;
#pragma unroll
            for (int nf = 0; nf < 8; nf++) {
                int col = kvb + nf * 8 + c2;
                float s0 = S[nf][0] * scale;
                float s1 = S[nf][1] * scale;
                float s2 = S[nf][2] * scale;
                float s3 = S[nf][3] * scale;
                if (!full) {
                    if (col     > row0) s0 = -1e30f;
                    if (col + 1 > row0) s1 = -1e30f;
                    if (col     > row1) s2 = -1e30f;
                    if (col + 1 > row1) s3 = -1e30f;
                }
                S[nf][0] = s0; S[nf][1] = s1; S[nf][2] = s2; S[nf][3] = s3;
                mx0 = fmaxf(mx0, fmaxf(s0, s1));
                mx1 = fmaxf(mx1, fmaxf(s2, s3));
            }
            mx0 = fmaxf(mx0, __shfl_xor_sync(0xffffffffu, mx0, 1));
            mx0 = fmaxf(mx0, __shfl_xor_sync(0xffffffffu, mx0, 2));
            mx1 = fmaxf(mx1, __shfl_xor_sync(0xffffffffu, mx1, 1));
            mx1 = fmaxf(mx1, __shfl_xor_sync(0xffffffffu, mx1, 2));

            float mn0 = fmaxf(m_run[0], mx0);
            float mn1 = fmaxf(m_run[1], mx1);
            float corr0 = __expf(m_run[0] - mn0);
            float corr1 = __expf(m_run[1] - mn1);
            l_run[0] *= corr0;
            l_run[1] *= corr1;
#pragma unroll
            for (int nf = 0; nf < 8; nf++) {
                O[nf][0] *= corr0; O[nf][1] *= corr0;
                O[nf][2] *= corr1; O[nf][3] *= corr1;
            }

            float sum0 = 0.0f, sum1 = 0.0f;
#pragma unroll
            for (int nf = 0; nf < 8; nf++) {
                float p0 = __expf(S[nf][0] - mn0);
                float p1 = __expf(S[nf][1] - mn0);
                float p2 = __expf(S[nf][2] - mn1);
                float p3 = __expf(S[nf][3] - mn1);
                S[nf][0] = p0; S[nf][1] = p1; S[nf][2] = p2; S[nf][3] = p3;
                sum0 += p0 + p1;
                sum1 += p2 + p3;
            }
            sum0 += __shfl_xor_sync(0xffffffffu, sum0, 1);
            sum0 += __shfl_xor_sync(0xffffffffu, sum0, 2);
            sum1 += __shfl_xor_sync(0xffffffffu, sum1, 1);
            sum1 += __shfl_xor_sync(0xffffffffu, sum1, 2);
            l_run[0] += sum0;
            l_run[1] += sum1;
            m_run[0] = mn0;
            m_run[1] = mn1;

            // ---- O += P V (1-pass: fp16 P, V hi only) ----
#pragma unroll
            for (int j = 0; j < 4; j++) {
                uint32_t pH[4];
                pH[0] = pack2h(S[2*j][0],   S[2*j][1]);
                pH[1] = pack2h(S[2*j][2],   S[2*j][3]);
                pH[2] = pack2h(S[2*j+1][0], S[2*j+1][1]);
                pH[3] = pack2h(S[2*j+1][2], S[2*j+1][3]);
#pragma unroll
                for (int np = 0; np < 4; np++) {
                    uint32_t vh[4];
                    uint32_t voff = ((j * 16 + (lane & 15)) * 72 + np * 16 + (lane >> 4) * 8) * 2;
                    LDSM_X4T(vh, vHA + voff);
                    MMA_F16(O[2*np],   pH, vh);
                    MMA_F16(O[2*np+1], pH, vh + 2);
                }
            }
        }

        s  = (s  == 2) ? 0 : s + 1;
        sn = (sn == 2) ? 0 : sn + 1;
    }

    // ---- epilogue: normalize, write fp16 hi [B,T,C] ----
    float inv0 = 1.0f / l_run[0];
    float inv1 = 1.0f / l_run[1];
    size_t o0off = ((size_t)b * TT + row0) * CC + (size_t)hd * HD;
    size_t o1off = ((size_t)b * TT + row1) * CC + (size_t)hd * HD;
#pragma unroll
    for (int nf = 0; nf < 8; nf++) {
        int c = nf * 8 + c2;
        *(uint32_t*)&outHi[o0off + c] = pack2h(O[nf][0] * inv0, O[nf][1] * inv0);
        *(uint32_t*)&outHi[o1off + c] = pack2h(O[nf][2] * inv1, O[nf][3] * inv1);
    }
}

// ---------------------------------------------------------------------------
extern "C" void kernel_launch(void* const* d_in, const int* in_sizes, int n_in,
                              void* d_out, int out_size)
{
    const float* x     = (const float*)d_in[0];
    const float* Wqkv  = (const float*)d_in[1];
    const float* bqkv  = (const float*)d_in[2];
    const float* Wproj = (const float*)d_in[3];
    const float* bproj = (const float*)d_in[4];
    float* out = (float*)d_out;

    __half *xhi, *wqhi, *wphi, *qkvhi, *qkvlo, *atthi;
    cudaGetSymbolAddress((void**)&xhi,   g_xhi);
    cudaGetSymbolAddress((void**)&wqhi,  g_wqhi);
    cudaGetSymbolAddress((void**)&wphi,  g_wphi);
    cudaGetSymbolAddress((void**)&qkvhi, g_qkvhi);
    cudaGetSymbolAddress((void**)&qkvlo, g_qkvlo);
    cudaGetSymbolAddress((void**)&atthi, g_atthi);

    cudaFuncSetAttribute(gemm_f16,
                         cudaFuncAttributeMaxDynamicSharedMemorySize, GEMM_SMEM);
    cudaFuncSetAttribute(attn_hmma,
                         cudaFuncAttributeMaxDynamicSharedMemorySize, ATTN_SMEM);

    // 0) truncate inputs to fp16 hi (no lo operands consumed anywhere)
    int n4x = BT * CC / 4;
    trunc_f32<<<n4x / 256, 256>>>(x, xhi, n4x);
    int n4q = CC * 3 * CC / 4;
    trunc_f32<<<n4q / 256, 256>>>(Wqkv, wqhi, n4q);
    int n4p = CC * CC / 4;
    trunc_f32<<<n4p / 256, 256>>>(Wproj, wphi, n4p);

    dim3 blk(256);
    // 1) qkv = x @ W_qkv + b_qkv  -> hi/lo fp16 (lo = output rounding residual,
    //    consumed by attention's 2-pass QK for K).  1-pass mainloop, BK=64.
    gemm_f16<<<dim3(3 * CC / 128, BT / 128), blk, GEMM_SMEM>>>(
        xhi, wqhi, nullptr, bqkv, nullptr, qkvhi, qkvlo, BT, 3 * CC, CC, 1, 3);
    // 2) attention -> att fp16 hi
    attn_hmma<<<dim3(TT / 128, HH, BB), blk, ATTN_SMEM>>>(qkvhi, qkvlo, atthi);
    // 3) out = att @ W_proj + b_proj  -> fp32.  1-pass, BK=64.
    gemm_f16<<<dim3(CC / 128, BT / 128), blk, GEMM_SMEM>>>(
        atthi, wphi, nullptr, bproj, out, nullptr, nullptr, BT, CC, CC, 0, 3);
}